// round 5
// baseline (speedup 1.0000x reference)
#include <cuda_runtime.h>
#include <cuda_bf16.h>
#include <math.h>
#include <cstdint>

#define B_SZ   2
#define LSEQ   1024
#define DMODEL 1024
#define DIN    2048
#define NST    16
#define DTR    64
#define MROWS  (B_SZ*LSEQ)   /* 2048 */

// ---------------- scratch (device globals; no allocation allowed) ------------
__device__ float g_XZ[MROWS*8192];              // [m][dir*4096 + (xi | z)]
__device__ float g_U [MROWS*4096];              // fp32 for scan
__device__ __nv_bfloat16 g_Uh[MROWS*4096],  g_Ul[MROWS*4096];
__device__ __nv_bfloat16 g_Xh[MROWS*DMODEL], g_Xl[MROWS*DMODEL];
__device__ __nv_bfloat16 g_Winh[8192*DMODEL], g_Winl[8192*DMODEL];
__device__ __nv_bfloat16 g_Xph[256*DIN],    g_Xpl[256*DIN];      // padded xpW
__device__ float g_XDBLP[4*MROWS*256];
__device__ float g_XDBL[MROWS*256];
__device__ __nv_bfloat16 g_XDh[MROWS*256],  g_XDl[MROWS*256];
__device__ __nv_bfloat16 g_dtWh[4096*DTR],  g_dtWl[4096*DTR];    // dir-concat rows
__device__ float g_DELTA[(size_t)MROWS*4096];
__device__ __nv_bfloat16 g_YGh[MROWS*4096], g_YGl[MROWS*4096];
__device__ __nv_bfloat16 g_Wouth[DMODEL*4096], g_Woutl[DMODEL*4096]; // K-concat cols

// ======================= helpers =============================================
__device__ __forceinline__ uint32_t smem_u32(const void* p) {
    uint32_t a;
    asm("{ .reg .u64 t; cvta.to.shared.u64 t, %1; cvt.u32.u64 %0, t; }" : "=r"(a) : "l"(p));
    return a;
}
#define LDM4(r0,r1,r2,r3,addr)                                                      \
    asm volatile("ldmatrix.sync.aligned.m8n8.x4.shared.b16 {%0,%1,%2,%3}, [%4];"    \
        : "=r"(r0),"=r"(r1),"=r"(r2),"=r"(r3) : "r"(addr))
#define MMA16816(c,a,b)                                                             \
    asm volatile("mma.sync.aligned.m16n8k16.row.col.f32.bf16.bf16.f32 "             \
        "{%0,%1,%2,%3}, {%4,%5,%6,%7}, {%8,%9}, {%0,%1,%2,%3};"                     \
        : "+f"((c)[0]),"+f"((c)[1]),"+f"((c)[2]),"+f"((c)[3])                       \
        : "r"((a)[0]),"r"((a)[1]),"r"((a)[2]),"r"((a)[3]),"r"((b)[0]),"r"((b)[1]))
#define CPA16(dst, src) asm volatile("cp.async.cg.shared.global [%0], [%1], 16;" :: "r"(dst), "l"(src) : "memory")
#define CPCOMMIT()      asm volatile("cp.async.commit_group;" ::: "memory")
#define CPWAIT0()       asm volatile("cp.async.wait_group 0;" ::: "memory")
#define CPWAIT1()       asm volatile("cp.async.wait_group 1;" ::: "memory")

__device__ __forceinline__ void split1(float v, __nv_bfloat16& h, __nv_bfloat16& l) {
    h = __float2bfloat16(v);
    l = __float2bfloat16(v - __bfloat162float(h));
}

// ======================= HMMA GEMM (pre-split bf16 hi/lo planes) =============
// C[M,N] = A[M,K]*B[N,K]^T, fp32 via hi*hi + hi*lo + lo*hi.
// A gets +a_off1 (elements) when CTA n-tile >= nsplit (dir-dependent A slice).
// kz>0: split-K over blockIdx.z; C offset by z*M*ldc (partials).
// EPI: 0 = store, 1 = softplus(acc + bias[n]) (bias0/bias1 split at nsplit),
//      2 = store alpha*acc
#define BKC 32
#define ASTRIDE 80             /* bytes per smem row: 32 bf16 + 8 pad */
#define STG_A_HI 0
#define STG_A_LO 10240
#define STG_B_HI 20480
#define STG_B_LO 30720
#define STG_STRIDE 40960
#define HG_SMEM (2*STG_STRIDE)

template<int EPI>
__global__ __launch_bounds__(256, 1) void hgemm(
    const __nv_bfloat16* __restrict__ Ah, const __nv_bfloat16* __restrict__ Al,
    int lda, int a_off1, int nsplit,
    const __nv_bfloat16* __restrict__ Bh, const __nv_bfloat16* __restrict__ Bl,
    int ldb,
    float* __restrict__ C, int ldc, int K,
    const float* __restrict__ bias0, const float* __restrict__ bias1,
    float alpha, int kz)
{
    extern __shared__ char sm[];
    const uint32_t smb = smem_u32(sm);
    const int tid = threadIdx.x;
    const int bm = blockIdx.y * 128, bn = blockIdx.x * 128;
    if (kz > 0) {
        Ah += (size_t)blockIdx.z * kz;  Al += (size_t)blockIdx.z * kz;
        Bh += (size_t)blockIdx.z * kz;  Bl += (size_t)blockIdx.z * kz;
        C  += (size_t)blockIdx.z * (size_t)(gridDim.y * 128) * (size_t)ldc;
        K = kz;
    }
    const int aoff = (nsplit && bn >= nsplit) ? a_off1 : 0;

    // ---- producer: each thread owns 2x16B per plane per chunk ---------------
    const int grow = tid >> 1;               // 0..127
    const int seg  = (tid & 1) << 1;         // 0 or 2 (16B units within 64B row)
    const char* gAh = (const char*)(Ah + aoff + (size_t)(bm + grow) * lda);
    const char* gAl = (const char*)(Al + aoff + (size_t)(bm + grow) * lda);
    const char* gBh = (const char*)(Bh + (size_t)(bn + grow) * ldb);
    const char* gBl = (const char*)(Bl + (size_t)(bn + grow) * ldb);
    const uint32_t srow = smb + (uint32_t)(grow * ASTRIDE + seg * 16);

    // ---- warp geometry ------------------------------------------------------
    const int wid = tid >> 5, lane = tid & 31;
    const int wm = (wid >> 2) * 64;
    const int wn = (wid & 3) * 32;
    const int tq = lane >> 2, tr = lane & 3;
    const uint32_t aoffm = (uint32_t)((wm + (lane & 15)) * ASTRIDE + ((lane >> 4) << 4));
    const int g = lane >> 3;
    const uint32_t boffm = (uint32_t)((wn + ((g >> 1) << 3) + (lane & 7)) * ASTRIDE + ((g & 1) << 4));

    float acc[4][4][4];
#pragma unroll
    for (int i = 0; i < 4; i++)
#pragma unroll
        for (int j = 0; j < 4; j++)
#pragma unroll
            for (int q = 0; q < 4; q++) acc[i][j][q] = 0.f;

    const int nch = K / BKC;

    auto issue = [&](int s) {
        const uint32_t st = srow + (uint32_t)(s & 1) * STG_STRIDE;
        const int go = s * (BKC * 2) + seg * 16;     // byte offset in gmem row
        CPA16(st + STG_A_HI,      gAh + go);
        CPA16(st + STG_A_HI + 16, gAh + go + 16);
        CPA16(st + STG_A_LO,      gAl + go);
        CPA16(st + STG_A_LO + 16, gAl + go + 16);
        CPA16(st + STG_B_HI,      gBh + go);
        CPA16(st + STG_B_HI + 16, gBh + go + 16);
        CPA16(st + STG_B_LO,      gBl + go);
        CPA16(st + STG_B_LO + 16, gBl + go + 16);
        CPCOMMIT();
    };

    issue(0);
    for (int s = 0; s < nch; s++) {
        if (s + 1 < nch) { issue(s + 1); CPWAIT1(); }
        else             { CPWAIT0(); }
        __syncthreads();
        const uint32_t sa = smb + (uint32_t)(s & 1) * STG_STRIDE;
#pragma unroll
        for (int ph = 0; ph < 2; ph++) {
            const uint32_t ka = sa + ph * 32;        // +16 bf16 per k-phase
            uint32_t ah[4][4], al[4][4], bh[4][2], bl[4][2];
#pragma unroll
            for (int i = 0; i < 4; i++)
                LDM4(ah[i][0], ah[i][1], ah[i][2], ah[i][3], ka + STG_A_HI + aoffm + i*(16*ASTRIDE));
#pragma unroll
            for (int i = 0; i < 4; i++)
                LDM4(al[i][0], al[i][1], al[i][2], al[i][3], ka + STG_A_LO + aoffm + i*(16*ASTRIDE));
            LDM4(bh[0][0], bh[0][1], bh[1][0], bh[1][1], ka + STG_B_HI + boffm);
            LDM4(bh[2][0], bh[2][1], bh[3][0], bh[3][1], ka + STG_B_HI + boffm + 16*ASTRIDE);
            LDM4(bl[0][0], bl[0][1], bl[1][0], bl[1][1], ka + STG_B_LO + boffm);
            LDM4(bl[2][0], bl[2][1], bl[3][0], bl[3][1], ka + STG_B_LO + boffm + 16*ASTRIDE);
            // term-major ordering: 16 independent accumulators between reuses
#pragma unroll
            for (int i = 0; i < 4; i++)
#pragma unroll
                for (int j = 0; j < 4; j++)
                    MMA16816(acc[i][j], ah[i], bh[j]);
#pragma unroll
            for (int i = 0; i < 4; i++)
#pragma unroll
                for (int j = 0; j < 4; j++)
                    MMA16816(acc[i][j], ah[i], bl[j]);
#pragma unroll
            for (int i = 0; i < 4; i++)
#pragma unroll
                for (int j = 0; j < 4; j++)
                    MMA16816(acc[i][j], al[i], bh[j]);
        }
        __syncthreads();
    }

    // ---- epilogue -----------------------------------------------------------
    const float* bias = nullptr;
    if (EPI == 1) bias = (nsplit && bn >= nsplit) ? (bias1 - nsplit) : bias0;
#pragma unroll
    for (int i = 0; i < 4; i++) {
        const int row0 = bm + wm + 16*i + tq;
#pragma unroll
        for (int j = 0; j < 4; j++) {
            const int col = bn + wn + 8*j + 2*tr;
            float v0 = acc[i][j][0], v1 = acc[i][j][1];
            float v2 = acc[i][j][2], v3 = acc[i][j][3];
            if (EPI == 1) {
                const float b0v = bias[col], b1v = bias[col+1];
                v0 += b0v; v1 += b1v; v2 += b0v; v3 += b1v;
                v0 = (v0 > 20.f) ? v0 : log1pf(__expf(v0));
                v1 = (v1 > 20.f) ? v1 : log1pf(__expf(v1));
                v2 = (v2 > 20.f) ? v2 : log1pf(__expf(v2));
                v3 = (v3 > 20.f) ? v3 : log1pf(__expf(v3));
            } else if (EPI == 2) {
                v0 *= alpha; v1 *= alpha; v2 *= alpha; v3 *= alpha;
            }
            *reinterpret_cast<float2*>(C + (size_t)row0 * ldc + col)       = make_float2(v0, v1);
            *reinterpret_cast<float2*>(C + (size_t)(row0 + 8) * ldc + col) = make_float2(v2, v3);
        }
    }
}

// ======================= convert kernels =====================================
__global__ __launch_bounds__(256) void cvt_plane(
    const float* __restrict__ src, __nv_bfloat16* __restrict__ hi,
    __nv_bfloat16* __restrict__ lo, int n4)
{
    const int i = blockIdx.x * 256 + threadIdx.x;
    if (i >= n4) return;
    float4 v = reinterpret_cast<const float4*>(src)[i];
    __nv_bfloat16 h0,h1,h2,h3,l0,l1,l2,l3;
    split1(v.x,h0,l0); split1(v.y,h1,l1); split1(v.z,h2,l2); split1(v.w,h3,l3);
    reinterpret_cast<__nv_bfloat162*>(hi)[2*i]   = __nv_bfloat162(h0,h1);
    reinterpret_cast<__nv_bfloat162*>(hi)[2*i+1] = __nv_bfloat162(h2,h3);
    reinterpret_cast<__nv_bfloat162*>(lo)[2*i]   = __nv_bfloat162(l0,l1);
    reinterpret_cast<__nv_bfloat162*>(lo)[2*i+1] = __nv_bfloat162(l2,l3);
}

// xpW -> [256][2048]: rows 0-95 f, 96-127 zero, 128-223 b, 224-255 zero
__global__ __launch_bounds__(256) void cvt_xp(
    const float* __restrict__ f, const float* __restrict__ b)
{
    const int i = blockIdx.x * 256 + threadIdx.x;     // over 256*2048/4
    const int idx = i * 4;
    const int r = idx >> 11, c = idx & 2047;
    float4 v = make_float4(0.f,0.f,0.f,0.f);
    if (r < 96)                 v = *reinterpret_cast<const float4*>(f + r*2048 + c);
    else if (r >= 128 && r < 224) v = *reinterpret_cast<const float4*>(b + (r-128)*2048 + c);
    __nv_bfloat16 h0,h1,h2,h3,l0,l1,l2,l3;
    split1(v.x,h0,l0); split1(v.y,h1,l1); split1(v.z,h2,l2); split1(v.w,h3,l3);
    reinterpret_cast<__nv_bfloat162*>(g_Xph)[2*i]   = __nv_bfloat162(h0,h1);
    reinterpret_cast<__nv_bfloat162*>(g_Xph)[2*i+1] = __nv_bfloat162(h2,h3);
    reinterpret_cast<__nv_bfloat162*>(g_Xpl)[2*i]   = __nv_bfloat162(l0,l1);
    reinterpret_cast<__nv_bfloat162*>(g_Xpl)[2*i+1] = __nv_bfloat162(l2,l3);
}

// outW K-concat -> [1024][4096]: cols<2048 from f, else b
__global__ __launch_bounds__(256) void cvt_out(
    const float* __restrict__ f, const float* __restrict__ b)
{
    const int i = blockIdx.x * 256 + threadIdx.x;     // over 1024*4096/4
    const int idx = i * 4;
    const int r = idx >> 12, c = idx & 4095;
    float4 v = (c < 2048)
        ? *reinterpret_cast<const float4*>(f + (size_t)r*2048 + c)
        : *reinterpret_cast<const float4*>(b + (size_t)r*2048 + (c - 2048));
    __nv_bfloat16 h0,h1,h2,h3,l0,l1,l2,l3;
    split1(v.x,h0,l0); split1(v.y,h1,l1); split1(v.z,h2,l2); split1(v.w,h3,l3);
    reinterpret_cast<__nv_bfloat162*>(g_Wouth)[2*i]   = __nv_bfloat162(h0,h1);
    reinterpret_cast<__nv_bfloat162*>(g_Wouth)[2*i+1] = __nv_bfloat162(h2,h3);
    reinterpret_cast<__nv_bfloat162*>(g_Woutl)[2*i]   = __nv_bfloat162(l0,l1);
    reinterpret_cast<__nv_bfloat162*>(g_Woutl)[2*i+1] = __nv_bfloat162(l2,l3);
}

// ------------- depthwise conv + SiLU; writes fp32 U and bf16 planes ----------
__global__ __launch_bounds__(256) void conv_silu_kernel(
    const float* __restrict__ convW_f, const float* __restrict__ convB_f,
    const float* __restrict__ convW_b, const float* __restrict__ convB_b)
{
    const int i = blockIdx.x * 256 + threadIdx.x;   // over MROWS*4096
    const int c = i & 4095;
    const int row = i >> 12;
    const int l = row & (LSEQ - 1);
    const int b = row >> 10;
    const int dir = c >> 11;
    const int d = c & (DIN - 1);
    const float* w = (dir ? convW_b : convW_f) + d*4;
    float acc = (dir ? convB_b : convB_f)[d];
    const float* xi = g_XZ + dir*4096 + d;
    if (dir == 0) {
#pragma unroll
        for (int k = 0; k < 4; k++) {
            int ls = l - 3 + k;
            if (ls >= 0) acc = fmaf(w[k], xi[(size_t)(b*LSEQ + ls)*8192], acc);
        }
    } else {
#pragma unroll
        for (int k = 0; k < 4; k++) {
            int ls = l + 3 - k;
            if (ls < LSEQ) acc = fmaf(w[k], xi[(size_t)(b*LSEQ + ls)*8192], acc);
        }
    }
    const float sig = 1.f / (1.f + __expf(-acc));
    const float u = acc * sig;
    const size_t o = (size_t)row*4096 + c;
    g_U[o] = u;
    __nv_bfloat16 h, lo2; split1(u, h, lo2);
    g_Uh[o] = h; g_Ul[o] = lo2;
}

// ------------------------- split-K reduce + plane split ----------------------
__global__ __launch_bounds__(256) void reduce_xdbl_kernel()
{
    const int i = blockIdx.x * 256 + threadIdx.x;   // over MROWS*256
    float s = 0.f;
#pragma unroll
    for (int k = 0; k < 4; k++) s += g_XDBLP[(size_t)k*MROWS*256 + i];
    g_XDBL[i] = s;
    __nv_bfloat16 h, l; split1(s, h, l);
    g_XDh[i] = h; g_XDl[i] = l;
}

// ------------------- selective scan + gating; writes YG planes ---------------
__global__ __launch_bounds__(256) void scan_kernel(
    const float* __restrict__ Alog_f, const float* __restrict__ Alog_b,
    const float* __restrict__ Dp_f,  const float* __restrict__ Dp_b)
{
    const int dir = blockIdx.z;
    const int b   = blockIdx.y;
    const int d0  = blockIdx.x * 16;
    const int t  = threadIdx.x;
    const int dl = t >> 4;
    const int n  = t & 15;
    const int d  = d0 + dl;

    const float Acoef = -__expf((dir ? Alog_b : Alog_f)[d*NST + n]);
    const float DpV   = (dir ? Dp_b : Dp_f)[d];

    __shared__ float sD[32][16], sU[32][16], sZ[32][16], sB2[32][16], sC2[32][16];

    const int la0 = t >> 4, qa0 = t & 15;
    const int la1 = (t + 256) >> 4, qa1 = (t + 256) & 15;

    float rg[10];
    {
        const int lb = (dir == 0) ? 0 : (LSEQ - 32);
        const int row0 = b*LSEQ + lb + la0;
        const int row1 = b*LSEQ + lb + la1;
        rg[0] = g_DELTA[(size_t)row0*4096 + dir*2048 + d0 + qa0];
        rg[1] = g_DELTA[(size_t)row1*4096 + dir*2048 + d0 + qa1];
        rg[2] = g_U[(size_t)row0*4096 + dir*2048 + d0 + qa0];
        rg[3] = g_U[(size_t)row1*4096 + dir*2048 + d0 + qa1];
        rg[4] = g_XZ[(size_t)row0*8192 + dir*4096 + 2048 + d0 + qa0];
        rg[5] = g_XZ[(size_t)row1*8192 + dir*4096 + 2048 + d0 + qa1];
        rg[6] = g_XDBL[(size_t)row0*256 + dir*128 + 64 + qa0];
        rg[7] = g_XDBL[(size_t)row1*256 + dir*128 + 64 + qa1];
        rg[8] = g_XDBL[(size_t)row0*256 + dir*128 + 80 + qa0];
        rg[9] = g_XDBL[(size_t)row1*256 + dir*128 + 80 + qa1];
    }

    float h = 0.f;
    const int NCH = LSEQ / 32;
    for (int c = 0; c < NCH; c++) {
        __syncthreads();
        sD [la0][qa0] = rg[0]; sD [la1][qa1] = rg[1];
        sU [la0][qa0] = rg[2]; sU [la1][qa1] = rg[3];
        sZ [la0][qa0] = rg[4]; sZ [la1][qa1] = rg[5];
        sB2[la0][qa0] = rg[6]; sB2[la1][qa1] = rg[7];
        sC2[la0][qa0] = rg[8]; sC2[la1][qa1] = rg[9];
        __syncthreads();
        if (c + 1 < NCH) {
            const int lb = (dir == 0) ? (c+1)*32 : (LSEQ - (c+2)*32);
            const int row0 = b*LSEQ + lb + la0;
            const int row1 = b*LSEQ + lb + la1;
            rg[0] = g_DELTA[(size_t)row0*4096 + dir*2048 + d0 + qa0];
            rg[1] = g_DELTA[(size_t)row1*4096 + dir*2048 + d0 + qa1];
            rg[2] = g_U[(size_t)row0*4096 + dir*2048 + d0 + qa0];
            rg[3] = g_U[(size_t)row1*4096 + dir*2048 + d0 + qa1];
            rg[4] = g_XZ[(size_t)row0*8192 + dir*4096 + 2048 + d0 + qa0];
            rg[5] = g_XZ[(size_t)row1*8192 + dir*4096 + 2048 + d0 + qa1];
            rg[6] = g_XDBL[(size_t)row0*256 + dir*128 + 64 + qa0];
            rg[7] = g_XDBL[(size_t)row1*256 + dir*128 + 64 + qa1];
            rg[8] = g_XDBL[(size_t)row0*256 + dir*128 + 80 + qa0];
            rg[9] = g_XDBL[(size_t)row1*256 + dir*128 + 80 + qa1];
        }
        const int lb = (dir == 0) ? c*32 : (LSEQ - (c+1)*32);
#pragma unroll 4
        for (int s = 0; s < 32; s++) {
            const int ll = (dir == 0) ? s : (31 - s);
            const float del = sD[ll][dl];
            const float uu  = sU[ll][dl];
            const float dA  = __expf(del * Acoef);
            h = fmaf(h, dA, del * uu * sB2[ll][n]);
            float py = h * sC2[ll][n];
            py += __shfl_xor_sync(0xffffffffu, py, 8);
            py += __shfl_xor_sync(0xffffffffu, py, 4);
            py += __shfl_xor_sync(0xffffffffu, py, 2);
            py += __shfl_xor_sync(0xffffffffu, py, 1);
            if (n == 0) {
                const float zz = sZ[ll][dl];
                const float y = fmaf(uu, DpV, py);
                const float sig = 1.f / (1.f + __expf(-zz));
                const float yg = y * (zz * sig);
                const size_t o = (size_t)(b*LSEQ + lb + ll)*4096 + dir*2048 + d;
                __nv_bfloat16 hh, lo2; split1(yg, hh, lo2);
                g_YGh[o] = hh; g_YGl[o] = lo2;
            }
        }
    }
}

// ------------------------------------ launch ---------------------------------
extern "C" void kernel_launch(void* const* d_in, const int* in_sizes, int n_in,
                              void* d_out, int out_size)
{
    const float* x      = (const float*)d_in[0];
    const float* inW_f  = (const float*)d_in[1];
    const float* convW_f= (const float*)d_in[2];
    const float* convB_f= (const float*)d_in[3];
    const float* xpW_f  = (const float*)d_in[4];
    const float* dtW_f  = (const float*)d_in[5];
    const float* dtB_f  = (const float*)d_in[6];
    const float* Alog_f = (const float*)d_in[7];
    const float* Dp_f   = (const float*)d_in[8];
    const float* outW_f = (const float*)d_in[9];
    const float* inW_b  = (const float*)d_in[10];
    const float* convW_b= (const float*)d_in[11];
    const float* convB_b= (const float*)d_in[12];
    const float* xpW_b  = (const float*)d_in[13];
    const float* dtW_b  = (const float*)d_in[14];
    const float* dtB_b  = (const float*)d_in[15];
    const float* Alog_b = (const float*)d_in[16];
    const float* Dp_b   = (const float*)d_in[17];
    const float* outW_b = (const float*)d_in[18];
    float* out = (float*)d_out;

    float *XZ, *XDBLP, *DELTA;
    __nv_bfloat16 *Xh, *Xl, *Winh, *Winl, *Uh, *Ul, *Xph, *Xpl, *XDh, *XDl;
    __nv_bfloat16 *dtWh, *dtWl, *YGh, *YGl, *Wouth, *Woutl;
    cudaGetSymbolAddress((void**)&XZ,    g_XZ);
    cudaGetSymbolAddress((void**)&XDBLP, g_XDBLP);
    cudaGetSymbolAddress((void**)&DELTA, g_DELTA);
    cudaGetSymbolAddress((void**)&Xh,    g_Xh);
    cudaGetSymbolAddress((void**)&Xl,    g_Xl);
    cudaGetSymbolAddress((void**)&Winh,  g_Winh);
    cudaGetSymbolAddress((void**)&Winl,  g_Winl);
    cudaGetSymbolAddress((void**)&Uh,    g_Uh);
    cudaGetSymbolAddress((void**)&Ul,    g_Ul);
    cudaGetSymbolAddress((void**)&Xph,   g_Xph);
    cudaGetSymbolAddress((void**)&Xpl,   g_Xpl);
    cudaGetSymbolAddress((void**)&XDh,   g_XDh);
    cudaGetSymbolAddress((void**)&XDl,   g_XDl);
    cudaGetSymbolAddress((void**)&dtWh,  g_dtWh);
    cudaGetSymbolAddress((void**)&dtWl,  g_dtWl);
    cudaGetSymbolAddress((void**)&YGh,   g_YGh);
    cudaGetSymbolAddress((void**)&YGl,   g_YGl);
    cudaGetSymbolAddress((void**)&Wouth, g_Wouth);
    cudaGetSymbolAddress((void**)&Woutl, g_Woutl);

    cudaFuncSetAttribute(hgemm<0>, cudaFuncAttributeMaxDynamicSharedMemorySize, HG_SMEM);
    cudaFuncSetAttribute(hgemm<1>, cudaFuncAttributeMaxDynamicSharedMemorySize, HG_SMEM);
    cudaFuncSetAttribute(hgemm<2>, cudaFuncAttributeMaxDynamicSharedMemorySize, HG_SMEM);

    // 0) operand conversions (weights + x)
    cvt_plane<<<2048, 256>>>(x,      Xh,   Xl,   MROWS*DMODEL/4);
    cvt_plane<<<4096, 256>>>(inW_f,  Winh, Winl, 4096*DMODEL/4);
    cvt_plane<<<4096, 256>>>(inW_b,  Winh + 4096*DMODEL, Winl + 4096*DMODEL, 4096*DMODEL/4);
    cvt_plane<<<128,  256>>>(dtW_f,  dtWh, dtWl, 2048*DTR/4);
    cvt_plane<<<128,  256>>>(dtW_b,  dtWh + 2048*DTR, dtWl + 2048*DTR, 2048*DTR/4);
    cvt_xp  <<<512,  256>>>(xpW_f, xpW_b);
    cvt_out <<<4096, 256>>>(outW_f, outW_b);

    // 1) input projection: [2048,8192] = X[2048,1024] * Win[8192,1024]^T
    hgemm<0><<<dim3(64,16,1), 256, HG_SMEM>>>(
        Xh, Xl, DMODEL, 0, 0, Winh, Winl, DMODEL,
        XZ, 8192, DMODEL, nullptr, nullptr, 1.f, 0);

    // 2) depthwise conv + SiLU (emits U fp32 + planes)
    conv_silu_kernel<<<(MROWS*4096)/256, 256>>>(convW_f, convB_f, convW_b, convB_b);

    // 3) x_dbl: [2048,256] = U[.,dir-slice] * Xp[256,2048]^T, split-K=4
    hgemm<0><<<dim3(2,16,4), 256, HG_SMEM>>>(
        Uh, Ul, 4096, 2048, 128, Xph, Xpl, DIN,
        XDBLP, 256, DIN, nullptr, nullptr, 1.f, 512);
    reduce_xdbl_kernel<<<(MROWS*256)/256, 256>>>();

    // 4) delta = softplus(dt @ dtWcat^T + dtB), N=4096, K=64
    hgemm<1><<<dim3(32,16,1), 256, HG_SMEM>>>(
        XDh, XDl, 256, 128, 2048, dtWh, dtWl, DTR,
        DELTA, 4096, DTR, dtB_f, dtB_b, 1.f, 0);

    // 5) selective scan + gating (emits YG planes)
    scan_kernel<<<dim3(128,2,2), 256>>>(Alog_f, Alog_b, Dp_f, Dp_b);

    // 6) out = 0.5 * YG[2048,4096] * Wout[1024,4096]^T (K-concat)
    hgemm<2><<<dim3(8,16,1), 256, HG_SMEM>>>(
        YGh, YGl, 4096, 0, 0, Wouth, Woutl, 4096,
        out, DMODEL, 4096, nullptr, nullptr, 0.5f, 0);
}

// round 6
// speedup vs baseline: 1.0535x; 1.0535x over previous
#include <cuda_runtime.h>
#include <cuda_bf16.h>
#include <math.h>
#include <cstdint>

#define B_SZ   2
#define LSEQ   1024
#define DMODEL 1024
#define DIN    2048
#define NST    16
#define DTR    64
#define MROWS  (B_SZ*LSEQ)   /* 2048 */

// ---------------- scratch (device globals; no allocation allowed) ------------
__device__ float g_XZ[MROWS*8192];              // [m][dir*4096 + (xi | z)]
__device__ float g_U [MROWS*4096];              // fp32 for scan
__device__ __nv_bfloat16 g_Uh[MROWS*4096],  g_Ul[MROWS*4096];
__device__ __nv_bfloat16 g_Xh[MROWS*DMODEL], g_Xl[MROWS*DMODEL];
__device__ __nv_bfloat16 g_Winh[8192*DMODEL], g_Winl[8192*DMODEL];
__device__ __nv_bfloat16 g_Xph[256*DIN],    g_Xpl[256*DIN];      // padded xpW
__device__ float g_XDBLP[4*MROWS*256];
__device__ float g_XDBL[MROWS*256];
__device__ __nv_bfloat16 g_XDh[MROWS*256],  g_XDl[MROWS*256];
__device__ __nv_bfloat16 g_dtWh[4096*DTR],  g_dtWl[4096*DTR];    // dir-concat rows
__device__ float g_DELTA[(size_t)MROWS*4096];
__device__ __nv_bfloat16 g_YGh[MROWS*4096], g_YGl[MROWS*4096];
__device__ __nv_bfloat16 g_Wouth[DMODEL*4096], g_Woutl[DMODEL*4096]; // K-concat cols

// ======================= helpers =============================================
__device__ __forceinline__ uint32_t smem_u32(const void* p) {
    uint32_t a;
    asm("{ .reg .u64 t; cvta.to.shared.u64 t, %1; cvt.u32.u64 %0, t; }" : "=r"(a) : "l"(p));
    return a;
}
#define LDM4(r0,r1,r2,r3,addr)                                                      \
    asm volatile("ldmatrix.sync.aligned.m8n8.x4.shared.b16 {%0,%1,%2,%3}, [%4];"    \
        : "=r"(r0),"=r"(r1),"=r"(r2),"=r"(r3) : "r"(addr))
#define MMA16816(c,a,b)                                                             \
    asm volatile("mma.sync.aligned.m16n8k16.row.col.f32.bf16.bf16.f32 "             \
        "{%0,%1,%2,%3}, {%4,%5,%6,%7}, {%8,%9}, {%0,%1,%2,%3};"                     \
        : "+f"((c)[0]),"+f"((c)[1]),"+f"((c)[2]),"+f"((c)[3])                       \
        : "r"((a)[0]),"r"((a)[1]),"r"((a)[2]),"r"((a)[3]),"r"((b)[0]),"r"((b)[1]))
#define CPA16(dst, src) asm volatile("cp.async.cg.shared.global [%0], [%1], 16;" :: "r"(dst), "l"(src) : "memory")
#define CPCOMMIT()      asm volatile("cp.async.commit_group;" ::: "memory")
#define CPWAIT0()       asm volatile("cp.async.wait_group 0;" ::: "memory")
#define CPWAIT1()       asm volatile("cp.async.wait_group 1;" ::: "memory")

__device__ __forceinline__ void split1(float v, __nv_bfloat16& h, __nv_bfloat16& l) {
    h = __float2bfloat16(v);
    l = __float2bfloat16(v - __bfloat162float(h));
}

// ======================= HMMA GEMM (pre-split bf16 hi/lo planes) =============
// C[M,N] = A[M,K]*B[N,K]^T, fp32 via hi*hi + hi*lo + lo*hi.
// A gets +a_off1 (elements) when CTA n-tile >= nsplit (dir-dependent A slice).
// kz>0: split-K over blockIdx.z; C offset by z*M*ldc (partials).
// EPI: 0 = store, 1 = softplus(acc + bias[n]) (bias0/bias1 split at nsplit),
//      2 = store alpha*acc
#define BKC 32
#define ASTRIDE 80             /* bytes per smem row: 32 bf16 + 8 pad */
#define STG_A_HI 0
#define STG_A_LO 10240
#define STG_B_HI 20480
#define STG_B_LO 30720
#define STG_STRIDE 40960
#define HG_SMEM (2*STG_STRIDE)

template<int EPI>
__global__ __launch_bounds__(256, 2) void hgemm(
    const __nv_bfloat16* __restrict__ Ah, const __nv_bfloat16* __restrict__ Al,
    int lda, int a_off1, int nsplit,
    const __nv_bfloat16* __restrict__ Bh, const __nv_bfloat16* __restrict__ Bl,
    int ldb,
    float* __restrict__ C, int ldc, int K,
    const float* __restrict__ bias0, const float* __restrict__ bias1,
    float alpha, int kz)
{
    extern __shared__ char sm[];
    const uint32_t smb = smem_u32(sm);
    const int tid = threadIdx.x;
    const int bm = blockIdx.y * 128, bn = blockIdx.x * 128;
    if (kz > 0) {
        Ah += (size_t)blockIdx.z * kz;  Al += (size_t)blockIdx.z * kz;
        Bh += (size_t)blockIdx.z * kz;  Bl += (size_t)blockIdx.z * kz;
        C  += (size_t)blockIdx.z * (size_t)(gridDim.y * 128) * (size_t)ldc;
        K = kz;
    }
    const int aoff = (nsplit && bn >= nsplit) ? a_off1 : 0;

    // ---- producer: each thread owns 2x16B per plane per chunk ---------------
    const int grow = tid >> 1;               // 0..127
    const int seg  = (tid & 1) << 1;         // 0 or 2 (16B units within 64B row)
    const char* gAh = (const char*)(Ah + aoff + (size_t)(bm + grow) * lda);
    const char* gAl = (const char*)(Al + aoff + (size_t)(bm + grow) * lda);
    const char* gBh = (const char*)(Bh + (size_t)(bn + grow) * ldb);
    const char* gBl = (const char*)(Bl + (size_t)(bn + grow) * ldb);
    const uint32_t srow = smb + (uint32_t)(grow * ASTRIDE + seg * 16);

    // ---- warp geometry ------------------------------------------------------
    const int wid = tid >> 5, lane = tid & 31;
    const int wm = (wid >> 2) * 64;
    const int wn = (wid & 3) * 32;
    const int tq = lane >> 2, tr = lane & 3;
    const uint32_t aoffm = (uint32_t)((wm + (lane & 15)) * ASTRIDE + ((lane >> 4) << 4));
    const int g = lane >> 3;
    const uint32_t boffm = (uint32_t)((wn + ((g >> 1) << 3) + (lane & 7)) * ASTRIDE + ((g & 1) << 4));

    float acc[4][4][4];
#pragma unroll
    for (int i = 0; i < 4; i++)
#pragma unroll
        for (int j = 0; j < 4; j++)
#pragma unroll
            for (int q = 0; q < 4; q++) acc[i][j][q] = 0.f;

    const int nch = K / BKC;

    auto issue = [&](int s) {
        const uint32_t st = srow + (uint32_t)(s & 1) * STG_STRIDE;
        const int go = s * (BKC * 2) + seg * 16;     // byte offset in gmem row
        CPA16(st + STG_A_HI,      gAh + go);
        CPA16(st + STG_A_HI + 16, gAh + go + 16);
        CPA16(st + STG_A_LO,      gAl + go);
        CPA16(st + STG_A_LO + 16, gAl + go + 16);
        CPA16(st + STG_B_HI,      gBh + go);
        CPA16(st + STG_B_HI + 16, gBh + go + 16);
        CPA16(st + STG_B_LO,      gBl + go);
        CPA16(st + STG_B_LO + 16, gBl + go + 16);
        CPCOMMIT();
    };

    issue(0);
    for (int s = 0; s < nch; s++) {
        if (s + 1 < nch) { issue(s + 1); CPWAIT1(); }
        else             { CPWAIT0(); }
        __syncthreads();
        const uint32_t sa = smb + (uint32_t)(s & 1) * STG_STRIDE;
#pragma unroll
        for (int ph = 0; ph < 2; ph++) {
            const uint32_t ka = sa + ph * 32;        // +16 bf16 per k-phase
            uint32_t ah[4][4], al[4][4], bh[4][2], bl[4][2];
#pragma unroll
            for (int i = 0; i < 4; i++)
                LDM4(ah[i][0], ah[i][1], ah[i][2], ah[i][3], ka + STG_A_HI + aoffm + i*(16*ASTRIDE));
#pragma unroll
            for (int i = 0; i < 4; i++)
                LDM4(al[i][0], al[i][1], al[i][2], al[i][3], ka + STG_A_LO + aoffm + i*(16*ASTRIDE));
            LDM4(bh[0][0], bh[0][1], bh[1][0], bh[1][1], ka + STG_B_HI + boffm);
            LDM4(bh[2][0], bh[2][1], bh[3][0], bh[3][1], ka + STG_B_HI + boffm + 16*ASTRIDE);
            LDM4(bl[0][0], bl[0][1], bl[1][0], bl[1][1], ka + STG_B_LO + boffm);
            LDM4(bl[2][0], bl[2][1], bl[3][0], bl[3][1], ka + STG_B_LO + boffm + 16*ASTRIDE);
            // term-major ordering: 16 independent accumulators between reuses
#pragma unroll
            for (int i = 0; i < 4; i++)
#pragma unroll
                for (int j = 0; j < 4; j++)
                    MMA16816(acc[i][j], ah[i], bh[j]);
#pragma unroll
            for (int i = 0; i < 4; i++)
#pragma unroll
                for (int j = 0; j < 4; j++)
                    MMA16816(acc[i][j], ah[i], bl[j]);
#pragma unroll
            for (int i = 0; i < 4; i++)
#pragma unroll
                for (int j = 0; j < 4; j++)
                    MMA16816(acc[i][j], al[i], bh[j]);
        }
        __syncthreads();
    }

    // ---- epilogue -----------------------------------------------------------
    const float* bias = nullptr;
    if (EPI == 1) bias = (nsplit && bn >= nsplit) ? (bias1 - nsplit) : bias0;
#pragma unroll
    for (int i = 0; i < 4; i++) {
        const int row0 = bm + wm + 16*i + tq;
#pragma unroll
        for (int j = 0; j < 4; j++) {
            const int col = bn + wn + 8*j + 2*tr;
            float v0 = acc[i][j][0], v1 = acc[i][j][1];
            float v2 = acc[i][j][2], v3 = acc[i][j][3];
            if (EPI == 1) {
                const float b0v = bias[col], b1v = bias[col+1];
                v0 += b0v; v1 += b1v; v2 += b0v; v3 += b1v;
                v0 = (v0 > 20.f) ? v0 : log1pf(__expf(v0));
                v1 = (v1 > 20.f) ? v1 : log1pf(__expf(v1));
                v2 = (v2 > 20.f) ? v2 : log1pf(__expf(v2));
                v3 = (v3 > 20.f) ? v3 : log1pf(__expf(v3));
            } else if (EPI == 2) {
                v0 *= alpha; v1 *= alpha; v2 *= alpha; v3 *= alpha;
            }
            *reinterpret_cast<float2*>(C + (size_t)row0 * ldc + col)       = make_float2(v0, v1);
            *reinterpret_cast<float2*>(C + (size_t)(row0 + 8) * ldc + col) = make_float2(v2, v3);
        }
    }
}

// ======================= convert kernels =====================================
__global__ __launch_bounds__(256) void cvt_plane(
    const float* __restrict__ src, __nv_bfloat16* __restrict__ hi,
    __nv_bfloat16* __restrict__ lo, int n4)
{
    const int i = blockIdx.x * 256 + threadIdx.x;
    if (i >= n4) return;
    float4 v = reinterpret_cast<const float4*>(src)[i];
    __nv_bfloat16 h0,h1,h2,h3,l0,l1,l2,l3;
    split1(v.x,h0,l0); split1(v.y,h1,l1); split1(v.z,h2,l2); split1(v.w,h3,l3);
    reinterpret_cast<__nv_bfloat162*>(hi)[2*i]   = __nv_bfloat162(h0,h1);
    reinterpret_cast<__nv_bfloat162*>(hi)[2*i+1] = __nv_bfloat162(h2,h3);
    reinterpret_cast<__nv_bfloat162*>(lo)[2*i]   = __nv_bfloat162(l0,l1);
    reinterpret_cast<__nv_bfloat162*>(lo)[2*i+1] = __nv_bfloat162(l2,l3);
}

// xpW -> [256][2048]: rows 0-95 f, 96-127 zero, 128-223 b, 224-255 zero
__global__ __launch_bounds__(256) void cvt_xp(
    const float* __restrict__ f, const float* __restrict__ b)
{
    const int i = blockIdx.x * 256 + threadIdx.x;     // over 256*2048/4
    const int idx = i * 4;
    const int r = idx >> 11, c = idx & 2047;
    float4 v = make_float4(0.f,0.f,0.f,0.f);
    if (r < 96)                 v = *reinterpret_cast<const float4*>(f + r*2048 + c);
    else if (r >= 128 && r < 224) v = *reinterpret_cast<const float4*>(b + (r-128)*2048 + c);
    __nv_bfloat16 h0,h1,h2,h3,l0,l1,l2,l3;
    split1(v.x,h0,l0); split1(v.y,h1,l1); split1(v.z,h2,l2); split1(v.w,h3,l3);
    reinterpret_cast<__nv_bfloat162*>(g_Xph)[2*i]   = __nv_bfloat162(h0,h1);
    reinterpret_cast<__nv_bfloat162*>(g_Xph)[2*i+1] = __nv_bfloat162(h2,h3);
    reinterpret_cast<__nv_bfloat162*>(g_Xpl)[2*i]   = __nv_bfloat162(l0,l1);
    reinterpret_cast<__nv_bfloat162*>(g_Xpl)[2*i+1] = __nv_bfloat162(l2,l3);
}

// outW K-concat -> [1024][4096]: cols<2048 from f, else b
__global__ __launch_bounds__(256) void cvt_out(
    const float* __restrict__ f, const float* __restrict__ b)
{
    const int i = blockIdx.x * 256 + threadIdx.x;     // over 1024*4096/4
    const int idx = i * 4;
    const int r = idx >> 12, c = idx & 4095;
    float4 v = (c < 2048)
        ? *reinterpret_cast<const float4*>(f + (size_t)r*2048 + c)
        : *reinterpret_cast<const float4*>(b + (size_t)r*2048 + (c - 2048));
    __nv_bfloat16 h0,h1,h2,h3,l0,l1,l2,l3;
    split1(v.x,h0,l0); split1(v.y,h1,l1); split1(v.z,h2,l2); split1(v.w,h3,l3);
    reinterpret_cast<__nv_bfloat162*>(g_Wouth)[2*i]   = __nv_bfloat162(h0,h1);
    reinterpret_cast<__nv_bfloat162*>(g_Wouth)[2*i+1] = __nv_bfloat162(h2,h3);
    reinterpret_cast<__nv_bfloat162*>(g_Woutl)[2*i]   = __nv_bfloat162(l0,l1);
    reinterpret_cast<__nv_bfloat162*>(g_Woutl)[2*i+1] = __nv_bfloat162(l2,l3);
}

// ------------- depthwise conv + SiLU; writes fp32 U and bf16 planes ----------
__global__ __launch_bounds__(256) void conv_silu_kernel(
    const float* __restrict__ convW_f, const float* __restrict__ convB_f,
    const float* __restrict__ convW_b, const float* __restrict__ convB_b)
{
    const int i = blockIdx.x * 256 + threadIdx.x;   // over MROWS*4096
    const int c = i & 4095;
    const int row = i >> 12;
    const int l = row & (LSEQ - 1);
    const int b = row >> 10;
    const int dir = c >> 11;
    const int d = c & (DIN - 1);
    const float* w = (dir ? convW_b : convW_f) + d*4;
    float acc = (dir ? convB_b : convB_f)[d];
    const float* xi = g_XZ + dir*4096 + d;
    if (dir == 0) {
#pragma unroll
        for (int k = 0; k < 4; k++) {
            int ls = l - 3 + k;
            if (ls >= 0) acc = fmaf(w[k], xi[(size_t)(b*LSEQ + ls)*8192], acc);
        }
    } else {
#pragma unroll
        for (int k = 0; k < 4; k++) {
            int ls = l + 3 - k;
            if (ls < LSEQ) acc = fmaf(w[k], xi[(size_t)(b*LSEQ + ls)*8192], acc);
        }
    }
    const float sig = 1.f / (1.f + __expf(-acc));
    const float u = acc * sig;
    const size_t o = (size_t)row*4096 + c;
    g_U[o] = u;
    __nv_bfloat16 h, lo2; split1(u, h, lo2);
    g_Uh[o] = h; g_Ul[o] = lo2;
}

// ------------------------- split-K reduce + plane split ----------------------
__global__ __launch_bounds__(256) void reduce_xdbl_kernel()
{
    const int i = blockIdx.x * 256 + threadIdx.x;   // over MROWS*256
    float s = 0.f;
#pragma unroll
    for (int k = 0; k < 4; k++) s += g_XDBLP[(size_t)k*MROWS*256 + i];
    g_XDBL[i] = s;
    __nv_bfloat16 h, l; split1(s, h, l);
    g_XDh[i] = h; g_XDl[i] = l;
}

// ------------------- selective scan + gating; writes YG planes ---------------
__global__ __launch_bounds__(256) void scan_kernel(
    const float* __restrict__ Alog_f, const float* __restrict__ Alog_b,
    const float* __restrict__ Dp_f,  const float* __restrict__ Dp_b)
{
    const int dir = blockIdx.z;
    const int b   = blockIdx.y;
    const int d0  = blockIdx.x * 16;
    const int t  = threadIdx.x;
    const int dl = t >> 4;
    const int n  = t & 15;
    const int d  = d0 + dl;

    const float Acoef = -__expf((dir ? Alog_b : Alog_f)[d*NST + n]);
    const float DpV   = (dir ? Dp_b : Dp_f)[d];

    __shared__ float sD[32][16], sU[32][16], sZ[32][16], sB2[32][16], sC2[32][16];

    const int la0 = t >> 4, qa0 = t & 15;
    const int la1 = (t + 256) >> 4, qa1 = (t + 256) & 15;

    float rg[10];
    {
        const int lb = (dir == 0) ? 0 : (LSEQ - 32);
        const int row0 = b*LSEQ + lb + la0;
        const int row1 = b*LSEQ + lb + la1;
        rg[0] = g_DELTA[(size_t)row0*4096 + dir*2048 + d0 + qa0];
        rg[1] = g_DELTA[(size_t)row1*4096 + dir*2048 + d0 + qa1];
        rg[2] = g_U[(size_t)row0*4096 + dir*2048 + d0 + qa0];
        rg[3] = g_U[(size_t)row1*4096 + dir*2048 + d0 + qa1];
        rg[4] = g_XZ[(size_t)row0*8192 + dir*4096 + 2048 + d0 + qa0];
        rg[5] = g_XZ[(size_t)row1*8192 + dir*4096 + 2048 + d0 + qa1];
        rg[6] = g_XDBL[(size_t)row0*256 + dir*128 + 64 + qa0];
        rg[7] = g_XDBL[(size_t)row1*256 + dir*128 + 64 + qa1];
        rg[8] = g_XDBL[(size_t)row0*256 + dir*128 + 80 + qa0];
        rg[9] = g_XDBL[(size_t)row1*256 + dir*128 + 80 + qa1];
    }

    float h = 0.f;
    const int NCH = LSEQ / 32;
    for (int c = 0; c < NCH; c++) {
        __syncthreads();
        sD [la0][qa0] = rg[0]; sD [la1][qa1] = rg[1];
        sU [la0][qa0] = rg[2]; sU [la1][qa1] = rg[3];
        sZ [la0][qa0] = rg[4]; sZ [la1][qa1] = rg[5];
        sB2[la0][qa0] = rg[6]; sB2[la1][qa1] = rg[7];
        sC2[la0][qa0] = rg[8]; sC2[la1][qa1] = rg[9];
        __syncthreads();
        if (c + 1 < NCH) {
            const int lb = (dir == 0) ? (c+1)*32 : (LSEQ - (c+2)*32);
            const int row0 = b*LSEQ + lb + la0;
            const int row1 = b*LSEQ + lb + la1;
            rg[0] = g_DELTA[(size_t)row0*4096 + dir*2048 + d0 + qa0];
            rg[1] = g_DELTA[(size_t)row1*4096 + dir*2048 + d0 + qa1];
            rg[2] = g_U[(size_t)row0*4096 + dir*2048 + d0 + qa0];
            rg[3] = g_U[(size_t)row1*4096 + dir*2048 + d0 + qa1];
            rg[4] = g_XZ[(size_t)row0*8192 + dir*4096 + 2048 + d0 + qa0];
            rg[5] = g_XZ[(size_t)row1*8192 + dir*4096 + 2048 + d0 + qa1];
            rg[6] = g_XDBL[(size_t)row0*256 + dir*128 + 64 + qa0];
            rg[7] = g_XDBL[(size_t)row1*256 + dir*128 + 64 + qa1];
            rg[8] = g_XDBL[(size_t)row0*256 + dir*128 + 80 + qa0];
            rg[9] = g_XDBL[(size_t)row1*256 + dir*128 + 80 + qa1];
        }
        const int lb = (dir == 0) ? c*32 : (LSEQ - (c+1)*32);
#pragma unroll 4
        for (int s = 0; s < 32; s++) {
            const int ll = (dir == 0) ? s : (31 - s);
            const float del = sD[ll][dl];
            const float uu  = sU[ll][dl];
            const float dA  = __expf(del * Acoef);
            h = fmaf(h, dA, del * uu * sB2[ll][n]);
            float py = h * sC2[ll][n];
            py += __shfl_xor_sync(0xffffffffu, py, 8);
            py += __shfl_xor_sync(0xffffffffu, py, 4);
            py += __shfl_xor_sync(0xffffffffu, py, 2);
            py += __shfl_xor_sync(0xffffffffu, py, 1);
            if (n == 0) {
                const float zz = sZ[ll][dl];
                const float y = fmaf(uu, DpV, py);
                const float sig = 1.f / (1.f + __expf(-zz));
                const float yg = y * (zz * sig);
                const size_t o = (size_t)(b*LSEQ + lb + ll)*4096 + dir*2048 + d;
                __nv_bfloat16 hh, lo2; split1(yg, hh, lo2);
                g_YGh[o] = hh; g_YGl[o] = lo2;
            }
        }
    }
}

// ------------------------------------ launch ---------------------------------
extern "C" void kernel_launch(void* const* d_in, const int* in_sizes, int n_in,
                              void* d_out, int out_size)
{
    const float* x      = (const float*)d_in[0];
    const float* inW_f  = (const float*)d_in[1];
    const float* convW_f= (const float*)d_in[2];
    const float* convB_f= (const float*)d_in[3];
    const float* xpW_f  = (const float*)d_in[4];
    const float* dtW_f  = (const float*)d_in[5];
    const float* dtB_f  = (const float*)d_in[6];
    const float* Alog_f = (const float*)d_in[7];
    const float* Dp_f   = (const float*)d_in[8];
    const float* outW_f = (const float*)d_in[9];
    const float* inW_b  = (const float*)d_in[10];
    const float* convW_b= (const float*)d_in[11];
    const float* convB_b= (const float*)d_in[12];
    const float* xpW_b  = (const float*)d_in[13];
    const float* dtW_b  = (const float*)d_in[14];
    const float* dtB_b  = (const float*)d_in[15];
    const float* Alog_b = (const float*)d_in[16];
    const float* Dp_b   = (const float*)d_in[17];
    const float* outW_b = (const float*)d_in[18];
    float* out = (float*)d_out;

    float *XZ, *XDBLP, *DELTA;
    __nv_bfloat16 *Xh, *Xl, *Winh, *Winl, *Uh, *Ul, *Xph, *Xpl, *XDh, *XDl;
    __nv_bfloat16 *dtWh, *dtWl, *YGh, *YGl, *Wouth, *Woutl;
    cudaGetSymbolAddress((void**)&XZ,    g_XZ);
    cudaGetSymbolAddress((void**)&XDBLP, g_XDBLP);
    cudaGetSymbolAddress((void**)&DELTA, g_DELTA);
    cudaGetSymbolAddress((void**)&Xh,    g_Xh);
    cudaGetSymbolAddress((void**)&Xl,    g_Xl);
    cudaGetSymbolAddress((void**)&Winh,  g_Winh);
    cudaGetSymbolAddress((void**)&Winl,  g_Winl);
    cudaGetSymbolAddress((void**)&Uh,    g_Uh);
    cudaGetSymbolAddress((void**)&Ul,    g_Ul);
    cudaGetSymbolAddress((void**)&Xph,   g_Xph);
    cudaGetSymbolAddress((void**)&Xpl,   g_Xpl);
    cudaGetSymbolAddress((void**)&XDh,   g_XDh);
    cudaGetSymbolAddress((void**)&XDl,   g_XDl);
    cudaGetSymbolAddress((void**)&dtWh,  g_dtWh);
    cudaGetSymbolAddress((void**)&dtWl,  g_dtWl);
    cudaGetSymbolAddress((void**)&YGh,   g_YGh);
    cudaGetSymbolAddress((void**)&YGl,   g_YGl);
    cudaGetSymbolAddress((void**)&Wouth, g_Wouth);
    cudaGetSymbolAddress((void**)&Woutl, g_Woutl);

    cudaFuncSetAttribute(hgemm<0>, cudaFuncAttributeMaxDynamicSharedMemorySize, HG_SMEM);
    cudaFuncSetAttribute(hgemm<1>, cudaFuncAttributeMaxDynamicSharedMemorySize, HG_SMEM);
    cudaFuncSetAttribute(hgemm<2>, cudaFuncAttributeMaxDynamicSharedMemorySize, HG_SMEM);

    // 0) converts feeding in-proj (launches 0-2), then in-proj at launch index 3
    //    so the ncu capture slot lands on the big GEMM.
    cvt_plane<<<2048, 256>>>(x,      Xh,   Xl,   MROWS*DMODEL/4);
    cvt_plane<<<4096, 256>>>(inW_f,  Winh, Winl, 4096*DMODEL/4);
    cvt_plane<<<4096, 256>>>(inW_b,  Winh + 4096*DMODEL, Winl + 4096*DMODEL, 4096*DMODEL/4);

    // 1) input projection: [2048,8192] = X[2048,1024] * Win[8192,1024]^T
    hgemm<0><<<dim3(64,16,1), 256, HG_SMEM>>>(
        Xh, Xl, DMODEL, 0, 0, Winh, Winl, DMODEL,
        XZ, 8192, DMODEL, nullptr, nullptr, 1.f, 0);

    // remaining converts (feed later stages only)
    cvt_plane<<<128,  256>>>(dtW_f,  dtWh, dtWl, 2048*DTR/4);
    cvt_plane<<<128,  256>>>(dtW_b,  dtWh + 2048*DTR, dtWl + 2048*DTR, 2048*DTR/4);
    cvt_xp  <<<512,  256>>>(xpW_f, xpW_b);
    cvt_out <<<4096, 256>>>(outW_f, outW_b);

    // 2) depthwise conv + SiLU (emits U fp32 + planes)
    conv_silu_kernel<<<(MROWS*4096)/256, 256>>>(convW_f, convB_f, convW_b, convB_b);

    // 3) x_dbl: [2048,256] = U[.,dir-slice] * Xp[256,2048]^T, split-K=4
    hgemm<0><<<dim3(2,16,4), 256, HG_SMEM>>>(
        Uh, Ul, 4096, 2048, 128, Xph, Xpl, DIN,
        XDBLP, 256, DIN, nullptr, nullptr, 1.f, 512);
    reduce_xdbl_kernel<<<(MROWS*256)/256, 256>>>();

    // 4) delta = softplus(dt @ dtWcat^T + dtB), N=4096, K=64
    hgemm<1><<<dim3(32,16,1), 256, HG_SMEM>>>(
        XDh, XDl, 256, 128, 2048, dtWh, dtWl, DTR,
        DELTA, 4096, DTR, dtB_f, dtB_b, 1.f, 0);

    // 5) selective scan + gating (emits YG planes)
    scan_kernel<<<dim3(128,2,2), 256>>>(Alog_f, Alog_b, Dp_f, Dp_b);

    // 6) out = 0.5 * YG[2048,4096] * Wout[1024,4096]^T (K-concat)
    hgemm<2><<<dim3(8,16,1), 256, HG_SMEM>>>(
        YGh, YGl, 4096, 0, 0, Wouth, Woutl, 4096,
        out, DMODEL, 4096, nullptr, nullptr, 0.5f, 0);
}

// round 7
// speedup vs baseline: 1.0838x; 1.0287x over previous
#include <cuda_runtime.h>
#include <cuda_bf16.h>
#include <math.h>
#include <cstdint>

#define B_SZ   2
#define LSEQ   1024
#define DMODEL 1024
#define DIN    2048
#define NST    16
#define DTR    64
#define MROWS  (B_SZ*LSEQ)   /* 2048 */

// ---------------- scratch (device globals; no allocation allowed) ------------
__device__ float g_XZ[MROWS*8192];              // [m][dir*4096 + (xi | z)]
__device__ float g_U [MROWS*4096];              // fp32 for scan
__device__ __nv_bfloat16 g_Uh[MROWS*4096],  g_Ul[MROWS*4096];
__device__ __nv_bfloat16 g_Xh[MROWS*DMODEL], g_Xl[MROWS*DMODEL];
__device__ __nv_bfloat16 g_Winh[8192*DMODEL], g_Winl[8192*DMODEL];
__device__ __nv_bfloat16 g_Xph[256*DIN],    g_Xpl[256*DIN];      // padded xpW
__device__ float g_XDBLP[8*MROWS*256];
__device__ float g_XDBL[MROWS*256];
__device__ __nv_bfloat16 g_XDh[MROWS*256],  g_XDl[MROWS*256];
__device__ __nv_bfloat16 g_dtWh[4096*DTR],  g_dtWl[4096*DTR];    // dir-concat rows
__device__ float g_DELTA[(size_t)MROWS*4096];
__device__ __nv_bfloat16 g_YGh[MROWS*4096], g_YGl[MROWS*4096];
__device__ __nv_bfloat16 g_Wouth[DMODEL*4096], g_Woutl[DMODEL*4096]; // K-concat cols
__device__ float g_OUTP[2*MROWS*DMODEL];        // out-proj split-K partials

// ======================= helpers =============================================
__device__ __forceinline__ uint32_t smem_u32(const void* p) {
    uint32_t a;
    asm("{ .reg .u64 t; cvta.to.shared.u64 t, %1; cvt.u32.u64 %0, t; }" : "=r"(a) : "l"(p));
    return a;
}
#define LDM4(r0,r1,r2,r3,addr)                                                      \
    asm volatile("ldmatrix.sync.aligned.m8n8.x4.shared.b16 {%0,%1,%2,%3}, [%4];"    \
        : "=r"(r0),"=r"(r1),"=r"(r2),"=r"(r3) : "r"(addr))
#define MMA16816(c,a,b)                                                             \
    asm volatile("mma.sync.aligned.m16n8k16.row.col.f32.bf16.bf16.f32 "             \
        "{%0,%1,%2,%3}, {%4,%5,%6,%7}, {%8,%9}, {%0,%1,%2,%3};"                     \
        : "+f"((c)[0]),"+f"((c)[1]),"+f"((c)[2]),"+f"((c)[3])                       \
        : "r"((a)[0]),"r"((a)[1]),"r"((a)[2]),"r"((a)[3]),"r"((b)[0]),"r"((b)[1]))
#define CPA16(dst, src) asm volatile("cp.async.cg.shared.global [%0], [%1], 16;" :: "r"(dst), "l"(src) : "memory")
#define CPCOMMIT()      asm volatile("cp.async.commit_group;" ::: "memory")
#define CPWAIT0()       asm volatile("cp.async.wait_group 0;" ::: "memory")

__device__ __forceinline__ void split1(float v, __nv_bfloat16& h, __nv_bfloat16& l) {
    h = __float2bfloat16(v);
    l = __float2bfloat16(v - __bfloat162float(h));
}

// ======================= HMMA GEMM (pre-split bf16 hi/lo planes) =============
// C[M,N] = A[M,K]*B[N,K]^T, fp32 via hi*hi + hi*lo + lo*hi.
// A gets +a_off1 (elements) when CTA n-tile >= nsplit (dir-dependent A slice).
// kz>0: split-K over blockIdx.z; C offset by z*M*ldc (partials).
// EPI: 0 = store, 1 = softplus(acc + bias[n]) (bias0/bias1 split at nsplit)
#define BKC 32
#define ASTRIDE 80             /* bytes per smem row: 32 bf16 + 8 pad */
#define STG_A_HI 0
#define STG_A_LO 10240
#define STG_B_HI 20480
#define STG_B_LO 30720
#define STG_STRIDE 40960
#define HG_SMEM (2*STG_STRIDE)

template<int EPI>
__global__ __launch_bounds__(256, 2) void hgemm(
    const __nv_bfloat16* __restrict__ Ah, const __nv_bfloat16* __restrict__ Al,
    int lda, int a_off1, int nsplit,
    const __nv_bfloat16* __restrict__ Bh, const __nv_bfloat16* __restrict__ Bl,
    int ldb,
    float* __restrict__ C, int ldc, int K,
    const float* __restrict__ bias0, const float* __restrict__ bias1,
    int kz)
{
    extern __shared__ char sm[];
    const uint32_t smb = smem_u32(sm);
    const int tid = threadIdx.x;
    const int bm = blockIdx.y * 128, bn = blockIdx.x * 128;
    if (kz > 0) {
        Ah += (size_t)blockIdx.z * kz;  Al += (size_t)blockIdx.z * kz;
        Bh += (size_t)blockIdx.z * kz;  Bl += (size_t)blockIdx.z * kz;
        C  += (size_t)blockIdx.z * (size_t)(gridDim.y * 128) * (size_t)ldc;
        K = kz;
    }
    const int aoff = (nsplit && bn >= nsplit) ? a_off1 : 0;

    // ---- producer: each thread owns 2x16B per plane per chunk ---------------
    const int grow = tid >> 1;               // 0..127
    const int seg  = (tid & 1) << 1;         // 0 or 2 (16B units within 64B row)
    const char* gAh = (const char*)(Ah + aoff + (size_t)(bm + grow) * lda);
    const char* gAl = (const char*)(Al + aoff + (size_t)(bm + grow) * lda);
    const char* gBh = (const char*)(Bh + (size_t)(bn + grow) * ldb);
    const char* gBl = (const char*)(Bl + (size_t)(bn + grow) * ldb);
    const uint32_t srow = smb + (uint32_t)(grow * ASTRIDE + seg * 16);

    // ---- warp geometry ------------------------------------------------------
    const int wid = tid >> 5, lane = tid & 31;
    const int wm = (wid >> 2) * 64;
    const int wn = (wid & 3) * 32;
    const int tq = lane >> 2, tr = lane & 3;
    const uint32_t aoffm = (uint32_t)((wm + (lane & 15)) * ASTRIDE + ((lane >> 4) << 4));
    const int g = lane >> 3;
    const uint32_t boffm = (uint32_t)((wn + ((g >> 1) << 3) + (lane & 7)) * ASTRIDE + ((g & 1) << 4));

    float acc[4][4][4];
#pragma unroll
    for (int i = 0; i < 4; i++)
#pragma unroll
        for (int j = 0; j < 4; j++)
#pragma unroll
            for (int q = 0; q < 4; q++) acc[i][j][q] = 0.f;

    const int nch = K / BKC;

    auto issue = [&](int s) {
        const uint32_t st = srow + (uint32_t)(s & 1) * STG_STRIDE;
        const int go = s * (BKC * 2) + seg * 16;     // byte offset in gmem row
        CPA16(st + STG_A_HI,      gAh + go);
        CPA16(st + STG_A_HI + 16, gAh + go + 16);
        CPA16(st + STG_A_LO,      gAl + go);
        CPA16(st + STG_A_LO + 16, gAl + go + 16);
        CPA16(st + STG_B_HI,      gBh + go);
        CPA16(st + STG_B_HI + 16, gBh + go + 16);
        CPA16(st + STG_B_LO,      gBl + go);
        CPA16(st + STG_B_LO + 16, gBl + go + 16);
        CPCOMMIT();
    };

    issue(0);
    for (int s = 0; s < nch; s++) {
        CPWAIT0();                 // buf s&1 fully resident
        __syncthreads();           // + all warps done reading buf (s+1)&1 (chunk s-1)
        if (s + 1 < nch) issue(s + 1);   // overlaps compute(s)
        const uint32_t sa = smb + (uint32_t)(s & 1) * STG_STRIDE;
#pragma unroll
        for (int ph = 0; ph < 2; ph++) {
            const uint32_t ka = sa + ph * 32;        // +16 bf16 per k-phase
            uint32_t ah[4][4], al[4][4], bh[4][2], bl[4][2];
#pragma unroll
            for (int i = 0; i < 4; i++)
                LDM4(ah[i][0], ah[i][1], ah[i][2], ah[i][3], ka + STG_A_HI + aoffm + i*(16*ASTRIDE));
#pragma unroll
            for (int i = 0; i < 4; i++)
                LDM4(al[i][0], al[i][1], al[i][2], al[i][3], ka + STG_A_LO + aoffm + i*(16*ASTRIDE));
            LDM4(bh[0][0], bh[0][1], bh[1][0], bh[1][1], ka + STG_B_HI + boffm);
            LDM4(bh[2][0], bh[2][1], bh[3][0], bh[3][1], ka + STG_B_HI + boffm + 16*ASTRIDE);
            LDM4(bl[0][0], bl[0][1], bl[1][0], bl[1][1], ka + STG_B_LO + boffm);
            LDM4(bl[2][0], bl[2][1], bl[3][0], bl[3][1], ka + STG_B_LO + boffm + 16*ASTRIDE);
#pragma unroll
            for (int i = 0; i < 4; i++)
#pragma unroll
                for (int j = 0; j < 4; j++)
                    MMA16816(acc[i][j], ah[i], bh[j]);
#pragma unroll
            for (int i = 0; i < 4; i++)
#pragma unroll
                for (int j = 0; j < 4; j++)
                    MMA16816(acc[i][j], ah[i], bl[j]);
#pragma unroll
            for (int i = 0; i < 4; i++)
#pragma unroll
                for (int j = 0; j < 4; j++)
                    MMA16816(acc[i][j], al[i], bh[j]);
        }
    }

    // ---- epilogue -----------------------------------------------------------
    const float* bias = nullptr;
    if (EPI == 1) bias = (nsplit && bn >= nsplit) ? (bias1 - nsplit) : bias0;
#pragma unroll
    for (int i = 0; i < 4; i++) {
        const int row0 = bm + wm + 16*i + tq;
#pragma unroll
        for (int j = 0; j < 4; j++) {
            const int col = bn + wn + 8*j + 2*tr;
            float v0 = acc[i][j][0], v1 = acc[i][j][1];
            float v2 = acc[i][j][2], v3 = acc[i][j][3];
            if (EPI == 1) {
                const float b0v = bias[col], b1v = bias[col+1];
                v0 += b0v; v1 += b1v; v2 += b0v; v3 += b1v;
                v0 = (v0 > 20.f) ? v0 : log1pf(__expf(v0));
                v1 = (v1 > 20.f) ? v1 : log1pf(__expf(v1));
                v2 = (v2 > 20.f) ? v2 : log1pf(__expf(v2));
                v3 = (v3 > 20.f) ? v3 : log1pf(__expf(v3));
            }
            *reinterpret_cast<float2*>(C + (size_t)row0 * ldc + col)       = make_float2(v0, v1);
            *reinterpret_cast<float2*>(C + (size_t)(row0 + 8) * ldc + col) = make_float2(v2, v3);
        }
    }
}

// ======================= convert kernels =====================================
__global__ __launch_bounds__(256) void cvt_plane(
    const float* __restrict__ src, __nv_bfloat16* __restrict__ hi,
    __nv_bfloat16* __restrict__ lo, int n4)
{
    const int i = blockIdx.x * 256 + threadIdx.x;
    if (i >= n4) return;
    float4 v = reinterpret_cast<const float4*>(src)[i];
    __nv_bfloat16 h0,h1,h2,h3,l0,l1,l2,l3;
    split1(v.x,h0,l0); split1(v.y,h1,l1); split1(v.z,h2,l2); split1(v.w,h3,l3);
    reinterpret_cast<__nv_bfloat162*>(hi)[2*i]   = __nv_bfloat162(h0,h1);
    reinterpret_cast<__nv_bfloat162*>(hi)[2*i+1] = __nv_bfloat162(h2,h3);
    reinterpret_cast<__nv_bfloat162*>(lo)[2*i]   = __nv_bfloat162(l0,l1);
    reinterpret_cast<__nv_bfloat162*>(lo)[2*i+1] = __nv_bfloat162(l2,l3);
}

// xpW -> [256][2048]: rows 0-95 f, 96-127 zero, 128-223 b, 224-255 zero
__global__ __launch_bounds__(256) void cvt_xp(
    const float* __restrict__ f, const float* __restrict__ b)
{
    const int i = blockIdx.x * 256 + threadIdx.x;     // over 256*2048/4
    const int idx = i * 4;
    const int r = idx >> 11, c = idx & 2047;
    float4 v = make_float4(0.f,0.f,0.f,0.f);
    if (r < 96)                 v = *reinterpret_cast<const float4*>(f + r*2048 + c);
    else if (r >= 128 && r < 224) v = *reinterpret_cast<const float4*>(b + (r-128)*2048 + c);
    __nv_bfloat16 h0,h1,h2,h3,l0,l1,l2,l3;
    split1(v.x,h0,l0); split1(v.y,h1,l1); split1(v.z,h2,l2); split1(v.w,h3,l3);
    reinterpret_cast<__nv_bfloat162*>(g_Xph)[2*i]   = __nv_bfloat162(h0,h1);
    reinterpret_cast<__nv_bfloat162*>(g_Xph)[2*i+1] = __nv_bfloat162(h2,h3);
    reinterpret_cast<__nv_bfloat162*>(g_Xpl)[2*i]   = __nv_bfloat162(l0,l1);
    reinterpret_cast<__nv_bfloat162*>(g_Xpl)[2*i+1] = __nv_bfloat162(l2,l3);
}

// outW K-concat -> [1024][4096]: cols<2048 from f, else b
__global__ __launch_bounds__(256) void cvt_out(
    const float* __restrict__ f, const float* __restrict__ b)
{
    const int i = blockIdx.x * 256 + threadIdx.x;     // over 1024*4096/4
    const int idx = i * 4;
    const int r = idx >> 12, c = idx & 4095;
    float4 v = (c < 2048)
        ? *reinterpret_cast<const float4*>(f + (size_t)r*2048 + c)
        : *reinterpret_cast<const float4*>(b + (size_t)r*2048 + (c - 2048));
    __nv_bfloat16 h0,h1,h2,h3,l0,l1,l2,l3;
    split1(v.x,h0,l0); split1(v.y,h1,l1); split1(v.z,h2,l2); split1(v.w,h3,l3);
    reinterpret_cast<__nv_bfloat162*>(g_Wouth)[2*i]   = __nv_bfloat162(h0,h1);
    reinterpret_cast<__nv_bfloat162*>(g_Wouth)[2*i+1] = __nv_bfloat162(h2,h3);
    reinterpret_cast<__nv_bfloat162*>(g_Woutl)[2*i]   = __nv_bfloat162(l0,l1);
    reinterpret_cast<__nv_bfloat162*>(g_Woutl)[2*i+1] = __nv_bfloat162(l2,l3);
}

// out = 0.5*(p0 + p1)   (out-proj split-K combine, fused 0.5x)
__global__ __launch_bounds__(256) void reduce_out_kernel(float* __restrict__ out)
{
    const int i = blockIdx.x * 256 + threadIdx.x;     // over MROWS*DMODEL/4
    const float4 a = reinterpret_cast<const float4*>(g_OUTP)[i];
    const float4 b = reinterpret_cast<const float4*>(g_OUTP + MROWS*DMODEL)[i];
    reinterpret_cast<float4*>(out)[i] =
        make_float4(0.5f*(a.x+b.x), 0.5f*(a.y+b.y), 0.5f*(a.z+b.z), 0.5f*(a.w+b.w));
}

// ------------- depthwise conv + SiLU; writes fp32 U and bf16 planes ----------
__global__ __launch_bounds__(256) void conv_silu_kernel(
    const float* __restrict__ convW_f, const float* __restrict__ convB_f,
    const float* __restrict__ convW_b, const float* __restrict__ convB_b)
{
    const int i = blockIdx.x * 256 + threadIdx.x;   // over MROWS*4096
    const int c = i & 4095;
    const int row = i >> 12;
    const int l = row & (LSEQ - 1);
    const int b = row >> 10;
    const int dir = c >> 11;
    const int d = c & (DIN - 1);
    const float* w = (dir ? convW_b : convW_f) + d*4;
    float acc = (dir ? convB_b : convB_f)[d];
    const float* xi = g_XZ + dir*4096 + d;
    if (dir == 0) {
#pragma unroll
        for (int k = 0; k < 4; k++) {
            int ls = l - 3 + k;
            if (ls >= 0) acc = fmaf(w[k], xi[(size_t)(b*LSEQ + ls)*8192], acc);
        }
    } else {
#pragma unroll
        for (int k = 0; k < 4; k++) {
            int ls = l + 3 - k;
            if (ls < LSEQ) acc = fmaf(w[k], xi[(size_t)(b*LSEQ + ls)*8192], acc);
        }
    }
    const float sig = 1.f / (1.f + __expf(-acc));
    const float u = acc * sig;
    const size_t o = (size_t)row*4096 + c;
    g_U[o] = u;
    __nv_bfloat16 h, lo2; split1(u, h, lo2);
    g_Uh[o] = h; g_Ul[o] = lo2;
}

// ------------------------- split-K reduce + plane split ----------------------
__global__ __launch_bounds__(256) void reduce_xdbl_kernel()
{
    const int i = blockIdx.x * 256 + threadIdx.x;   // over MROWS*256
    float s = 0.f;
#pragma unroll
    for (int k = 0; k < 8; k++) s += g_XDBLP[(size_t)k*MROWS*256 + i];
    g_XDBL[i] = s;
    __nv_bfloat16 h, l; split1(s, h, l);
    g_XDh[i] = h; g_XDl[i] = l;
}

// ------------------- selective scan + gating; writes YG planes ---------------
__global__ __launch_bounds__(256) void scan_kernel(
    const float* __restrict__ Alog_f, const float* __restrict__ Alog_b,
    const float* __restrict__ Dp_f,  const float* __restrict__ Dp_b)
{
    const int dir = blockIdx.z;
    const int b   = blockIdx.y;
    const int d0  = blockIdx.x * 16;
    const int t  = threadIdx.x;
    const int dl = t >> 4;
    const int n  = t & 15;
    const int d  = d0 + dl;

    const float Acoef = -__expf((dir ? Alog_b : Alog_f)[d*NST + n]);
    const float DpV   = (dir ? Dp_b : Dp_f)[d];

    __shared__ float sD[32][16], sU[32][16], sZ[32][16], sB2[32][16], sC2[32][16];

    const int la0 = t >> 4, qa0 = t & 15;
    const int la1 = (t + 256) >> 4, qa1 = (t + 256) & 15;

    float rg[10];
    {
        const int lb = (dir == 0) ? 0 : (LSEQ - 32);
        const int row0 = b*LSEQ + lb + la0;
        const int row1 = b*LSEQ + lb + la1;
        rg[0] = g_DELTA[(size_t)row0*4096 + dir*2048 + d0 + qa0];
        rg[1] = g_DELTA[(size_t)row1*4096 + dir*2048 + d0 + qa1];
        rg[2] = g_U[(size_t)row0*4096 + dir*2048 + d0 + qa0];
        rg[3] = g_U[(size_t)row1*4096 + dir*2048 + d0 + qa1];
        rg[4] = g_XZ[(size_t)row0*8192 + dir*4096 + 2048 + d0 + qa0];
        rg[5] = g_XZ[(size_t)row1*8192 + dir*4096 + 2048 + d0 + qa1];
        rg[6] = g_XDBL[(size_t)row0*256 + dir*128 + 64 + qa0];
        rg[7] = g_XDBL[(size_t)row1*256 + dir*128 + 64 + qa1];
        rg[8] = g_XDBL[(size_t)row0*256 + dir*128 + 80 + qa0];
        rg[9] = g_XDBL[(size_t)row1*256 + dir*128 + 80 + qa1];
    }

    float h = 0.f;
    const int NCH = LSEQ / 32;
    for (int c = 0; c < NCH; c++) {
        __syncthreads();
        sD [la0][qa0] = rg[0]; sD [la1][qa1] = rg[1];
        sU [la0][qa0] = rg[2]; sU [la1][qa1] = rg[3];
        sZ [la0][qa0] = rg[4]; sZ [la1][qa1] = rg[5];
        sB2[la0][qa0] = rg[6]; sB2[la1][qa1] = rg[7];
        sC2[la0][qa0] = rg[8]; sC2[la1][qa1] = rg[9];
        __syncthreads();
        if (c + 1 < NCH) {
            const int lb = (dir == 0) ? (c+1)*32 : (LSEQ - (c+2)*32);
            const int row0 = b*LSEQ + lb + la0;
            const int row1 = b*LSEQ + lb + la1;
            rg[0] = g_DELTA[(size_t)row0*4096 + dir*2048 + d0 + qa0];
            rg[1] = g_DELTA[(size_t)row1*4096 + dir*2048 + d0 + qa1];
            rg[2] = g_U[(size_t)row0*4096 + dir*2048 + d0 + qa0];
            rg[3] = g_U[(size_t)row1*4096 + dir*2048 + d0 + qa1];
            rg[4] = g_XZ[(size_t)row0*8192 + dir*4096 + 2048 + d0 + qa0];
            rg[5] = g_XZ[(size_t)row1*8192 + dir*4096 + 2048 + d0 + qa1];
            rg[6] = g_XDBL[(size_t)row0*256 + dir*128 + 64 + qa0];
            rg[7] = g_XDBL[(size_t)row1*256 + dir*128 + 64 + qa1];
            rg[8] = g_XDBL[(size_t)row0*256 + dir*128 + 80 + qa0];
            rg[9] = g_XDBL[(size_t)row1*256 + dir*128 + 80 + qa1];
        }
        const int lb = (dir == 0) ? c*32 : (LSEQ - (c+1)*32);
#pragma unroll 4
        for (int s = 0; s < 32; s++) {
            const int ll = (dir == 0) ? s : (31 - s);
            const float del = sD[ll][dl];
            const float uu  = sU[ll][dl];
            const float dA  = __expf(del * Acoef);
            h = fmaf(h, dA, del * uu * sB2[ll][n]);
            float py = h * sC2[ll][n];
            py += __shfl_xor_sync(0xffffffffu, py, 8);
            py += __shfl_xor_sync(0xffffffffu, py, 4);
            py += __shfl_xor_sync(0xffffffffu, py, 2);
            py += __shfl_xor_sync(0xffffffffu, py, 1);
            if (n == 0) {
                const float zz = sZ[ll][dl];
                const float y = fmaf(uu, DpV, py);
                const float sig = 1.f / (1.f + __expf(-zz));
                const float yg = y * (zz * sig);
                const size_t o = (size_t)(b*LSEQ + lb + ll)*4096 + dir*2048 + d;
                __nv_bfloat16 hh, lo2; split1(yg, hh, lo2);
                g_YGh[o] = hh; g_YGl[o] = lo2;
            }
        }
    }
}

// ------------------------------------ launch ---------------------------------
extern "C" void kernel_launch(void* const* d_in, const int* in_sizes, int n_in,
                              void* d_out, int out_size)
{
    const float* x      = (const float*)d_in[0];
    const float* inW_f  = (const float*)d_in[1];
    const float* convW_f= (const float*)d_in[2];
    const float* convB_f= (const float*)d_in[3];
    const float* xpW_f  = (const float*)d_in[4];
    const float* dtW_f  = (const float*)d_in[5];
    const float* dtB_f  = (const float*)d_in[6];
    const float* Alog_f = (const float*)d_in[7];
    const float* Dp_f   = (const float*)d_in[8];
    const float* outW_f = (const float*)d_in[9];
    const float* inW_b  = (const float*)d_in[10];
    const float* convW_b= (const float*)d_in[11];
    const float* convB_b= (const float*)d_in[12];
    const float* xpW_b  = (const float*)d_in[13];
    const float* dtW_b  = (const float*)d_in[14];
    const float* dtB_b  = (const float*)d_in[15];
    const float* Alog_b = (const float*)d_in[16];
    const float* Dp_b   = (const float*)d_in[17];
    const float* outW_b = (const float*)d_in[18];
    float* out = (float*)d_out;

    float *XZ, *XDBLP, *DELTA, *OUTP;
    __nv_bfloat16 *Xh, *Xl, *Winh, *Winl, *Uh, *Ul, *Xph, *Xpl, *XDh, *XDl;
    __nv_bfloat16 *dtWh, *dtWl, *YGh, *YGl, *Wouth, *Woutl;
    cudaGetSymbolAddress((void**)&XZ,    g_XZ);
    cudaGetSymbolAddress((void**)&XDBLP, g_XDBLP);
    cudaGetSymbolAddress((void**)&DELTA, g_DELTA);
    cudaGetSymbolAddress((void**)&OUTP,  g_OUTP);
    cudaGetSymbolAddress((void**)&Xh,    g_Xh);
    cudaGetSymbolAddress((void**)&Xl,    g_Xl);
    cudaGetSymbolAddress((void**)&Winh,  g_Winh);
    cudaGetSymbolAddress((void**)&Winl,  g_Winl);
    cudaGetSymbolAddress((void**)&Uh,    g_Uh);
    cudaGetSymbolAddress((void**)&Ul,    g_Ul);
    cudaGetSymbolAddress((void**)&Xph,   g_Xph);
    cudaGetSymbolAddress((void**)&Xpl,   g_Xpl);
    cudaGetSymbolAddress((void**)&XDh,   g_XDh);
    cudaGetSymbolAddress((void**)&XDl,   g_XDl);
    cudaGetSymbolAddress((void**)&dtWh,  g_dtWh);
    cudaGetSymbolAddress((void**)&dtWl,  g_dtWl);
    cudaGetSymbolAddress((void**)&YGh,   g_YGh);
    cudaGetSymbolAddress((void**)&YGl,   g_YGl);
    cudaGetSymbolAddress((void**)&Wouth, g_Wouth);
    cudaGetSymbolAddress((void**)&Woutl, g_Woutl);

    cudaFuncSetAttribute(hgemm<0>, cudaFuncAttributeMaxDynamicSharedMemorySize, HG_SMEM);
    cudaFuncSetAttribute(hgemm<1>, cudaFuncAttributeMaxDynamicSharedMemorySize, HG_SMEM);

    // 0) converts feeding in-proj (launches 0-2); in-proj stays at ncu slot 3
    cvt_plane<<<2048, 256>>>(x,      Xh,   Xl,   MROWS*DMODEL/4);
    cvt_plane<<<4096, 256>>>(inW_f,  Winh, Winl, 4096*DMODEL/4);
    cvt_plane<<<4096, 256>>>(inW_b,  Winh + 4096*DMODEL, Winl + 4096*DMODEL, 4096*DMODEL/4);

    // 1) input projection: [2048,8192] = X[2048,1024] * Win[8192,1024]^T
    hgemm<0><<<dim3(64,16,1), 256, HG_SMEM>>>(
        Xh, Xl, DMODEL, 0, 0, Winh, Winl, DMODEL,
        XZ, 8192, DMODEL, nullptr, nullptr, 0);

    // remaining converts (feed later stages only)
    cvt_plane<<<128,  256>>>(dtW_f,  dtWh, dtWl, 2048*DTR/4);
    cvt_plane<<<128,  256>>>(dtW_b,  dtWh + 2048*DTR, dtWl + 2048*DTR, 2048*DTR/4);
    cvt_xp  <<<512,  256>>>(xpW_f, xpW_b);
    cvt_out <<<4096, 256>>>(outW_f, outW_b);

    // 2) depthwise conv + SiLU (emits U fp32 + planes)
    conv_silu_kernel<<<(MROWS*4096)/256, 256>>>(convW_f, convB_f, convW_b, convB_b);

    // 3) x_dbl: [2048,256] = U[.,dir-slice] * Xp[256,2048]^T, split-K=8
    hgemm<0><<<dim3(2,16,8), 256, HG_SMEM>>>(
        Uh, Ul, 4096, 2048, 128, Xph, Xpl, DIN,
        XDBLP, 256, DIN, nullptr, nullptr, 256);
    reduce_xdbl_kernel<<<(MROWS*256)/256, 256>>>();

    // 4) delta = softplus(dt @ dtWcat^T + dtB), N=4096, K=64
    hgemm<1><<<dim3(32,16,1), 256, HG_SMEM>>>(
        XDh, XDl, 256, 128, 2048, dtWh, dtWl, DTR,
        DELTA, 4096, DTR, dtB_f, dtB_b, 0);

    // 5) selective scan + gating (emits YG planes)
    scan_kernel<<<dim3(128,2,2), 256>>>(Alog_f, Alog_b, Dp_f, Dp_b);

    // 6) out-proj split-K=2: partials, then out = 0.5*(p0+p1)
    hgemm<0><<<dim3(8,16,2), 256, HG_SMEM>>>(
        YGh, YGl, 4096, 0, 0, Wouth, Woutl, 4096,
        OUTP, DMODEL, 4096, nullptr, nullptr, 2048);
    reduce_out_kernel<<<(MROWS*DMODEL/4)/256, 256>>>(out);
}

// round 8
// speedup vs baseline: 1.0910x; 1.0067x over previous
#include <cuda_runtime.h>
#include <cuda_bf16.h>
#include <math.h>
#include <cstdint>

#define B_SZ   2
#define LSEQ   1024
#define DMODEL 1024
#define DIN    2048
#define NST    16
#define DTR    64
#define MROWS  (B_SZ*LSEQ)   /* 2048 */

// ---------------- scratch (device globals; no allocation allowed) ------------
__device__ float g_XZ[MROWS*8192];              // [m][dir*4096 + (xi | z)]
__device__ float g_U [MROWS*4096];              // fp32 for scan
__device__ __nv_bfloat16 g_Uh[MROWS*4096],  g_Ul[MROWS*4096];
__device__ __nv_bfloat16 g_Xh[MROWS*DMODEL], g_Xl[MROWS*DMODEL];
__device__ __nv_bfloat16 g_Winh[8192*DMODEL], g_Winl[8192*DMODEL];
__device__ __nv_bfloat16 g_Xph[256*DIN],    g_Xpl[256*DIN];      // padded xpW
__device__ float g_XDBLP[8*MROWS*256];
__device__ float g_XDBL[MROWS*256];
__device__ __nv_bfloat16 g_XDh[MROWS*256],  g_XDl[MROWS*256];
__device__ __nv_bfloat16 g_dtWh[4096*DTR],  g_dtWl[4096*DTR];    // dir-concat rows
__device__ float g_DELTA[(size_t)MROWS*4096];
__device__ __nv_bfloat16 g_YGh[MROWS*4096], g_YGl[MROWS*4096];
__device__ __nv_bfloat16 g_Wouth[DMODEL*4096], g_Woutl[DMODEL*4096]; // K-concat cols
__device__ float g_OUTP[4*MROWS*DMODEL];        // out-proj split-K=4 partials

// ======================= helpers =============================================
__device__ __forceinline__ uint32_t smem_u32(const void* p) {
    uint32_t a;
    asm("{ .reg .u64 t; cvta.to.shared.u64 t, %1; cvt.u32.u64 %0, t; }" : "=r"(a) : "l"(p));
    return a;
}
#define LDM4(r0,r1,r2,r3,addr)                                                      \
    asm volatile("ldmatrix.sync.aligned.m8n8.x4.shared.b16 {%0,%1,%2,%3}, [%4];"    \
        : "=r"(r0),"=r"(r1),"=r"(r2),"=r"(r3) : "r"(addr))
#define MMA16816(c,a,b)                                                             \
    asm volatile("mma.sync.aligned.m16n8k16.row.col.f32.bf16.bf16.f32 "             \
        "{%0,%1,%2,%3}, {%4,%5,%6,%7}, {%8,%9}, {%0,%1,%2,%3};"                     \
        : "+f"((c)[0]),"+f"((c)[1]),"+f"((c)[2]),"+f"((c)[3])                       \
        : "r"((a)[0]),"r"((a)[1]),"r"((a)[2]),"r"((a)[3]),"r"((b)[0]),"r"((b)[1]))
#define CPA16(dst, src) asm volatile("cp.async.cg.shared.global [%0], [%1], 16;" :: "r"(dst), "l"(src) : "memory")
#define CPCOMMIT()      asm volatile("cp.async.commit_group;" ::: "memory")
#define CPWAIT0()       asm volatile("cp.async.wait_group 0;" ::: "memory")

__device__ __forceinline__ void split1(float v, __nv_bfloat16& h, __nv_bfloat16& l) {
    h = __float2bfloat16(v);
    l = __float2bfloat16(v - __bfloat162float(h));
}
__device__ __forceinline__ void store_planes(
    __nv_bfloat16* __restrict__ hi, __nv_bfloat16* __restrict__ lo,
    int i /*float4 idx*/, float4 v)
{
    __nv_bfloat16 h0,h1,h2,h3,l0,l1,l2,l3;
    split1(v.x,h0,l0); split1(v.y,h1,l1); split1(v.z,h2,l2); split1(v.w,h3,l3);
    reinterpret_cast<__nv_bfloat162*>(hi)[2*i]   = __nv_bfloat162(h0,h1);
    reinterpret_cast<__nv_bfloat162*>(hi)[2*i+1] = __nv_bfloat162(h2,h3);
    reinterpret_cast<__nv_bfloat162*>(lo)[2*i]   = __nv_bfloat162(l0,l1);
    reinterpret_cast<__nv_bfloat162*>(lo)[2*i+1] = __nv_bfloat162(l2,l3);
}

// ======================= HMMA GEMM (pre-split bf16 hi/lo planes) =============
#define BKC 32
#define ASTRIDE 80             /* bytes per smem row: 32 bf16 + 8 pad */
#define STG_A_HI 0
#define STG_A_LO 10240
#define STG_B_HI 20480
#define STG_B_LO 30720
#define STG_STRIDE 40960
#define HG_SMEM (2*STG_STRIDE)

template<int EPI>
__global__ __launch_bounds__(256, 2) void hgemm(
    const __nv_bfloat16* __restrict__ Ah, const __nv_bfloat16* __restrict__ Al,
    int lda, int a_off1, int nsplit,
    const __nv_bfloat16* __restrict__ Bh, const __nv_bfloat16* __restrict__ Bl,
    int ldb,
    float* __restrict__ C, int ldc, int K,
    const float* __restrict__ bias0, const float* __restrict__ bias1,
    int kz)
{
    extern __shared__ char sm[];
    const uint32_t smb = smem_u32(sm);
    const int tid = threadIdx.x;
    const int bm = blockIdx.y * 128, bn = blockIdx.x * 128;
    if (kz > 0) {
        Ah += (size_t)blockIdx.z * kz;  Al += (size_t)blockIdx.z * kz;
        Bh += (size_t)blockIdx.z * kz;  Bl += (size_t)blockIdx.z * kz;
        C  += (size_t)blockIdx.z * (size_t)(gridDim.y * 128) * (size_t)ldc;
        K = kz;
    }
    const int aoff = (nsplit && bn >= nsplit) ? a_off1 : 0;

    const int grow = tid >> 1;
    const int seg  = (tid & 1) << 1;
    const char* gAh = (const char*)(Ah + aoff + (size_t)(bm + grow) * lda);
    const char* gAl = (const char*)(Al + aoff + (size_t)(bm + grow) * lda);
    const char* gBh = (const char*)(Bh + (size_t)(bn + grow) * ldb);
    const char* gBl = (const char*)(Bl + (size_t)(bn + grow) * ldb);
    const uint32_t srow = smb + (uint32_t)(grow * ASTRIDE + seg * 16);

    const int wid = tid >> 5, lane = tid & 31;
    const int wm = (wid >> 2) * 64;
    const int wn = (wid & 3) * 32;
    const int tq = lane >> 2, tr = lane & 3;
    const uint32_t aoffm = (uint32_t)((wm + (lane & 15)) * ASTRIDE + ((lane >> 4) << 4));
    const int g = lane >> 3;
    const uint32_t boffm = (uint32_t)((wn + ((g >> 1) << 3) + (lane & 7)) * ASTRIDE + ((g & 1) << 4));

    float acc[4][4][4];
#pragma unroll
    for (int i = 0; i < 4; i++)
#pragma unroll
        for (int j = 0; j < 4; j++)
#pragma unroll
            for (int q = 0; q < 4; q++) acc[i][j][q] = 0.f;

    const int nch = K / BKC;

    auto issue = [&](int s) {
        const uint32_t st = srow + (uint32_t)(s & 1) * STG_STRIDE;
        const int go = s * (BKC * 2) + seg * 16;
        CPA16(st + STG_A_HI,      gAh + go);
        CPA16(st + STG_A_HI + 16, gAh + go + 16);
        CPA16(st + STG_A_LO,      gAl + go);
        CPA16(st + STG_A_LO + 16, gAl + go + 16);
        CPA16(st + STG_B_HI,      gBh + go);
        CPA16(st + STG_B_HI + 16, gBh + go + 16);
        CPA16(st + STG_B_LO,      gBl + go);
        CPA16(st + STG_B_LO + 16, gBl + go + 16);
        CPCOMMIT();
    };

    issue(0);
    for (int s = 0; s < nch; s++) {
        CPWAIT0();
        __syncthreads();
        if (s + 1 < nch) issue(s + 1);
        const uint32_t sa = smb + (uint32_t)(s & 1) * STG_STRIDE;
#pragma unroll
        for (int ph = 0; ph < 2; ph++) {
            const uint32_t ka = sa + ph * 32;
            uint32_t ah[4][4], al[4][4], bh[4][2], bl[4][2];
            // phase A: hi fragments only, then 16 independent hh MMAs
#pragma unroll
            for (int i = 0; i < 4; i++)
                LDM4(ah[i][0], ah[i][1], ah[i][2], ah[i][3], ka + STG_A_HI + aoffm + i*(16*ASTRIDE));
            LDM4(bh[0][0], bh[0][1], bh[1][0], bh[1][1], ka + STG_B_HI + boffm);
            LDM4(bh[2][0], bh[2][1], bh[3][0], bh[3][1], ka + STG_B_HI + boffm + 16*ASTRIDE);
#pragma unroll
            for (int i = 0; i < 4; i++)
#pragma unroll
                for (int j = 0; j < 4; j++)
                    MMA16816(acc[i][j], ah[i], bh[j]);
            // phase B: lo fragments load under the hh MMAs' shadow, then hl+lh
#pragma unroll
            for (int i = 0; i < 4; i++)
                LDM4(al[i][0], al[i][1], al[i][2], al[i][3], ka + STG_A_LO + aoffm + i*(16*ASTRIDE));
            LDM4(bl[0][0], bl[0][1], bl[1][0], bl[1][1], ka + STG_B_LO + boffm);
            LDM4(bl[2][0], bl[2][1], bl[3][0], bl[3][1], ka + STG_B_LO + boffm + 16*ASTRIDE);
#pragma unroll
            for (int i = 0; i < 4; i++)
#pragma unroll
                for (int j = 0; j < 4; j++)
                    MMA16816(acc[i][j], ah[i], bl[j]);
#pragma unroll
            for (int i = 0; i < 4; i++)
#pragma unroll
                for (int j = 0; j < 4; j++)
                    MMA16816(acc[i][j], al[i], bh[j]);
        }
    }

    const float* bias = nullptr;
    if (EPI == 1) bias = (nsplit && bn >= nsplit) ? (bias1 - nsplit) : bias0;
#pragma unroll
    for (int i = 0; i < 4; i++) {
        const int row0 = bm + wm + 16*i + tq;
#pragma unroll
        for (int j = 0; j < 4; j++) {
            const int col = bn + wn + 8*j + 2*tr;
            float v0 = acc[i][j][0], v1 = acc[i][j][1];
            float v2 = acc[i][j][2], v3 = acc[i][j][3];
            if (EPI == 1) {
                const float b0v = bias[col], b1v = bias[col+1];
                v0 += b0v; v1 += b1v; v2 += b0v; v3 += b1v;
                v0 = (v0 > 20.f) ? v0 : log1pf(__expf(v0));
                v1 = (v1 > 20.f) ? v1 : log1pf(__expf(v1));
                v2 = (v2 > 20.f) ? v2 : log1pf(__expf(v2));
                v3 = (v3 > 20.f) ? v3 : log1pf(__expf(v3));
            }
            *reinterpret_cast<float2*>(C + (size_t)row0 * ldc + col)       = make_float2(v0, v1);
            *reinterpret_cast<float2*>(C + (size_t)(row0 + 8) * ldc + col) = make_float2(v2, v3);
        }
    }
}

// ======================= merged convert kernels ===============================
#define N4_X    (MROWS*DMODEL/4)        /* 524288  */
#define N4_INW  (4096*DMODEL/4)         /* 1048576 per dir */
#define N4_DTW  (2048*DTR/4)            /* 32768 per dir */
#define N4_XP   (256*DIN/4)             /* 131072 */
#define N4_OUT  (DMODEL*4096/4)         /* 1048576 */

__global__ __launch_bounds__(256) void cvt_x_kernel(const float* __restrict__ x)
{
    const int i = blockIdx.x * 256 + threadIdx.x;
    store_planes(g_Xh, g_Xl, i, reinterpret_cast<const float4*>(x)[i]);
}

__global__ __launch_bounds__(256) void cvt_inw_kernel(
    const float* __restrict__ f, const float* __restrict__ b)
{
    const int i = blockIdx.x * 256 + threadIdx.x;   // over 2*N4_INW
    const float4 v = (i < N4_INW)
        ? reinterpret_cast<const float4*>(f)[i]
        : reinterpret_cast<const float4*>(b)[i - N4_INW];
    store_planes(g_Winh, g_Winl, i, v);
}

__global__ __launch_bounds__(256) void cvt_rest_kernel(
    const float* __restrict__ dtW_f, const float* __restrict__ dtW_b,
    const float* __restrict__ xpW_f, const float* __restrict__ xpW_b,
    const float* __restrict__ outW_f, const float* __restrict__ outW_b)
{
    int i = blockIdx.x * 256 + threadIdx.x;
    if (i < 2*N4_DTW) {                        // dtW f|b -> g_dtW planes
        const float4 v = (i < N4_DTW)
            ? reinterpret_cast<const float4*>(dtW_f)[i]
            : reinterpret_cast<const float4*>(dtW_b)[i - N4_DTW];
        store_planes(g_dtWh, g_dtWl, i, v);
        return;
    }
    i -= 2*N4_DTW;
    if (i < N4_XP) {                           // padded xpW [256][2048]
        const int idx = i * 4;
        const int r = idx >> 11, c = idx & 2047;
        float4 v = make_float4(0.f,0.f,0.f,0.f);
        if (r < 96)                   v = *reinterpret_cast<const float4*>(xpW_f + r*2048 + c);
        else if (r >= 128 && r < 224) v = *reinterpret_cast<const float4*>(xpW_b + (r-128)*2048 + c);
        store_planes(g_Xph, g_Xpl, i, v);
        return;
    }
    i -= N4_XP;                                // outW K-concat [1024][4096]
    {
        const int idx = i * 4;
        const int r = idx >> 12, c = idx & 4095;
        const float4 v = (c < 2048)
            ? *reinterpret_cast<const float4*>(outW_f + (size_t)r*2048 + c)
            : *reinterpret_cast<const float4*>(outW_b + (size_t)r*2048 + (c - 2048));
        store_planes(g_Wouth, g_Woutl, i, v);
    }
}

// out = 0.5*(p0+p1+p2+p3)
__global__ __launch_bounds__(256) void reduce_out_kernel(float* __restrict__ out)
{
    const int i = blockIdx.x * 256 + threadIdx.x;
    float4 s = reinterpret_cast<const float4*>(g_OUTP)[i];
#pragma unroll
    for (int k = 1; k < 4; k++) {
        const float4 p = reinterpret_cast<const float4*>(g_OUTP + (size_t)k*MROWS*DMODEL)[i];
        s.x += p.x; s.y += p.y; s.z += p.z; s.w += p.w;
    }
    reinterpret_cast<float4*>(out)[i] = make_float4(0.5f*s.x, 0.5f*s.y, 0.5f*s.z, 0.5f*s.w);
}

// ------------- depthwise conv + SiLU; writes fp32 U and bf16 planes ----------
__global__ __launch_bounds__(256) void conv_silu_kernel(
    const float* __restrict__ convW_f, const float* __restrict__ convB_f,
    const float* __restrict__ convW_b, const float* __restrict__ convB_b)
{
    const int i = blockIdx.x * 256 + threadIdx.x;
    const int c = i & 4095;
    const int row = i >> 12;
    const int l = row & (LSEQ - 1);
    const int b = row >> 10;
    const int dir = c >> 11;
    const int d = c & (DIN - 1);
    const float* w = (dir ? convW_b : convW_f) + d*4;
    float acc = (dir ? convB_b : convB_f)[d];
    const float* xi = g_XZ + dir*4096 + d;
    if (dir == 0) {
#pragma unroll
        for (int k = 0; k < 4; k++) {
            int ls = l - 3 + k;
            if (ls >= 0) acc = fmaf(w[k], xi[(size_t)(b*LSEQ + ls)*8192], acc);
        }
    } else {
#pragma unroll
        for (int k = 0; k < 4; k++) {
            int ls = l + 3 - k;
            if (ls < LSEQ) acc = fmaf(w[k], xi[(size_t)(b*LSEQ + ls)*8192], acc);
        }
    }
    const float sig = 1.f / (1.f + __expf(-acc));
    const float u = acc * sig;
    const size_t o = (size_t)row*4096 + c;
    g_U[o] = u;
    __nv_bfloat16 h, lo2; split1(u, h, lo2);
    g_Uh[o] = h; g_Ul[o] = lo2;
}

// ------------------------- split-K reduce + plane split ----------------------
__global__ __launch_bounds__(256) void reduce_xdbl_kernel()
{
    const int i = blockIdx.x * 256 + threadIdx.x;
    float s = 0.f;
#pragma unroll
    for (int k = 0; k < 8; k++) s += g_XDBLP[(size_t)k*MROWS*256 + i];
    g_XDBL[i] = s;
    __nv_bfloat16 h, l; split1(s, h, l);
    g_XDh[i] = h; g_XDl[i] = l;
}

// ------------------- selective scan + gating; writes YG planes ---------------
__global__ __launch_bounds__(256) void scan_kernel(
    const float* __restrict__ Alog_f, const float* __restrict__ Alog_b,
    const float* __restrict__ Dp_f,  const float* __restrict__ Dp_b)
{
    const int dir = blockIdx.z;
    const int b   = blockIdx.y;
    const int d0  = blockIdx.x * 16;
    const int t  = threadIdx.x;
    const int dl = t >> 4;
    const int n  = t & 15;
    const int d  = d0 + dl;

    const float Acoef = -__expf((dir ? Alog_b : Alog_f)[d*NST + n]);
    const float DpV   = (dir ? Dp_b : Dp_f)[d];

    __shared__ float sD[32][16], sU[32][16], sZ[32][16], sB2[32][16], sC2[32][16];

    const int la0 = t >> 4, qa0 = t & 15;
    const int la1 = (t + 256) >> 4, qa1 = (t + 256) & 15;

    float rg[10];
    {
        const int lb = (dir == 0) ? 0 : (LSEQ - 32);
        const int row0 = b*LSEQ + lb + la0;
        const int row1 = b*LSEQ + lb + la1;
        rg[0] = g_DELTA[(size_t)row0*4096 + dir*2048 + d0 + qa0];
        rg[1] = g_DELTA[(size_t)row1*4096 + dir*2048 + d0 + qa1];
        rg[2] = g_U[(size_t)row0*4096 + dir*2048 + d0 + qa0];
        rg[3] = g_U[(size_t)row1*4096 + dir*2048 + d0 + qa1];
        rg[4] = g_XZ[(size_t)row0*8192 + dir*4096 + 2048 + d0 + qa0];
        rg[5] = g_XZ[(size_t)row1*8192 + dir*4096 + 2048 + d0 + qa1];
        rg[6] = g_XDBL[(size_t)row0*256 + dir*128 + 64 + qa0];
        rg[7] = g_XDBL[(size_t)row1*256 + dir*128 + 64 + qa1];
        rg[8] = g_XDBL[(size_t)row0*256 + dir*128 + 80 + qa0];
        rg[9] = g_XDBL[(size_t)row1*256 + dir*128 + 80 + qa1];
    }

    float h = 0.f;
    const int NCH = LSEQ / 32;
    for (int c = 0; c < NCH; c++) {
        __syncthreads();
        sD [la0][qa0] = rg[0]; sD [la1][qa1] = rg[1];
        sU [la0][qa0] = rg[2]; sU [la1][qa1] = rg[3];
        sZ [la0][qa0] = rg[4]; sZ [la1][qa1] = rg[5];
        sB2[la0][qa0] = rg[6]; sB2[la1][qa1] = rg[7];
        sC2[la0][qa0] = rg[8]; sC2[la1][qa1] = rg[9];
        __syncthreads();
        if (c + 1 < NCH) {
            const int lb = (dir == 0) ? (c+1)*32 : (LSEQ - (c+2)*32);
            const int row0 = b*LSEQ + lb + la0;
            const int row1 = b*LSEQ + lb + la1;
            rg[0] = g_DELTA[(size_t)row0*4096 + dir*2048 + d0 + qa0];
            rg[1] = g_DELTA[(size_t)row1*4096 + dir*2048 + d0 + qa1];
            rg[2] = g_U[(size_t)row0*4096 + dir*2048 + d0 + qa0];
            rg[3] = g_U[(size_t)row1*4096 + dir*2048 + d0 + qa1];
            rg[4] = g_XZ[(size_t)row0*8192 + dir*4096 + 2048 + d0 + qa0];
            rg[5] = g_XZ[(size_t)row1*8192 + dir*4096 + 2048 + d0 + qa1];
            rg[6] = g_XDBL[(size_t)row0*256 + dir*128 + 64 + qa0];
            rg[7] = g_XDBL[(size_t)row1*256 + dir*128 + 64 + qa1];
            rg[8] = g_XDBL[(size_t)row0*256 + dir*128 + 80 + qa0];
            rg[9] = g_XDBL[(size_t)row1*256 + dir*128 + 80 + qa1];
        }
        const int lb = (dir == 0) ? c*32 : (LSEQ - (c+1)*32);
#pragma unroll 4
        for (int s = 0; s < 32; s++) {
            const int ll = (dir == 0) ? s : (31 - s);
            const float del = sD[ll][dl];
            const float uu  = sU[ll][dl];
            const float dA  = __expf(del * Acoef);
            h = fmaf(h, dA, del * uu * sB2[ll][n]);
            float py = h * sC2[ll][n];
            py += __shfl_xor_sync(0xffffffffu, py, 8);
            py += __shfl_xor_sync(0xffffffffu, py, 4);
            py += __shfl_xor_sync(0xffffffffu, py, 2);
            py += __shfl_xor_sync(0xffffffffu, py, 1);
            if (n == 0) {
                const float zz = sZ[ll][dl];
                const float y = fmaf(uu, DpV, py);
                const float sig = 1.f / (1.f + __expf(-zz));
                const float yg = y * (zz * sig);
                const size_t o = (size_t)(b*LSEQ + lb + ll)*4096 + dir*2048 + d;
                __nv_bfloat16 hh, lo2; split1(yg, hh, lo2);
                g_YGh[o] = hh; g_YGl[o] = lo2;
            }
        }
    }
}

// ------------------------------------ launch ---------------------------------
extern "C" void kernel_launch(void* const* d_in, const int* in_sizes, int n_in,
                              void* d_out, int out_size)
{
    const float* x      = (const float*)d_in[0];
    const float* inW_f  = (const float*)d_in[1];
    const float* convW_f= (const float*)d_in[2];
    const float* convB_f= (const float*)d_in[3];
    const float* xpW_f  = (const float*)d_in[4];
    const float* dtW_f  = (const float*)d_in[5];
    const float* dtB_f  = (const float*)d_in[6];
    const float* Alog_f = (const float*)d_in[7];
    const float* Dp_f   = (const float*)d_in[8];
    const float* outW_f = (const float*)d_in[9];
    const float* inW_b  = (const float*)d_in[10];
    const float* convW_b= (const float*)d_in[11];
    const float* convB_b= (const float*)d_in[12];
    const float* xpW_b  = (const float*)d_in[13];
    const float* dtW_b  = (const float*)d_in[14];
    const float* dtB_b  = (const float*)d_in[15];
    const float* Alog_b = (const float*)d_in[16];
    const float* Dp_b   = (const float*)d_in[17];
    const float* outW_b = (const float*)d_in[18];
    float* out = (float*)d_out;

    float *XZ, *XDBLP, *DELTA, *OUTP;
    __nv_bfloat16 *Xh, *Xl, *Winh, *Winl, *Uh, *Ul, *Xph, *Xpl, *XDh, *XDl;
    __nv_bfloat16 *dtWh, *dtWl, *YGh, *YGl, *Wouth, *Woutl;
    cudaGetSymbolAddress((void**)&XZ,    g_XZ);
    cudaGetSymbolAddress((void**)&XDBLP, g_XDBLP);
    cudaGetSymbolAddress((void**)&DELTA, g_DELTA);
    cudaGetSymbolAddress((void**)&OUTP,  g_OUTP);
    cudaGetSymbolAddress((void**)&Xh,    g_Xh);
    cudaGetSymbolAddress((void**)&Xl,    g_Xl);
    cudaGetSymbolAddress((void**)&Winh,  g_Winh);
    cudaGetSymbolAddress((void**)&Winl,  g_Winl);
    cudaGetSymbolAddress((void**)&Uh,    g_Uh);
    cudaGetSymbolAddress((void**)&Ul,    g_Ul);
    cudaGetSymbolAddress((void**)&Xph,   g_Xph);
    cudaGetSymbolAddress((void**)&Xpl,   g_Xpl);
    cudaGetSymbolAddress((void**)&XDh,   g_XDh);
    cudaGetSymbolAddress((void**)&XDl,   g_XDl);
    cudaGetSymbolAddress((void**)&dtWh,  g_dtWh);
    cudaGetSymbolAddress((void**)&dtWl,  g_dtWl);
    cudaGetSymbolAddress((void**)&YGh,   g_YGh);
    cudaGetSymbolAddress((void**)&YGl,   g_YGl);
    cudaGetSymbolAddress((void**)&Wouth, g_Wouth);
    cudaGetSymbolAddress((void**)&Woutl, g_Woutl);

    cudaFuncSetAttribute(hgemm<0>, cudaFuncAttributeMaxDynamicSharedMemorySize, HG_SMEM);
    cudaFuncSetAttribute(hgemm<1>, cudaFuncAttributeMaxDynamicSharedMemorySize, HG_SMEM);

    // 0-2) merged converts (in-proj GEMM stays at launch index 3 = ncu slot)
    cvt_x_kernel  <<<N4_X/256, 256>>>(x);
    cvt_inw_kernel<<<2*N4_INW/256, 256>>>(inW_f, inW_b);
    cvt_rest_kernel<<<(2*N4_DTW + N4_XP + N4_OUT)/256, 256>>>(
        dtW_f, dtW_b, xpW_f, xpW_b, outW_f, outW_b);

    // 3) input projection: [2048,8192] = X[2048,1024] * Win[8192,1024]^T
    hgemm<0><<<dim3(64,16,1), 256, HG_SMEM>>>(
        Xh, Xl, DMODEL, 0, 0, Winh, Winl, DMODEL,
        XZ, 8192, DMODEL, nullptr, nullptr, 0);

    // 4) depthwise conv + SiLU (emits U fp32 + planes)
    conv_silu_kernel<<<(MROWS*4096)/256, 256>>>(convW_f, convB_f, convW_b, convB_b);

    // 5) x_dbl: [2048,256] = U[.,dir-slice] * Xp[256,2048]^T, split-K=8
    hgemm<0><<<dim3(2,16,8), 256, HG_SMEM>>>(
        Uh, Ul, 4096, 2048, 128, Xph, Xpl, DIN,
        XDBLP, 256, DIN, nullptr, nullptr, 256);
    reduce_xdbl_kernel<<<(MROWS*256)/256, 256>>>();

    // 6) delta = softplus(dt @ dtWcat^T + dtB), N=4096, K=64
    hgemm<1><<<dim3(32,16,1), 256, HG_SMEM>>>(
        XDh, XDl, 256, 128, 2048, dtWh, dtWl, DTR,
        DELTA, 4096, DTR, dtB_f, dtB_b, 0);

    // 7) selective scan + gating (emits YG planes)
    scan_kernel<<<dim3(128,2,2), 256>>>(Alog_f, Alog_b, Dp_f, Dp_b);

    // 8) out-proj split-K=4 (512 CTAs = 2 balanced waves), then 0.5*sum
    hgemm<0><<<dim3(8,16,4), 256, HG_SMEM>>>(
        YGh, YGl, 4096, 0, 0, Wouth, Woutl, 4096,
        OUTP, DMODEL, 4096, nullptr, nullptr, 1024);
    reduce_out_kernel<<<(MROWS*DMODEL/4)/256, 256>>>(out);
}

// round 9
// speedup vs baseline: 1.3881x; 1.2723x over previous
#include <cuda_runtime.h>
#include <cuda_bf16.h>
#include <math.h>
#include <cstdint>

#define B_SZ   2
#define LSEQ   1024
#define DMODEL 1024
#define DIN    2048
#define NST    16
#define DTR    64
#define MROWS  (B_SZ*LSEQ)   /* 2048 */

// ---------------- scratch (device globals; no allocation allowed) ------------
__device__ float g_XZ[MROWS*8192];              // [m][dir*4096 + (xi | z)]
__device__ float g_U [MROWS*4096];              // fp32 for scan
__device__ __nv_bfloat16 g_Uh[MROWS*4096],  g_Ul[MROWS*4096];
__device__ __nv_bfloat16 g_Xh[MROWS*DMODEL], g_Xl[MROWS*DMODEL];
__device__ __nv_bfloat16 g_Winh[8192*DMODEL], g_Winl[8192*DMODEL];
__device__ __nv_bfloat16 g_Xph[256*DIN],    g_Xpl[256*DIN];      // padded xpW
__device__ float g_XDBLP[8*MROWS*256];
__device__ float g_XDBL[MROWS*256];
__device__ __nv_bfloat16 g_XDh[MROWS*256],  g_XDl[MROWS*256];
__device__ __nv_bfloat16 g_dtWh[4096*DTR],  g_dtWl[4096*DTR];    // dir-concat rows
__device__ float g_DELTA[(size_t)MROWS*4096];
__device__ __nv_bfloat16 g_YGh[MROWS*4096], g_YGl[MROWS*4096];
__device__ __nv_bfloat16 g_Wouth[DMODEL*4096], g_Woutl[DMODEL*4096]; // K-concat cols
__device__ float g_OUTP[4*MROWS*DMODEL];        // out-proj split-K=4 partials

// ======================= helpers =============================================
__device__ __forceinline__ uint32_t smem_u32(const void* p) {
    uint32_t a;
    asm("{ .reg .u64 t; cvta.to.shared.u64 t, %1; cvt.u32.u64 %0, t; }" : "=r"(a) : "l"(p));
    return a;
}
#define LDM4(r0,r1,r2,r3,addr)                                                      \
    asm volatile("ldmatrix.sync.aligned.m8n8.x4.shared.b16 {%0,%1,%2,%3}, [%4];"    \
        : "=r"(r0),"=r"(r1),"=r"(r2),"=r"(r3) : "r"(addr))
#define MMA16816(c,a,b)                                                             \
    asm volatile("mma.sync.aligned.m16n8k16.row.col.f32.bf16.bf16.f32 "             \
        "{%0,%1,%2,%3}, {%4,%5,%6,%7}, {%8,%9}, {%0,%1,%2,%3};"                     \
        : "+f"((c)[0]),"+f"((c)[1]),"+f"((c)[2]),"+f"((c)[3])                       \
        : "r"((a)[0]),"r"((a)[1]),"r"((a)[2]),"r"((a)[3]),"r"((b)[0]),"r"((b)[1]))
#define CPA16(dst, src) asm volatile("cp.async.cg.shared.global [%0], [%1], 16;" :: "r"(dst), "l"(src) : "memory")
#define CPCOMMIT()      asm volatile("cp.async.commit_group;" ::: "memory")
#define CPWAIT0()       asm volatile("cp.async.wait_group 0;" ::: "memory")

__device__ __forceinline__ void split1(float v, __nv_bfloat16& h, __nv_bfloat16& l) {
    h = __float2bfloat16(v);
    l = __float2bfloat16(v - __bfloat162float(h));
}
__device__ __forceinline__ void store_planes(
    __nv_bfloat16* __restrict__ hi, __nv_bfloat16* __restrict__ lo,
    int i /*float4 idx*/, float4 v)
{
    __nv_bfloat16 h0,h1,h2,h3,l0,l1,l2,l3;
    split1(v.x,h0,l0); split1(v.y,h1,l1); split1(v.z,h2,l2); split1(v.w,h3,l3);
    reinterpret_cast<__nv_bfloat162*>(hi)[2*i]   = __nv_bfloat162(h0,h1);
    reinterpret_cast<__nv_bfloat162*>(hi)[2*i+1] = __nv_bfloat162(h2,h3);
    reinterpret_cast<__nv_bfloat162*>(lo)[2*i]   = __nv_bfloat162(l0,l1);
    reinterpret_cast<__nv_bfloat162*>(lo)[2*i+1] = __nv_bfloat162(l2,l3);
}

// ======================= HMMA GEMM (pre-split bf16 hi/lo planes) =============
#define BKC 32
#define ASTRIDE 80
#define STG_A_HI 0
#define STG_A_LO 10240
#define STG_B_HI 20480
#define STG_B_LO 30720
#define STG_STRIDE 40960
#define HG_SMEM (2*STG_STRIDE)

template<int EPI>
__global__ __launch_bounds__(256, 2) void hgemm(
    const __nv_bfloat16* __restrict__ Ah, const __nv_bfloat16* __restrict__ Al,
    int lda, int a_off1, int nsplit,
    const __nv_bfloat16* __restrict__ Bh, const __nv_bfloat16* __restrict__ Bl,
    int ldb,
    float* __restrict__ C, int ldc, int K,
    const float* __restrict__ bias0, const float* __restrict__ bias1,
    int kz)
{
    extern __shared__ char sm[];
    const uint32_t smb = smem_u32(sm);
    const int tid = threadIdx.x;
    const int bm = blockIdx.y * 128, bn = blockIdx.x * 128;
    if (kz > 0) {
        Ah += (size_t)blockIdx.z * kz;  Al += (size_t)blockIdx.z * kz;
        Bh += (size_t)blockIdx.z * kz;  Bl += (size_t)blockIdx.z * kz;
        C  += (size_t)blockIdx.z * (size_t)(gridDim.y * 128) * (size_t)ldc;
        K = kz;
    }
    const int aoff = (nsplit && bn >= nsplit) ? a_off1 : 0;

    const int grow = tid >> 1;
    const int seg  = (tid & 1) << 1;
    const char* gAh = (const char*)(Ah + aoff + (size_t)(bm + grow) * lda);
    const char* gAl = (const char*)(Al + aoff + (size_t)(bm + grow) * lda);
    const char* gBh = (const char*)(Bh + (size_t)(bn + grow) * ldb);
    const char* gBl = (const char*)(Bl + (size_t)(bn + grow) * ldb);
    const uint32_t srow = smb + (uint32_t)(grow * ASTRIDE + seg * 16);

    const int wid = tid >> 5, lane = tid & 31;
    const int wm = (wid >> 2) * 64;
    const int wn = (wid & 3) * 32;
    const int tq = lane >> 2, tr = lane & 3;
    const uint32_t aoffm = (uint32_t)((wm + (lane & 15)) * ASTRIDE + ((lane >> 4) << 4));
    const int g = lane >> 3;
    const uint32_t boffm = (uint32_t)((wn + ((g >> 1) << 3) + (lane & 7)) * ASTRIDE + ((g & 1) << 4));

    float acc[4][4][4];
#pragma unroll
    for (int i = 0; i < 4; i++)
#pragma unroll
        for (int j = 0; j < 4; j++)
#pragma unroll
            for (int q = 0; q < 4; q++) acc[i][j][q] = 0.f;

    const int nch = K / BKC;

    auto issue = [&](int s) {
        const uint32_t st = srow + (uint32_t)(s & 1) * STG_STRIDE;
        const int go = s * (BKC * 2) + seg * 16;
        CPA16(st + STG_A_HI,      gAh + go);
        CPA16(st + STG_A_HI + 16, gAh + go + 16);
        CPA16(st + STG_A_LO,      gAl + go);
        CPA16(st + STG_A_LO + 16, gAl + go + 16);
        CPA16(st + STG_B_HI,      gBh + go);
        CPA16(st + STG_B_HI + 16, gBh + go + 16);
        CPA16(st + STG_B_LO,      gBl + go);
        CPA16(st + STG_B_LO + 16, gBl + go + 16);
        CPCOMMIT();
    };

    issue(0);
    for (int s = 0; s < nch; s++) {
        CPWAIT0();
        __syncthreads();
        if (s + 1 < nch) issue(s + 1);
        const uint32_t sa = smb + (uint32_t)(s & 1) * STG_STRIDE;
#pragma unroll
        for (int ph = 0; ph < 2; ph++) {
            const uint32_t ka = sa + ph * 32;
            uint32_t ah[4][4], al[4][4], bh[4][2], bl[4][2];
#pragma unroll
            for (int i = 0; i < 4; i++)
                LDM4(ah[i][0], ah[i][1], ah[i][2], ah[i][3], ka + STG_A_HI + aoffm + i*(16*ASTRIDE));
            LDM4(bh[0][0], bh[0][1], bh[1][0], bh[1][1], ka + STG_B_HI + boffm);
            LDM4(bh[2][0], bh[2][1], bh[3][0], bh[3][1], ka + STG_B_HI + boffm + 16*ASTRIDE);
#pragma unroll
            for (int i = 0; i < 4; i++)
#pragma unroll
                for (int j = 0; j < 4; j++)
                    MMA16816(acc[i][j], ah[i], bh[j]);
#pragma unroll
            for (int i = 0; i < 4; i++)
                LDM4(al[i][0], al[i][1], al[i][2], al[i][3], ka + STG_A_LO + aoffm + i*(16*ASTRIDE));
            LDM4(bl[0][0], bl[0][1], bl[1][0], bl[1][1], ka + STG_B_LO + boffm);
            LDM4(bl[2][0], bl[2][1], bl[3][0], bl[3][1], ka + STG_B_LO + boffm + 16*ASTRIDE);
#pragma unroll
            for (int i = 0; i < 4; i++)
#pragma unroll
                for (int j = 0; j < 4; j++)
                    MMA16816(acc[i][j], ah[i], bl[j]);
#pragma unroll
            for (int i = 0; i < 4; i++)
#pragma unroll
                for (int j = 0; j < 4; j++)
                    MMA16816(acc[i][j], al[i], bh[j]);
        }
    }

    const float* bias = nullptr;
    if (EPI == 1) bias = (nsplit && bn >= nsplit) ? (bias1 - nsplit) : bias0;
#pragma unroll
    for (int i = 0; i < 4; i++) {
        const int row0 = bm + wm + 16*i + tq;
#pragma unroll
        for (int j = 0; j < 4; j++) {
            const int col = bn + wn + 8*j + 2*tr;
            float v0 = acc[i][j][0], v1 = acc[i][j][1];
            float v2 = acc[i][j][2], v3 = acc[i][j][3];
            if (EPI == 1) {
                const float b0v = bias[col], b1v = bias[col+1];
                v0 += b0v; v1 += b1v; v2 += b0v; v3 += b1v;
                v0 = (v0 > 20.f) ? v0 : log1pf(__expf(v0));
                v1 = (v1 > 20.f) ? v1 : log1pf(__expf(v1));
                v2 = (v2 > 20.f) ? v2 : log1pf(__expf(v2));
                v3 = (v3 > 20.f) ? v3 : log1pf(__expf(v3));
            }
            *reinterpret_cast<float2*>(C + (size_t)row0 * ldc + col)       = make_float2(v0, v1);
            *reinterpret_cast<float2*>(C + (size_t)(row0 + 8) * ldc + col) = make_float2(v2, v3);
        }
    }
}

// ======================= merged convert kernels ===============================
#define N4_X    (MROWS*DMODEL/4)
#define N4_INW  (4096*DMODEL/4)
#define N4_DTW  (2048*DTR/4)
#define N4_XP   (256*DIN/4)
#define N4_OUT  (DMODEL*4096/4)

__global__ __launch_bounds__(256) void cvt_x_kernel(const float* __restrict__ x)
{
    const int i = blockIdx.x * 256 + threadIdx.x;
    store_planes(g_Xh, g_Xl, i, reinterpret_cast<const float4*>(x)[i]);
}

__global__ __launch_bounds__(256) void cvt_inw_kernel(
    const float* __restrict__ f, const float* __restrict__ b)
{
    const int i = blockIdx.x * 256 + threadIdx.x;
    const float4 v = (i < N4_INW)
        ? reinterpret_cast<const float4*>(f)[i]
        : reinterpret_cast<const float4*>(b)[i - N4_INW];
    store_planes(g_Winh, g_Winl, i, v);
}

__global__ __launch_bounds__(256) void cvt_rest_kernel(
    const float* __restrict__ dtW_f, const float* __restrict__ dtW_b,
    const float* __restrict__ xpW_f, const float* __restrict__ xpW_b,
    const float* __restrict__ outW_f, const float* __restrict__ outW_b)
{
    int i = blockIdx.x * 256 + threadIdx.x;
    if (i < 2*N4_DTW) {
        const float4 v = (i < N4_DTW)
            ? reinterpret_cast<const float4*>(dtW_f)[i]
            : reinterpret_cast<const float4*>(dtW_b)[i - N4_DTW];
        store_planes(g_dtWh, g_dtWl, i, v);
        return;
    }
    i -= 2*N4_DTW;
    if (i < N4_XP) {
        const int idx = i * 4;
        const int r = idx >> 11, c = idx & 2047;
        float4 v = make_float4(0.f,0.f,0.f,0.f);
        if (r < 96)                   v = *reinterpret_cast<const float4*>(xpW_f + r*2048 + c);
        else if (r >= 128 && r < 224) v = *reinterpret_cast<const float4*>(xpW_b + (r-128)*2048 + c);
        store_planes(g_Xph, g_Xpl, i, v);
        return;
    }
    i -= N4_XP;
    {
        const int idx = i * 4;
        const int r = idx >> 12, c = idx & 4095;
        const float4 v = (c < 2048)
            ? *reinterpret_cast<const float4*>(outW_f + (size_t)r*2048 + c)
            : *reinterpret_cast<const float4*>(outW_b + (size_t)r*2048 + (c - 2048));
        store_planes(g_Wouth, g_Woutl, i, v);
    }
}

__global__ __launch_bounds__(256) void reduce_out_kernel(float* __restrict__ out)
{
    const int i = blockIdx.x * 256 + threadIdx.x;
    float4 s = reinterpret_cast<const float4*>(g_OUTP)[i];
#pragma unroll
    for (int k = 1; k < 4; k++) {
        const float4 p = reinterpret_cast<const float4*>(g_OUTP + (size_t)k*MROWS*DMODEL)[i];
        s.x += p.x; s.y += p.y; s.z += p.z; s.w += p.w;
    }
    reinterpret_cast<float4*>(out)[i] = make_float4(0.5f*s.x, 0.5f*s.y, 0.5f*s.z, 0.5f*s.w);
}

// ------------- depthwise conv + SiLU; writes fp32 U and bf16 planes ----------
__global__ __launch_bounds__(256) void conv_silu_kernel(
    const float* __restrict__ convW_f, const float* __restrict__ convB_f,
    const float* __restrict__ convW_b, const float* __restrict__ convB_b)
{
    const int i = blockIdx.x * 256 + threadIdx.x;
    const int c = i & 4095;
    const int row = i >> 12;
    const int l = row & (LSEQ - 1);
    const int b = row >> 10;
    const int dir = c >> 11;
    const int d = c & (DIN - 1);
    const float* w = (dir ? convW_b : convW_f) + d*4;
    float acc = (dir ? convB_b : convB_f)[d];
    const float* xi = g_XZ + dir*4096 + d;
    if (dir == 0) {
#pragma unroll
        for (int k = 0; k < 4; k++) {
            int ls = l - 3 + k;
            if (ls >= 0) acc = fmaf(w[k], xi[(size_t)(b*LSEQ + ls)*8192], acc);
        }
    } else {
#pragma unroll
        for (int k = 0; k < 4; k++) {
            int ls = l + 3 - k;
            if (ls < LSEQ) acc = fmaf(w[k], xi[(size_t)(b*LSEQ + ls)*8192], acc);
        }
    }
    const float sig = 1.f / (1.f + __expf(-acc));
    const float u = acc * sig;
    const size_t o = (size_t)row*4096 + c;
    g_U[o] = u;
    __nv_bfloat16 h, lo2; split1(u, h, lo2);
    g_Uh[o] = h; g_Ul[o] = lo2;
}

// ------------------------- split-K reduce + plane split ----------------------
__global__ __launch_bounds__(256) void reduce_xdbl_kernel()
{
    const int i = blockIdx.x * 256 + threadIdx.x;
    float s = 0.f;
#pragma unroll
    for (int k = 0; k < 8; k++) s += g_XDBLP[(size_t)k*MROWS*256 + i];
    g_XDBL[i] = s;
    __nv_bfloat16 h, l; split1(s, h, l);
    g_XDh[i] = h; g_XDl[i] = l;
}

// ------------- selective scan + gating (hoisted epilogue, packed smem) -------
__global__ __launch_bounds__(256) void scan_kernel(
    const float* __restrict__ Alog_f, const float* __restrict__ Alog_b,
    const float* __restrict__ Dp_f,  const float* __restrict__ Dp_b)
{
    const int dir = blockIdx.z;
    const int b   = blockIdx.y;
    const int d0  = blockIdx.x * 16;
    const int t  = threadIdx.x;
    const int dl = t >> 4;
    const int n  = t & 15;
    const int d  = d0 + dl;

    const float Acoef = -__expf((dir ? Alog_b : Alog_f)[d*NST + n]);
    const float DpE   = (dir ? Dp_b : Dp_f)[d0 + (t & 15)];   // for gating pass

    __shared__ float2 sDdw[32][16];   // (delta, delta*u)  indexed [ll][dl]
    __shared__ float2 sBC [32][16];   // (B, C)            indexed [ll][n]
    __shared__ float2 sUZ [32][16];   // (u, z)            indexed [ll][dl]
    __shared__ float  sY  [32][16];   // reduced py        indexed [ll][dl]

    const int la0 = t >> 4, qa0 = t & 15;
    const int la1 = (t + 256) >> 4, qa1 = (t + 256) & 15;

    float rg[10];
    {
        const int lb = (dir == 0) ? 0 : (LSEQ - 32);
        const int row0 = b*LSEQ + lb + la0;
        const int row1 = b*LSEQ + lb + la1;
        rg[0] = g_DELTA[(size_t)row0*4096 + dir*2048 + d0 + qa0];
        rg[1] = g_DELTA[(size_t)row1*4096 + dir*2048 + d0 + qa1];
        rg[2] = g_U[(size_t)row0*4096 + dir*2048 + d0 + qa0];
        rg[3] = g_U[(size_t)row1*4096 + dir*2048 + d0 + qa1];
        rg[4] = g_XZ[(size_t)row0*8192 + dir*4096 + 2048 + d0 + qa0];
        rg[5] = g_XZ[(size_t)row1*8192 + dir*4096 + 2048 + d0 + qa1];
        rg[6] = g_XDBL[(size_t)row0*256 + dir*128 + 64 + qa0];
        rg[7] = g_XDBL[(size_t)row1*256 + dir*128 + 64 + qa1];
        rg[8] = g_XDBL[(size_t)row0*256 + dir*128 + 80 + qa0];
        rg[9] = g_XDBL[(size_t)row1*256 + dir*128 + 80 + qa1];
    }

    float h = 0.f;
    const int NCH = LSEQ / 32;
    for (int c = 0; c < NCH; c++) {
        __syncthreads();           // gating pass of chunk c-1 done -> safe to overwrite
        sDdw[la0][qa0] = make_float2(rg[0], rg[0]*rg[2]);
        sDdw[la1][qa1] = make_float2(rg[1], rg[1]*rg[3]);
        sUZ [la0][qa0] = make_float2(rg[2], rg[4]);
        sUZ [la1][qa1] = make_float2(rg[3], rg[5]);
        sBC [la0][qa0] = make_float2(rg[6], rg[8]);
        sBC [la1][qa1] = make_float2(rg[7], rg[9]);
        __syncthreads();
        if (c + 1 < NCH) {
            const int lb = (dir == 0) ? (c+1)*32 : (LSEQ - (c+2)*32);
            const int row0 = b*LSEQ + lb + la0;
            const int row1 = b*LSEQ + lb + la1;
            rg[0] = g_DELTA[(size_t)row0*4096 + dir*2048 + d0 + qa0];
            rg[1] = g_DELTA[(size_t)row1*4096 + dir*2048 + d0 + qa1];
            rg[2] = g_U[(size_t)row0*4096 + dir*2048 + d0 + qa0];
            rg[3] = g_U[(size_t)row1*4096 + dir*2048 + d0 + qa1];
            rg[4] = g_XZ[(size_t)row0*8192 + dir*4096 + 2048 + d0 + qa0];
            rg[5] = g_XZ[(size_t)row1*8192 + dir*4096 + 2048 + d0 + qa1];
            rg[6] = g_XDBL[(size_t)row0*256 + dir*128 + 64 + qa0];
            rg[7] = g_XDBL[(size_t)row1*256 + dir*128 + 64 + qa1];
            rg[8] = g_XDBL[(size_t)row0*256 + dir*128 + 80 + qa0];
            rg[9] = g_XDBL[(size_t)row1*256 + dir*128 + 80 + qa1];
        }
        const int lb = (dir == 0) ? c*32 : (LSEQ - (c+1)*32);
        // ---- hot loop: ~16 warp-instrs/step ---------------------------------
#pragma unroll 4
        for (int s = 0; s < 32; s++) {
            const int ll = (dir == 0) ? s : (31 - s);
            const float2 ddw = sDdw[ll][dl];
            const float2 bc  = sBC[ll][n];
            const float dA = __expf(ddw.x * Acoef);
            h = fmaf(h, dA, ddw.y * bc.x);
            float py = h * bc.y;
            py += __shfl_xor_sync(0xffffffffu, py, 8);
            py += __shfl_xor_sync(0xffffffffu, py, 4);
            py += __shfl_xor_sync(0xffffffffu, py, 2);
            py += __shfl_xor_sync(0xffffffffu, py, 1);
            if (n == 0) sY[ll][dl] = py;
        }
        __syncthreads();
        // ---- chunk gating pass: 2 elems/thread, vectorized ------------------
#pragma unroll
        for (int e = 0; e < 2; e++) {
            const int ll = (e ? la1 : la0);
            const int dq = qa0;                 // == (t+256)&15 too
            const float2 uz = sUZ[ll][dq];
            const float y = fmaf(uz.x, DpE, sY[ll][dq]);
            const float sig = 1.f / (1.f + __expf(-uz.y));
            const float yg = y * (uz.y * sig);
            const size_t o = (size_t)(b*LSEQ + lb + ll)*4096 + dir*2048 + d0 + dq;
            __nv_bfloat16 hh, lo2; split1(yg, hh, lo2);
            g_YGh[o] = hh; g_YGl[o] = lo2;
        }
    }
}

// ------------------------------------ launch ---------------------------------
extern "C" void kernel_launch(void* const* d_in, const int* in_sizes, int n_in,
                              void* d_out, int out_size)
{
    const float* x      = (const float*)d_in[0];
    const float* inW_f  = (const float*)d_in[1];
    const float* convW_f= (const float*)d_in[2];
    const float* convB_f= (const float*)d_in[3];
    const float* xpW_f  = (const float*)d_in[4];
    const float* dtW_f  = (const float*)d_in[5];
    const float* dtB_f  = (const float*)d_in[6];
    const float* Alog_f = (const float*)d_in[7];
    const float* Dp_f   = (const float*)d_in[8];
    const float* outW_f = (const float*)d_in[9];
    const float* inW_b  = (const float*)d_in[10];
    const float* convW_b= (const float*)d_in[11];
    const float* convB_b= (const float*)d_in[12];
    const float* xpW_b  = (const float*)d_in[13];
    const float* dtW_b  = (const float*)d_in[14];
    const float* dtB_b  = (const float*)d_in[15];
    const float* Alog_b = (const float*)d_in[16];
    const float* Dp_b   = (const float*)d_in[17];
    const float* outW_b = (const float*)d_in[18];
    float* out = (float*)d_out;

    float *XZ, *XDBLP, *DELTA, *OUTP;
    __nv_bfloat16 *Xh, *Xl, *Winh, *Winl, *Uh, *Ul, *Xph, *Xpl, *XDh, *XDl;
    __nv_bfloat16 *dtWh, *dtWl, *YGh, *YGl, *Wouth, *Woutl;
    cudaGetSymbolAddress((void**)&XZ,    g_XZ);
    cudaGetSymbolAddress((void**)&XDBLP, g_XDBLP);
    cudaGetSymbolAddress((void**)&DELTA, g_DELTA);
    cudaGetSymbolAddress((void**)&OUTP,  g_OUTP);
    cudaGetSymbolAddress((void**)&Xh,    g_Xh);
    cudaGetSymbolAddress((void**)&Xl,    g_Xl);
    cudaGetSymbolAddress((void**)&Winh,  g_Winh);
    cudaGetSymbolAddress((void**)&Winl,  g_Winl);
    cudaGetSymbolAddress((void**)&Uh,    g_Uh);
    cudaGetSymbolAddress((void**)&Ul,    g_Ul);
    cudaGetSymbolAddress((void**)&Xph,   g_Xph);
    cudaGetSymbolAddress((void**)&Xpl,   g_Xpl);
    cudaGetSymbolAddress((void**)&XDh,   g_XDh);
    cudaGetSymbolAddress((void**)&XDl,   g_XDl);
    cudaGetSymbolAddress((void**)&dtWh,  g_dtWh);
    cudaGetSymbolAddress((void**)&dtWl,  g_dtWl);
    cudaGetSymbolAddress((void**)&YGh,   g_YGh);
    cudaGetSymbolAddress((void**)&YGl,   g_YGl);
    cudaGetSymbolAddress((void**)&Wouth, g_Wouth);
    cudaGetSymbolAddress((void**)&Woutl, g_Woutl);

    cudaFuncSetAttribute(hgemm<0>, cudaFuncAttributeMaxDynamicSharedMemorySize, HG_SMEM);
    cudaFuncSetAttribute(hgemm<1>, cudaFuncAttributeMaxDynamicSharedMemorySize, HG_SMEM);

    // 0-2) merged converts (in-proj GEMM stays at launch index 3 = ncu slot)
    cvt_x_kernel  <<<N4_X/256, 256>>>(x);
    cvt_inw_kernel<<<2*N4_INW/256, 256>>>(inW_f, inW_b);
    cvt_rest_kernel<<<(2*N4_DTW + N4_XP + N4_OUT)/256, 256>>>(
        dtW_f, dtW_b, xpW_f, xpW_b, outW_f, outW_b);

    // 3) input projection: [2048,8192] = X[2048,1024] * Win[8192,1024]^T
    hgemm<0><<<dim3(64,16,1), 256, HG_SMEM>>>(
        Xh, Xl, DMODEL, 0, 0, Winh, Winl, DMODEL,
        XZ, 8192, DMODEL, nullptr, nullptr, 0);

    // 4) depthwise conv + SiLU (emits U fp32 + planes)
    conv_silu_kernel<<<(MROWS*4096)/256, 256>>>(convW_f, convB_f, convW_b, convB_b);

    // 5) x_dbl: [2048,256] = U[.,dir-slice] * Xp[256,2048]^T, split-K=8
    hgemm<0><<<dim3(2,16,8), 256, HG_SMEM>>>(
        Uh, Ul, 4096, 2048, 128, Xph, Xpl, DIN,
        XDBLP, 256, DIN, nullptr, nullptr, 256);
    reduce_xdbl_kernel<<<(MROWS*256)/256, 256>>>();

    // 6) delta = softplus(dt @ dtWcat^T + dtB), N=4096, K=64
    hgemm<1><<<dim3(32,16,1), 256, HG_SMEM>>>(
        XDh, XDl, 256, 128, 2048, dtWh, dtWl, DTR,
        DELTA, 4096, DTR, dtB_f, dtB_b, 0);

    // 7) selective scan + gating (hoisted gating pass, packed smem)
    scan_kernel<<<dim3(128,2,2), 256>>>(Alog_f, Alog_b, Dp_f, Dp_b);

    // 8) out-proj split-K=4 (512 CTAs), then 0.5*sum
    hgemm<0><<<dim3(8,16,4), 256, HG_SMEM>>>(
        YGh, YGl, 4096, 0, 0, Wouth, Woutl, 4096,
        OUTP, DMODEL, 4096, nullptr, nullptr, 1024);
    reduce_out_kernel<<<(MROWS*DMODEL/4)/256, 256>>>(out);
}

// round 10
// speedup vs baseline: 1.4867x; 1.0710x over previous
#include <cuda_runtime.h>
#include <cuda_bf16.h>
#include <math.h>
#include <cstdint>

#define B_SZ   2
#define LSEQ   1024
#define DMODEL 1024
#define DIN    2048
#define NST    16
#define DTR    64
#define MROWS  (B_SZ*LSEQ)   /* 2048 */

// ---------------- scratch (device globals; no allocation allowed) ------------
__device__ float g_XZ[MROWS*8192];              // [m][dir*4096 + (xi | z)]
__device__ float g_U [MROWS*4096];              // fp32 for scan
__device__ __nv_bfloat16 g_Uh[MROWS*4096],  g_Ul[MROWS*4096];
__device__ __nv_bfloat16 g_Xh[MROWS*DMODEL], g_Xl[MROWS*DMODEL];
__device__ __nv_bfloat16 g_Winh[8192*DMODEL], g_Winl[8192*DMODEL];
__device__ __nv_bfloat16 g_Xph[256*DIN],    g_Xpl[256*DIN];      // padded xpW
__device__ float g_XDBLP[8*MROWS*256];
__device__ float g_XDBL[MROWS*256];
__device__ __nv_bfloat16 g_XDh[MROWS*256],  g_XDl[MROWS*256];
__device__ __nv_bfloat16 g_dtWh[4096*DTR],  g_dtWl[4096*DTR];    // dir-concat rows
__device__ float g_DELTA[(size_t)MROWS*4096];
__device__ __nv_bfloat16 g_YGh[MROWS*4096], g_YGl[MROWS*4096];
__device__ __nv_bfloat16 g_Wouth[DMODEL*4096], g_Woutl[DMODEL*4096]; // K-concat cols
__device__ float g_OUTP[4*MROWS*DMODEL];        // out-proj split-K=4 partials

// ======================= helpers =============================================
__device__ __forceinline__ uint32_t smem_u32(const void* p) {
    uint32_t a;
    asm("{ .reg .u64 t; cvta.to.shared.u64 t, %1; cvt.u32.u64 %0, t; }" : "=r"(a) : "l"(p));
    return a;
}
#define LDM4(r0,r1,r2,r3,addr)                                                      \
    asm volatile("ldmatrix.sync.aligned.m8n8.x4.shared.b16 {%0,%1,%2,%3}, [%4];"    \
        : "=r"(r0),"=r"(r1),"=r"(r2),"=r"(r3) : "r"(addr))
#define MMA16816(c,a,b)                                                             \
    asm volatile("mma.sync.aligned.m16n8k16.row.col.f32.bf16.bf16.f32 "             \
        "{%0,%1,%2,%3}, {%4,%5,%6,%7}, {%8,%9}, {%0,%1,%2,%3};"                     \
        : "+f"((c)[0]),"+f"((c)[1]),"+f"((c)[2]),"+f"((c)[3])                       \
        : "r"((a)[0]),"r"((a)[1]),"r"((a)[2]),"r"((a)[3]),"r"((b)[0]),"r"((b)[1]))
#define CPA16(dst, src) asm volatile("cp.async.cg.shared.global [%0], [%1], 16;" :: "r"(dst), "l"(src) : "memory")
#define CPCOMMIT()      asm volatile("cp.async.commit_group;" ::: "memory")
#define CPWAIT0()       asm volatile("cp.async.wait_group 0;" ::: "memory")

__device__ __forceinline__ void split1(float v, __nv_bfloat16& h, __nv_bfloat16& l) {
    h = __float2bfloat16(v);
    l = __float2bfloat16(v - __bfloat162float(h));
}
__device__ __forceinline__ void store_planes(
    __nv_bfloat16* __restrict__ hi, __nv_bfloat16* __restrict__ lo,
    int i, float4 v)
{
    __nv_bfloat16 h0,h1,h2,h3,l0,l1,l2,l3;
    split1(v.x,h0,l0); split1(v.y,h1,l1); split1(v.z,h2,l2); split1(v.w,h3,l3);
    reinterpret_cast<__nv_bfloat162*>(hi)[2*i]   = __nv_bfloat162(h0,h1);
    reinterpret_cast<__nv_bfloat162*>(hi)[2*i+1] = __nv_bfloat162(h2,h3);
    reinterpret_cast<__nv_bfloat162*>(lo)[2*i]   = __nv_bfloat162(l0,l1);
    reinterpret_cast<__nv_bfloat162*>(lo)[2*i+1] = __nv_bfloat162(l2,l3);
}

// ======================= HMMA GEMM (pre-split bf16 hi/lo planes) =============
#define BKC 32
#define ASTRIDE 80
#define STG_A_HI 0
#define STG_A_LO 10240
#define STG_B_HI 20480
#define STG_B_LO 30720
#define STG_STRIDE 40960
#define HG_SMEM (2*STG_STRIDE)

template<int EPI>
__global__ __launch_bounds__(256, 2) void hgemm(
    const __nv_bfloat16* __restrict__ Ah, const __nv_bfloat16* __restrict__ Al,
    int lda, int a_off1, int nsplit,
    const __nv_bfloat16* __restrict__ Bh, const __nv_bfloat16* __restrict__ Bl,
    int ldb,
    float* __restrict__ C, int ldc, int K,
    const float* __restrict__ bias0, const float* __restrict__ bias1,
    int kz)
{
    extern __shared__ char sm[];
    const uint32_t smb = smem_u32(sm);
    const int tid = threadIdx.x;
    const int bm = blockIdx.y * 128, bn = blockIdx.x * 128;
    if (kz > 0) {
        Ah += (size_t)blockIdx.z * kz;  Al += (size_t)blockIdx.z * kz;
        Bh += (size_t)blockIdx.z * kz;  Bl += (size_t)blockIdx.z * kz;
        C  += (size_t)blockIdx.z * (size_t)(gridDim.y * 128) * (size_t)ldc;
        K = kz;
    }
    const int aoff = (nsplit && bn >= nsplit) ? a_off1 : 0;

    const int grow = tid >> 1;
    const int seg  = (tid & 1) << 1;
    const char* gAh = (const char*)(Ah + aoff + (size_t)(bm + grow) * lda);
    const char* gAl = (const char*)(Al + aoff + (size_t)(bm + grow) * lda);
    const char* gBh = (const char*)(Bh + (size_t)(bn + grow) * ldb);
    const char* gBl = (const char*)(Bl + (size_t)(bn + grow) * ldb);
    const uint32_t srow = smb + (uint32_t)(grow * ASTRIDE + seg * 16);

    const int wid = tid >> 5, lane = tid & 31;
    const int wm = (wid >> 2) * 64;
    const int wn = (wid & 3) * 32;
    const int tq = lane >> 2, tr = lane & 3;
    const uint32_t aoffm = (uint32_t)((wm + (lane & 15)) * ASTRIDE + ((lane >> 4) << 4));
    const int g = lane >> 3;
    const uint32_t boffm = (uint32_t)((wn + ((g >> 1) << 3) + (lane & 7)) * ASTRIDE + ((g & 1) << 4));

    float acc[4][4][4];
#pragma unroll
    for (int i = 0; i < 4; i++)
#pragma unroll
        for (int j = 0; j < 4; j++)
#pragma unroll
            for (int q = 0; q < 4; q++) acc[i][j][q] = 0.f;

    const int nch = K / BKC;

    auto issue = [&](int s) {
        const uint32_t st = srow + (uint32_t)(s & 1) * STG_STRIDE;
        const int go = s * (BKC * 2) + seg * 16;
        CPA16(st + STG_A_HI,      gAh + go);
        CPA16(st + STG_A_HI + 16, gAh + go + 16);
        CPA16(st + STG_A_LO,      gAl + go);
        CPA16(st + STG_A_LO + 16, gAl + go + 16);
        CPA16(st + STG_B_HI,      gBh + go);
        CPA16(st + STG_B_HI + 16, gBh + go + 16);
        CPA16(st + STG_B_LO,      gBl + go);
        CPA16(st + STG_B_LO + 16, gBl + go + 16);
        CPCOMMIT();
    };

    issue(0);
    for (int s = 0; s < nch; s++) {
        CPWAIT0();
        __syncthreads();
        if (s + 1 < nch) issue(s + 1);
        const uint32_t sa = smb + (uint32_t)(s & 1) * STG_STRIDE;
#pragma unroll
        for (int ph = 0; ph < 2; ph++) {
            const uint32_t ka = sa + ph * 32;
            uint32_t ah[4][4], al[4][4], bh[4][2], bl[4][2];
#pragma unroll
            for (int i = 0; i < 4; i++)
                LDM4(ah[i][0], ah[i][1], ah[i][2], ah[i][3], ka + STG_A_HI + aoffm + i*(16*ASTRIDE));
            LDM4(bh[0][0], bh[0][1], bh[1][0], bh[1][1], ka + STG_B_HI + boffm);
            LDM4(bh[2][0], bh[2][1], bh[3][0], bh[3][1], ka + STG_B_HI + boffm + 16*ASTRIDE);
#pragma unroll
            for (int i = 0; i < 4; i++)
#pragma unroll
                for (int j = 0; j < 4; j++)
                    MMA16816(acc[i][j], ah[i], bh[j]);
#pragma unroll
            for (int i = 0; i < 4; i++)
                LDM4(al[i][0], al[i][1], al[i][2], al[i][3], ka + STG_A_LO + aoffm + i*(16*ASTRIDE));
            LDM4(bl[0][0], bl[0][1], bl[1][0], bl[1][1], ka + STG_B_LO + boffm);
            LDM4(bl[2][0], bl[2][1], bl[3][0], bl[3][1], ka + STG_B_LO + boffm + 16*ASTRIDE);
#pragma unroll
            for (int i = 0; i < 4; i++)
#pragma unroll
                for (int j = 0; j < 4; j++)
                    MMA16816(acc[i][j], ah[i], bl[j]);
#pragma unroll
            for (int i = 0; i < 4; i++)
#pragma unroll
                for (int j = 0; j < 4; j++)
                    MMA16816(acc[i][j], al[i], bh[j]);
        }
    }

    const float* bias = nullptr;
    if (EPI == 1) bias = (nsplit && bn >= nsplit) ? (bias1 - nsplit) : bias0;
#pragma unroll
    for (int i = 0; i < 4; i++) {
        const int row0 = bm + wm + 16*i + tq;
#pragma unroll
        for (int j = 0; j < 4; j++) {
            const int col = bn + wn + 8*j + 2*tr;
            float v0 = acc[i][j][0], v1 = acc[i][j][1];
            float v2 = acc[i][j][2], v3 = acc[i][j][3];
            if (EPI == 1) {
                const float b0v = bias[col], b1v = bias[col+1];
                v0 += b0v; v1 += b1v; v2 += b0v; v3 += b1v;
                v0 = (v0 > 20.f) ? v0 : log1pf(__expf(v0));
                v1 = (v1 > 20.f) ? v1 : log1pf(__expf(v1));
                v2 = (v2 > 20.f) ? v2 : log1pf(__expf(v2));
                v3 = (v3 > 20.f) ? v3 : log1pf(__expf(v3));
            }
            *reinterpret_cast<float2*>(C + (size_t)row0 * ldc + col)       = make_float2(v0, v1);
            *reinterpret_cast<float2*>(C + (size_t)(row0 + 8) * ldc + col) = make_float2(v2, v3);
        }
    }
}

// ======================= merged convert kernels ===============================
#define N4_X    (MROWS*DMODEL/4)
#define N4_INW  (4096*DMODEL/4)
#define N4_DTW  (2048*DTR/4)
#define N4_XP   (256*DIN/4)
#define N4_OUT  (DMODEL*4096/4)

__global__ __launch_bounds__(256) void cvt_x_kernel(const float* __restrict__ x)
{
    const int i = blockIdx.x * 256 + threadIdx.x;
    store_planes(g_Xh, g_Xl, i, reinterpret_cast<const float4*>(x)[i]);
}

__global__ __launch_bounds__(256) void cvt_inw_kernel(
    const float* __restrict__ f, const float* __restrict__ b)
{
    const int i = blockIdx.x * 256 + threadIdx.x;
    const float4 v = (i < N4_INW)
        ? reinterpret_cast<const float4*>(f)[i]
        : reinterpret_cast<const float4*>(b)[i - N4_INW];
    store_planes(g_Winh, g_Winl, i, v);
}

__global__ __launch_bounds__(256) void cvt_rest_kernel(
    const float* __restrict__ dtW_f, const float* __restrict__ dtW_b,
    const float* __restrict__ xpW_f, const float* __restrict__ xpW_b,
    const float* __restrict__ outW_f, const float* __restrict__ outW_b)
{
    int i = blockIdx.x * 256 + threadIdx.x;
    if (i < 2*N4_DTW) {
        const float4 v = (i < N4_DTW)
            ? reinterpret_cast<const float4*>(dtW_f)[i]
            : reinterpret_cast<const float4*>(dtW_b)[i - N4_DTW];
        store_planes(g_dtWh, g_dtWl, i, v);
        return;
    }
    i -= 2*N4_DTW;
    if (i < N4_XP) {
        const int idx = i * 4;
        const int r = idx >> 11, c = idx & 2047;
        float4 v = make_float4(0.f,0.f,0.f,0.f);
        if (r < 96)                   v = *reinterpret_cast<const float4*>(xpW_f + r*2048 + c);
        else if (r >= 128 && r < 224) v = *reinterpret_cast<const float4*>(xpW_b + (r-128)*2048 + c);
        store_planes(g_Xph, g_Xpl, i, v);
        return;
    }
    i -= N4_XP;
    {
        const int idx = i * 4;
        const int r = idx >> 12, c = idx & 4095;
        const float4 v = (c < 2048)
            ? *reinterpret_cast<const float4*>(outW_f + (size_t)r*2048 + c)
            : *reinterpret_cast<const float4*>(outW_b + (size_t)r*2048 + (c - 2048));
        store_planes(g_Wouth, g_Woutl, i, v);
    }
}

__global__ __launch_bounds__(256) void reduce_out_kernel(float* __restrict__ out)
{
    const int i = blockIdx.x * 256 + threadIdx.x;
    float4 s = reinterpret_cast<const float4*>(g_OUTP)[i];
#pragma unroll
    for (int k = 1; k < 4; k++) {
        const float4 p = reinterpret_cast<const float4*>(g_OUTP + (size_t)k*MROWS*DMODEL)[i];
        s.x += p.x; s.y += p.y; s.z += p.z; s.w += p.w;
    }
    reinterpret_cast<float4*>(out)[i] = make_float4(0.5f*s.x, 0.5f*s.y, 0.5f*s.z, 0.5f*s.w);
}

// ------------- depthwise conv + SiLU; writes fp32 U and bf16 planes ----------
__global__ __launch_bounds__(256) void conv_silu_kernel(
    const float* __restrict__ convW_f, const float* __restrict__ convB_f,
    const float* __restrict__ convW_b, const float* __restrict__ convB_b)
{
    const int i = blockIdx.x * 256 + threadIdx.x;
    const int c = i & 4095;
    const int row = i >> 12;
    const int l = row & (LSEQ - 1);
    const int b = row >> 10;
    const int dir = c >> 11;
    const int d = c & (DIN - 1);
    const float* w = (dir ? convW_b : convW_f) + d*4;
    float acc = (dir ? convB_b : convB_f)[d];
    const float* xi = g_XZ + dir*4096 + d;
    if (dir == 0) {
#pragma unroll
        for (int k = 0; k < 4; k++) {
            int ls = l - 3 + k;
            if (ls >= 0) acc = fmaf(w[k], xi[(size_t)(b*LSEQ + ls)*8192], acc);
        }
    } else {
#pragma unroll
        for (int k = 0; k < 4; k++) {
            int ls = l + 3 - k;
            if (ls < LSEQ) acc = fmaf(w[k], xi[(size_t)(b*LSEQ + ls)*8192], acc);
        }
    }
    const float sig = 1.f / (1.f + __expf(-acc));
    const float u = acc * sig;
    const size_t o = (size_t)row*4096 + c;
    g_U[o] = u;
    __nv_bfloat16 h, lo2; split1(u, h, lo2);
    g_Uh[o] = h; g_Ul[o] = lo2;
}

// ------------------------- split-K reduce + plane split ----------------------
__global__ __launch_bounds__(256) void reduce_xdbl_kernel()
{
    const int i = blockIdx.x * 256 + threadIdx.x;
    float s = 0.f;
#pragma unroll
    for (int k = 0; k < 8; k++) s += g_XDBLP[(size_t)k*MROWS*256 + i];
    g_XDBL[i] = s;
    __nv_bfloat16 h, l; split1(s, h, l);
    g_XDh[i] = h; g_XDl[i] = l;
}

// ------------- selective scan: 2 states/thread, 4 d/warp, 3-shfl reduce ------
// block: 32 d-channels (d0 = bx*32), batch, dir. 256 threads.
// thread: warp w covers d = d0 + w*4 + (lane>>3); lane&7 = n'; states n', n'+8.
__global__ __launch_bounds__(256) void scan_kernel(
    const float* __restrict__ Alog_f, const float* __restrict__ Alog_b,
    const float* __restrict__ Dp_f,  const float* __restrict__ Dp_b)
{
    const int dir = blockIdx.z;
    const int b   = blockIdx.y;
    const int d0  = blockIdx.x * 32;
    const int t    = threadIdx.x;
    const int lane = t & 31;
    const int w    = t >> 5;
    const int dlw  = (w << 2) + (lane >> 3);   // 0..31 local d
    const int np   = lane & 7;                 // n' 0..7
    const int d    = d0 + dlw;

    const float* Alog = dir ? Alog_b : Alog_f;
    const float Ac0 = -__expf(Alog[d*NST + np]);
    const float Ac1 = -__expf(Alog[d*NST + np + 8]);
    const float DpE = (dir ? Dp_b : Dp_f)[d0 + (t & 31)];   // gating pass: dq = t&31

    __shared__ float2 sDdw[32][32];   // (delta, delta*u)      [ll][d_local]
    __shared__ float2 sUZ [32][32];   // (u, z)                [ll][d_local]
    __shared__ float4 sBC [32][8];    // (B[j],C[j],B[j+8],C[j+8]) [ll][j]
    __shared__ float  sY  [32][32];   // reduced py            [ll][d_local]

    // staging roles: 4 (ll,dq) per thread for D/U/Z; one BC pack per thread
    const int sll = t >> 5;           // changes with e by +8
    const int sdq = t & 31;
    const int bll = t >> 3, bj = t & 7;

    float rgD[4], rgU[4], rgZ[4], rgB[4];
    auto prefetch = [&](int lb) {
#pragma unroll
        for (int e = 0; e < 4; e++) {
            const int row = b*LSEQ + lb + sll + e*8;
            rgD[e] = g_DELTA[(size_t)row*4096 + dir*2048 + d0 + sdq];
            rgU[e] = g_U[(size_t)row*4096 + dir*2048 + d0 + sdq];
            rgZ[e] = g_XZ[(size_t)row*8192 + dir*4096 + 2048 + d0 + sdq];
        }
        const int rowb = b*LSEQ + lb + bll;
        rgB[0] = g_XDBL[(size_t)rowb*256 + dir*128 + 64 + bj];
        rgB[1] = g_XDBL[(size_t)rowb*256 + dir*128 + 80 + bj];
        rgB[2] = g_XDBL[(size_t)rowb*256 + dir*128 + 64 + bj + 8];
        rgB[3] = g_XDBL[(size_t)rowb*256 + dir*128 + 80 + bj + 8];
    };

    prefetch((dir == 0) ? 0 : (LSEQ - 32));

    float h0 = 0.f, h1 = 0.f;
    const int NCH = LSEQ / 32;
    for (int c = 0; c < NCH; c++) {
        __syncthreads();      // gating pass of chunk c-1 done
#pragma unroll
        for (int e = 0; e < 4; e++) {
            sDdw[sll + e*8][sdq] = make_float2(rgD[e], rgD[e]*rgU[e]);
            sUZ [sll + e*8][sdq] = make_float2(rgU[e], rgZ[e]);
        }
        sBC[bll][bj] = make_float4(rgB[0], rgB[1], rgB[2], rgB[3]);
        __syncthreads();
        if (c + 1 < NCH)
            prefetch((dir == 0) ? (c+1)*32 : (LSEQ - (c+2)*32));
        const int lb = (dir == 0) ? c*32 : (LSEQ - (c+1)*32);
        // ---- hot loop -------------------------------------------------------
#pragma unroll 4
        for (int s = 0; s < 32; s++) {
            const int ll = (dir == 0) ? s : (31 - s);
            const float2 ddw = sDdw[ll][dlw];
            const float4 bc  = sBC[ll][np];
            const float dA0 = __expf(ddw.x * Ac0);
            const float dA1 = __expf(ddw.x * Ac1);
            h0 = fmaf(h0, dA0, ddw.y * bc.x);
            h1 = fmaf(h1, dA1, ddw.y * bc.z);
            float py = fmaf(h1, bc.w, h0 * bc.y);
            py += __shfl_xor_sync(0xffffffffu, py, 4);
            py += __shfl_xor_sync(0xffffffffu, py, 2);
            py += __shfl_xor_sync(0xffffffffu, py, 1);
            if (np == 0) sY[ll][dlw] = py;
        }
        __syncthreads();
        // ---- gating pass: 4 outputs/thread ---------------------------------
#pragma unroll
        for (int e = 0; e < 4; e++) {
            const int ll = sll + e*8;
            const float2 uz = sUZ[ll][sdq];
            const float y = fmaf(uz.x, DpE, sY[ll][sdq]);
            const float sig = 1.f / (1.f + __expf(-uz.y));
            const float yg = y * (uz.y * sig);
            const size_t o = (size_t)(b*LSEQ + lb + ll)*4096 + dir*2048 + d0 + sdq;
            __nv_bfloat16 hh, lo2; split1(yg, hh, lo2);
            g_YGh[o] = hh; g_YGl[o] = lo2;
        }
    }
}

// ------------------------------------ launch ---------------------------------
extern "C" void kernel_launch(void* const* d_in, const int* in_sizes, int n_in,
                              void* d_out, int out_size)
{
    const float* x      = (const float*)d_in[0];
    const float* inW_f  = (const float*)d_in[1];
    const float* convW_f= (const float*)d_in[2];
    const float* convB_f= (const float*)d_in[3];
    const float* xpW_f  = (const float*)d_in[4];
    const float* dtW_f  = (const float*)d_in[5];
    const float* dtB_f  = (const float*)d_in[6];
    const float* Alog_f = (const float*)d_in[7];
    const float* Dp_f   = (const float*)d_in[8];
    const float* outW_f = (const float*)d_in[9];
    const float* inW_b  = (const float*)d_in[10];
    const float* convW_b= (const float*)d_in[11];
    const float* convB_b= (const float*)d_in[12];
    const float* xpW_b  = (const float*)d_in[13];
    const float* dtW_b  = (const float*)d_in[14];
    const float* dtB_b  = (const float*)d_in[15];
    const float* Alog_b = (const float*)d_in[16];
    const float* Dp_b   = (const float*)d_in[17];
    const float* outW_b = (const float*)d_in[18];
    float* out = (float*)d_out;

    float *XZ, *XDBLP, *DELTA, *OUTP;
    __nv_bfloat16 *Xh, *Xl, *Winh, *Winl, *Uh, *Ul, *Xph, *Xpl, *XDh, *XDl;
    __nv_bfloat16 *dtWh, *dtWl, *YGh, *YGl, *Wouth, *Woutl;
    cudaGetSymbolAddress((void**)&XZ,    g_XZ);
    cudaGetSymbolAddress((void**)&XDBLP, g_XDBLP);
    cudaGetSymbolAddress((void**)&DELTA, g_DELTA);
    cudaGetSymbolAddress((void**)&OUTP,  g_OUTP);
    cudaGetSymbolAddress((void**)&Xh,    g_Xh);
    cudaGetSymbolAddress((void**)&Xl,    g_Xl);
    cudaGetSymbolAddress((void**)&Winh,  g_Winh);
    cudaGetSymbolAddress((void**)&Winl,  g_Winl);
    cudaGetSymbolAddress((void**)&Uh,    g_Uh);
    cudaGetSymbolAddress((void**)&Ul,    g_Ul);
    cudaGetSymbolAddress((void**)&Xph,   g_Xph);
    cudaGetSymbolAddress((void**)&Xpl,   g_Xpl);
    cudaGetSymbolAddress((void**)&XDh,   g_XDh);
    cudaGetSymbolAddress((void**)&XDl,   g_XDl);
    cudaGetSymbolAddress((void**)&dtWh,  g_dtWh);
    cudaGetSymbolAddress((void**)&dtWl,  g_dtWl);
    cudaGetSymbolAddress((void**)&YGh,   g_YGh);
    cudaGetSymbolAddress((void**)&YGl,   g_YGl);
    cudaGetSymbolAddress((void**)&Wouth, g_Wouth);
    cudaGetSymbolAddress((void**)&Woutl, g_Woutl);

    cudaFuncSetAttribute(hgemm<0>, cudaFuncAttributeMaxDynamicSharedMemorySize, HG_SMEM);
    cudaFuncSetAttribute(hgemm<1>, cudaFuncAttributeMaxDynamicSharedMemorySize, HG_SMEM);

    // 0-2) merged converts (in-proj GEMM stays at launch index 3 = ncu slot)
    cvt_x_kernel  <<<N4_X/256, 256>>>(x);
    cvt_inw_kernel<<<2*N4_INW/256, 256>>>(inW_f, inW_b);
    cvt_rest_kernel<<<(2*N4_DTW + N4_XP + N4_OUT)/256, 256>>>(
        dtW_f, dtW_b, xpW_f, xpW_b, outW_f, outW_b);

    // 3) input projection: [2048,8192] = X[2048,1024] * Win[8192,1024]^T
    hgemm<0><<<dim3(64,16,1), 256, HG_SMEM>>>(
        Xh, Xl, DMODEL, 0, 0, Winh, Winl, DMODEL,
        XZ, 8192, DMODEL, nullptr, nullptr, 0);

    // 4) depthwise conv + SiLU (emits U fp32 + planes)
    conv_silu_kernel<<<(MROWS*4096)/256, 256>>>(convW_f, convB_f, convW_b, convB_b);

    // 5) x_dbl: [2048,256] = U[.,dir-slice] * Xp[256,2048]^T, split-K=8
    hgemm<0><<<dim3(2,16,8), 256, HG_SMEM>>>(
        Uh, Ul, 4096, 2048, 128, Xph, Xpl, DIN,
        XDBLP, 256, DIN, nullptr, nullptr, 256);
    reduce_xdbl_kernel<<<(MROWS*256)/256, 256>>>();

    // 6) delta = softplus(dt @ dtWcat^T + dtB), N=4096, K=64
    hgemm<1><<<dim3(32,16,1), 256, HG_SMEM>>>(
        XDh, XDl, 256, 128, 2048, dtWh, dtWl, DTR,
        DELTA, 4096, DTR, dtB_f, dtB_b, 0);

    // 7) selective scan + gating (2 states/thread, 3-shfl reduction)
    scan_kernel<<<dim3(64,2,2), 256>>>(Alog_f, Alog_b, Dp_f, Dp_b);

    // 8) out-proj split-K=4 (512 CTAs), then 0.5*sum
    hgemm<0><<<dim3(8,16,4), 256, HG_SMEM>>>(
        YGh, YGl, 4096, 0, 0, Wouth, Woutl, 4096,
        OUTP, DMODEL, 4096, nullptr, nullptr, 1024);
    reduce_out_kernel<<<(MROWS*DMODEL/4)/256, 256>>>(out);
}

// round 11
// speedup vs baseline: 1.8598x; 1.2510x over previous
#include <cuda_runtime.h>
#include <cuda_bf16.h>
#include <cuda_fp16.h>
#include <math.h>
#include <cstdint>

#define B_SZ   2
#define LSEQ   1024
#define DMODEL 1024
#define DIN    2048
#define NST    16
#define DTR    64
#define MROWS  (B_SZ*LSEQ)   /* 2048 */

// ---------------- scratch (device globals; no allocation allowed) ------------
__device__ float g_XZ[MROWS*8192];              // [m][dir*4096 + (xi | z)]
__device__ float g_U [MROWS*4096];              // fp32 for scan
__device__ __nv_bfloat16 g_Uh[MROWS*4096],  g_Ul[MROWS*4096];
__device__ __half g_Xh[MROWS*DMODEL], g_Xl[MROWS*DMODEL];       // fp16 planes (in-proj A)
__device__ __half g_Win[8192*DMODEL];                            // single fp16 plane (in-proj B)
__device__ __nv_bfloat16 g_Xph[256*DIN],    g_Xpl[256*DIN];      // padded xpW
__device__ float g_XDBLP[8*MROWS*256];
__device__ float g_XDBL[MROWS*256];
__device__ __nv_bfloat16 g_XDh[MROWS*256],  g_XDl[MROWS*256];
__device__ __nv_bfloat16 g_dtWh[4096*DTR],  g_dtWl[4096*DTR];    // dir-concat rows
__device__ float g_DELTA[(size_t)MROWS*4096];
__device__ __half g_YGh[MROWS*4096], g_YGl[MROWS*4096];          // fp16 planes (out-proj A)
__device__ __half g_Wout[DMODEL*4096];                           // single fp16 plane (out-proj B)
__device__ float g_OUTP[4*MROWS*DMODEL];        // out-proj split-K=4 partials

// ======================= helpers =============================================
__device__ __forceinline__ uint32_t smem_u32(const void* p) {
    uint32_t a;
    asm("{ .reg .u64 t; cvta.to.shared.u64 t, %1; cvt.u32.u64 %0, t; }" : "=r"(a) : "l"(p));
    return a;
}
#define LDM4(r0,r1,r2,r3,addr)                                                      \
    asm volatile("ldmatrix.sync.aligned.m8n8.x4.shared.b16 {%0,%1,%2,%3}, [%4];"    \
        : "=r"(r0),"=r"(r1),"=r"(r2),"=r"(r3) : "r"(addr))
#define MMA_BF16(c,a,b)                                                             \
    asm volatile("mma.sync.aligned.m16n8k16.row.col.f32.bf16.bf16.f32 "             \
        "{%0,%1,%2,%3}, {%4,%5,%6,%7}, {%8,%9}, {%0,%1,%2,%3};"                     \
        : "+f"((c)[0]),"+f"((c)[1]),"+f"((c)[2]),"+f"((c)[3])                       \
        : "r"((a)[0]),"r"((a)[1]),"r"((a)[2]),"r"((a)[3]),"r"((b)[0]),"r"((b)[1]))
#define MMA_F16(c,a,b)                                                              \
    asm volatile("mma.sync.aligned.m16n8k16.row.col.f32.f16.f16.f32 "               \
        "{%0,%1,%2,%3}, {%4,%5,%6,%7}, {%8,%9}, {%0,%1,%2,%3};"                     \
        : "+f"((c)[0]),"+f"((c)[1]),"+f"((c)[2]),"+f"((c)[3])                       \
        : "r"((a)[0]),"r"((a)[1]),"r"((a)[2]),"r"((a)[3]),"r"((b)[0]),"r"((b)[1]))
#define CPA16(dst, src) asm volatile("cp.async.cg.shared.global [%0], [%1], 16;" :: "r"(dst), "l"(src) : "memory")
#define CPCOMMIT()      asm volatile("cp.async.commit_group;" ::: "memory")
#define CPWAIT0()       asm volatile("cp.async.wait_group 0;" ::: "memory")

__device__ __forceinline__ void split1(float v, __nv_bfloat16& h, __nv_bfloat16& l) {
    h = __float2bfloat16(v);
    l = __float2bfloat16(v - __bfloat162float(h));
}
__device__ __forceinline__ void split1h(float v, __half& h, __half& l) {
    h = __float2half(v);
    l = __float2half(v - __half2float(h));
}
__device__ __forceinline__ void store_planes(
    __nv_bfloat16* __restrict__ hi, __nv_bfloat16* __restrict__ lo,
    int i, float4 v)
{
    __nv_bfloat16 h0,h1,h2,h3,l0,l1,l2,l3;
    split1(v.x,h0,l0); split1(v.y,h1,l1); split1(v.z,h2,l2); split1(v.w,h3,l3);
    reinterpret_cast<__nv_bfloat162*>(hi)[2*i]   = __nv_bfloat162(h0,h1);
    reinterpret_cast<__nv_bfloat162*>(hi)[2*i+1] = __nv_bfloat162(h2,h3);
    reinterpret_cast<__nv_bfloat162*>(lo)[2*i]   = __nv_bfloat162(l0,l1);
    reinterpret_cast<__nv_bfloat162*>(lo)[2*i+1] = __nv_bfloat162(l2,l3);
}
__device__ __forceinline__ void store_planes_h(
    __half* __restrict__ hi, __half* __restrict__ lo, int i, float4 v)
{
    __half h0,h1,h2,h3,l0,l1,l2,l3;
    split1h(v.x,h0,l0); split1h(v.y,h1,l1); split1h(v.z,h2,l2); split1h(v.w,h3,l3);
    reinterpret_cast<__half2*>(hi)[2*i]   = __half2(h0,h1);
    reinterpret_cast<__half2*>(hi)[2*i+1] = __half2(h2,h3);
    reinterpret_cast<__half2*>(lo)[2*i]   = __half2(l0,l1);
    reinterpret_cast<__half2*>(lo)[2*i+1] = __half2(l2,l3);
}

// ======================= bf16 3-term GEMM (small stages) =====================
#define BKC 32
#define ASTRIDE 80
#define STG_A_HI 0
#define STG_A_LO 10240
#define STG_B_HI 20480
#define STG_B_LO 30720
#define STG_STRIDE 40960
#define HG_SMEM (2*STG_STRIDE)

template<int EPI>
__global__ __launch_bounds__(256, 2) void hgemm(
    const __nv_bfloat16* __restrict__ Ah, const __nv_bfloat16* __restrict__ Al,
    int lda, int a_off1, int nsplit,
    const __nv_bfloat16* __restrict__ Bh, const __nv_bfloat16* __restrict__ Bl,
    int ldb,
    float* __restrict__ C, int ldc, int K,
    const float* __restrict__ bias0, const float* __restrict__ bias1,
    int kz)
{
    extern __shared__ char sm[];
    const uint32_t smb = smem_u32(sm);
    const int tid = threadIdx.x;
    const int bm = blockIdx.y * 128, bn = blockIdx.x * 128;
    if (kz > 0) {
        Ah += (size_t)blockIdx.z * kz;  Al += (size_t)blockIdx.z * kz;
        Bh += (size_t)blockIdx.z * kz;  Bl += (size_t)blockIdx.z * kz;
        C  += (size_t)blockIdx.z * (size_t)(gridDim.y * 128) * (size_t)ldc;
        K = kz;
    }
    const int aoff = (nsplit && bn >= nsplit) ? a_off1 : 0;

    const int grow = tid >> 1;
    const int seg  = (tid & 1) << 1;
    const char* gAh = (const char*)(Ah + aoff + (size_t)(bm + grow) * lda);
    const char* gAl = (const char*)(Al + aoff + (size_t)(bm + grow) * lda);
    const char* gBh = (const char*)(Bh + (size_t)(bn + grow) * ldb);
    const char* gBl = (const char*)(Bl + (size_t)(bn + grow) * ldb);
    const uint32_t srow = smb + (uint32_t)(grow * ASTRIDE + seg * 16);

    const int wid = tid >> 5, lane = tid & 31;
    const int wm = (wid >> 2) * 64;
    const int wn = (wid & 3) * 32;
    const int tq = lane >> 2, tr = lane & 3;
    const uint32_t aoffm = (uint32_t)((wm + (lane & 15)) * ASTRIDE + ((lane >> 4) << 4));
    const int g = lane >> 3;
    const uint32_t boffm = (uint32_t)((wn + ((g >> 1) << 3) + (lane & 7)) * ASTRIDE + ((g & 1) << 4));

    float acc[4][4][4];
#pragma unroll
    for (int i = 0; i < 4; i++)
#pragma unroll
        for (int j = 0; j < 4; j++)
#pragma unroll
            for (int q = 0; q < 4; q++) acc[i][j][q] = 0.f;

    const int nch = K / BKC;

    auto issue = [&](int s) {
        const uint32_t st = srow + (uint32_t)(s & 1) * STG_STRIDE;
        const int go = s * (BKC * 2) + seg * 16;
        CPA16(st + STG_A_HI,      gAh + go);
        CPA16(st + STG_A_HI + 16, gAh + go + 16);
        CPA16(st + STG_A_LO,      gAl + go);
        CPA16(st + STG_A_LO + 16, gAl + go + 16);
        CPA16(st + STG_B_HI,      gBh + go);
        CPA16(st + STG_B_HI + 16, gBh + go + 16);
        CPA16(st + STG_B_LO,      gBl + go);
        CPA16(st + STG_B_LO + 16, gBl + go + 16);
        CPCOMMIT();
    };

    issue(0);
    for (int s = 0; s < nch; s++) {
        CPWAIT0();
        __syncthreads();
        if (s + 1 < nch) issue(s + 1);
        const uint32_t sa = smb + (uint32_t)(s & 1) * STG_STRIDE;
#pragma unroll
        for (int ph = 0; ph < 2; ph++) {
            const uint32_t ka = sa + ph * 32;
            uint32_t ah[4][4], al[4][4], bh[4][2], bl[4][2];
#pragma unroll
            for (int i = 0; i < 4; i++)
                LDM4(ah[i][0], ah[i][1], ah[i][2], ah[i][3], ka + STG_A_HI + aoffm + i*(16*ASTRIDE));
            LDM4(bh[0][0], bh[0][1], bh[1][0], bh[1][1], ka + STG_B_HI + boffm);
            LDM4(bh[2][0], bh[2][1], bh[3][0], bh[3][1], ka + STG_B_HI + boffm + 16*ASTRIDE);
#pragma unroll
            for (int i = 0; i < 4; i++)
#pragma unroll
                for (int j = 0; j < 4; j++)
                    MMA_BF16(acc[i][j], ah[i], bh[j]);
#pragma unroll
            for (int i = 0; i < 4; i++)
                LDM4(al[i][0], al[i][1], al[i][2], al[i][3], ka + STG_A_LO + aoffm + i*(16*ASTRIDE));
            LDM4(bl[0][0], bl[0][1], bl[1][0], bl[1][1], ka + STG_B_LO + boffm);
            LDM4(bl[2][0], bl[2][1], bl[3][0], bl[3][1], ka + STG_B_LO + boffm + 16*ASTRIDE);
#pragma unroll
            for (int i = 0; i < 4; i++)
#pragma unroll
                for (int j = 0; j < 4; j++)
                    MMA_BF16(acc[i][j], ah[i], bl[j]);
#pragma unroll
            for (int i = 0; i < 4; i++)
#pragma unroll
                for (int j = 0; j < 4; j++)
                    MMA_BF16(acc[i][j], al[i], bh[j]);
        }
    }

    const float* bias = nullptr;
    if (EPI == 1) bias = (nsplit && bn >= nsplit) ? (bias1 - nsplit) : bias0;
#pragma unroll
    for (int i = 0; i < 4; i++) {
        const int row0 = bm + wm + 16*i + tq;
#pragma unroll
        for (int j = 0; j < 4; j++) {
            const int col = bn + wn + 8*j + 2*tr;
            float v0 = acc[i][j][0], v1 = acc[i][j][1];
            float v2 = acc[i][j][2], v3 = acc[i][j][3];
            if (EPI == 1) {
                const float b0v = bias[col], b1v = bias[col+1];
                v0 += b0v; v1 += b1v; v2 += b0v; v3 += b1v;
                v0 = (v0 > 20.f) ? v0 : log1pf(__expf(v0));
                v1 = (v1 > 20.f) ? v1 : log1pf(__expf(v1));
                v2 = (v2 > 20.f) ? v2 : log1pf(__expf(v2));
                v3 = (v3 > 20.f) ? v3 : log1pf(__expf(v3));
            }
            *reinterpret_cast<float2*>(C + (size_t)row0 * ldc + col)       = make_float2(v0, v1);
            *reinterpret_cast<float2*>(C + (size_t)(row0 + 8) * ldc + col) = make_float2(v2, v3);
        }
    }
}

// ======================= fp16 2-term GEMM (A hi/lo, B single plane) ==========
#define H2_A_HI 0
#define H2_A_LO 10240
#define H2_B    20480
#define H2_STRIDE 30720
#define H2_SMEM (2*H2_STRIDE)

__global__ __launch_bounds__(256, 2) void hgemm2(
    const __half* __restrict__ Ah, const __half* __restrict__ Al, int lda,
    const __half* __restrict__ B, int ldb,
    float* __restrict__ C, int ldc, int K, int kz)
{
    extern __shared__ char sm[];
    const uint32_t smb = smem_u32(sm);
    const int tid = threadIdx.x;
    const int bm = blockIdx.y * 128, bn = blockIdx.x * 128;
    if (kz > 0) {
        Ah += (size_t)blockIdx.z * kz;  Al += (size_t)blockIdx.z * kz;
        B  += (size_t)blockIdx.z * kz;
        C  += (size_t)blockIdx.z * (size_t)(gridDim.y * 128) * (size_t)ldc;
        K = kz;
    }

    const int grow = tid >> 1;
    const int seg  = (tid & 1) << 1;
    const char* gAh = (const char*)(Ah + (size_t)(bm + grow) * lda);
    const char* gAl = (const char*)(Al + (size_t)(bm + grow) * lda);
    const char* gB  = (const char*)(B  + (size_t)(bn + grow) * ldb);
    const uint32_t srow = smb + (uint32_t)(grow * ASTRIDE + seg * 16);

    const int wid = tid >> 5, lane = tid & 31;
    const int wm = (wid >> 2) * 64;
    const int wn = (wid & 3) * 32;
    const int tq = lane >> 2, tr = lane & 3;
    const uint32_t aoffm = (uint32_t)((wm + (lane & 15)) * ASTRIDE + ((lane >> 4) << 4));
    const int g = lane >> 3;
    const uint32_t boffm = (uint32_t)((wn + ((g >> 1) << 3) + (lane & 7)) * ASTRIDE + ((g & 1) << 4));

    float acc[4][4][4];
#pragma unroll
    for (int i = 0; i < 4; i++)
#pragma unroll
        for (int j = 0; j < 4; j++)
#pragma unroll
            for (int q = 0; q < 4; q++) acc[i][j][q] = 0.f;

    const int nch = K / BKC;

    auto issue = [&](int s) {
        const uint32_t st = srow + (uint32_t)(s & 1) * H2_STRIDE;
        const int go = s * (BKC * 2) + seg * 16;
        CPA16(st + H2_A_HI,      gAh + go);
        CPA16(st + H2_A_HI + 16, gAh + go + 16);
        CPA16(st + H2_A_LO,      gAl + go);
        CPA16(st + H2_A_LO + 16, gAl + go + 16);
        CPA16(st + H2_B,         gB + go);
        CPA16(st + H2_B + 16,    gB + go + 16);
        CPCOMMIT();
    };

    issue(0);
    for (int s = 0; s < nch; s++) {
        CPWAIT0();
        __syncthreads();
        if (s + 1 < nch) issue(s + 1);
        const uint32_t sa = smb + (uint32_t)(s & 1) * H2_STRIDE;
#pragma unroll
        for (int ph = 0; ph < 2; ph++) {
            const uint32_t ka = sa + ph * 32;
            uint32_t ah[4][4], al[4][4], bb[4][2];
#pragma unroll
            for (int i = 0; i < 4; i++)
                LDM4(ah[i][0], ah[i][1], ah[i][2], ah[i][3], ka + H2_A_HI + aoffm + i*(16*ASTRIDE));
            LDM4(bb[0][0], bb[0][1], bb[1][0], bb[1][1], ka + H2_B + boffm);
            LDM4(bb[2][0], bb[2][1], bb[3][0], bb[3][1], ka + H2_B + boffm + 16*ASTRIDE);
#pragma unroll
            for (int i = 0; i < 4; i++)
#pragma unroll
                for (int j = 0; j < 4; j++)
                    MMA_F16(acc[i][j], ah[i], bb[j]);
#pragma unroll
            for (int i = 0; i < 4; i++)
                LDM4(al[i][0], al[i][1], al[i][2], al[i][3], ka + H2_A_LO + aoffm + i*(16*ASTRIDE));
#pragma unroll
            for (int i = 0; i < 4; i++)
#pragma unroll
                for (int j = 0; j < 4; j++)
                    MMA_F16(acc[i][j], al[i], bb[j]);
        }
    }

#pragma unroll
    for (int i = 0; i < 4; i++) {
        const int row0 = bm + wm + 16*i + tq;
#pragma unroll
        for (int j = 0; j < 4; j++) {
            const int col = bn + wn + 8*j + 2*tr;
            *reinterpret_cast<float2*>(C + (size_t)row0 * ldc + col)
                = make_float2(acc[i][j][0], acc[i][j][1]);
            *reinterpret_cast<float2*>(C + (size_t)(row0 + 8) * ldc + col)
                = make_float2(acc[i][j][2], acc[i][j][3]);
        }
    }
}

// ======================= merged convert kernels ===============================
#define N4_X    (MROWS*DMODEL/4)
#define N4_INW  (4096*DMODEL/4)
#define N4_DTW  (2048*DTR/4)
#define N4_XP   (256*DIN/4)
#define N4_OUT  (DMODEL*4096/4)

__global__ __launch_bounds__(256) void cvt_x_kernel(const float* __restrict__ x)
{
    const int i = blockIdx.x * 256 + threadIdx.x;
    store_planes_h(g_Xh, g_Xl, i, reinterpret_cast<const float4*>(x)[i]);
}

__global__ __launch_bounds__(256) void cvt_inw_kernel(
    const float* __restrict__ f, const float* __restrict__ b)
{
    const int i = blockIdx.x * 256 + threadIdx.x;
    const float4 v = (i < N4_INW)
        ? reinterpret_cast<const float4*>(f)[i]
        : reinterpret_cast<const float4*>(b)[i - N4_INW];
    reinterpret_cast<__half2*>(g_Win)[2*i]   = __floats2half2_rn(v.x, v.y);
    reinterpret_cast<__half2*>(g_Win)[2*i+1] = __floats2half2_rn(v.z, v.w);
}

__global__ __launch_bounds__(256) void cvt_rest_kernel(
    const float* __restrict__ dtW_f, const float* __restrict__ dtW_b,
    const float* __restrict__ xpW_f, const float* __restrict__ xpW_b,
    const float* __restrict__ outW_f, const float* __restrict__ outW_b)
{
    int i = blockIdx.x * 256 + threadIdx.x;
    if (i < 2*N4_DTW) {
        const float4 v = (i < N4_DTW)
            ? reinterpret_cast<const float4*>(dtW_f)[i]
            : reinterpret_cast<const float4*>(dtW_b)[i - N4_DTW];
        store_planes(g_dtWh, g_dtWl, i, v);
        return;
    }
    i -= 2*N4_DTW;
    if (i < N4_XP) {
        const int idx = i * 4;
        const int r = idx >> 11, c = idx & 2047;
        float4 v = make_float4(0.f,0.f,0.f,0.f);
        if (r < 96)                   v = *reinterpret_cast<const float4*>(xpW_f + r*2048 + c);
        else if (r >= 128 && r < 224) v = *reinterpret_cast<const float4*>(xpW_b + (r-128)*2048 + c);
        store_planes(g_Xph, g_Xpl, i, v);
        return;
    }
    i -= N4_XP;
    {   // outW K-concat -> single fp16 plane
        const int idx = i * 4;
        const int r = idx >> 12, c = idx & 4095;
        const float4 v = (c < 2048)
            ? *reinterpret_cast<const float4*>(outW_f + (size_t)r*2048 + c)
            : *reinterpret_cast<const float4*>(outW_b + (size_t)r*2048 + (c - 2048));
        reinterpret_cast<__half2*>(g_Wout)[2*i]   = __floats2half2_rn(v.x, v.y);
        reinterpret_cast<__half2*>(g_Wout)[2*i+1] = __floats2half2_rn(v.z, v.w);
    }
}

__global__ __launch_bounds__(256) void reduce_out_kernel(float* __restrict__ out)
{
    const int i = blockIdx.x * 256 + threadIdx.x;
    float4 s = reinterpret_cast<const float4*>(g_OUTP)[i];
#pragma unroll
    for (int k = 1; k < 4; k++) {
        const float4 p = reinterpret_cast<const float4*>(g_OUTP + (size_t)k*MROWS*DMODEL)[i];
        s.x += p.x; s.y += p.y; s.z += p.z; s.w += p.w;
    }
    reinterpret_cast<float4*>(out)[i] = make_float4(0.5f*s.x, 0.5f*s.y, 0.5f*s.z, 0.5f*s.w);
}

// ------------- depthwise conv + SiLU; writes fp32 U and bf16 planes ----------
__global__ __launch_bounds__(256) void conv_silu_kernel(
    const float* __restrict__ convW_f, const float* __restrict__ convB_f,
    const float* __restrict__ convW_b, const float* __restrict__ convB_b)
{
    const int i = blockIdx.x * 256 + threadIdx.x;
    const int c = i & 4095;
    const int row = i >> 12;
    const int l = row & (LSEQ - 1);
    const int b = row >> 10;
    const int dir = c >> 11;
    const int d = c & (DIN - 1);
    const float* w = (dir ? convW_b : convW_f) + d*4;
    float acc = (dir ? convB_b : convB_f)[d];
    const float* xi = g_XZ + dir*4096 + d;
    if (dir == 0) {
#pragma unroll
        for (int k = 0; k < 4; k++) {
            int ls = l - 3 + k;
            if (ls >= 0) acc = fmaf(w[k], xi[(size_t)(b*LSEQ + ls)*8192], acc);
        }
    } else {
#pragma unroll
        for (int k = 0; k < 4; k++) {
            int ls = l + 3 - k;
            if (ls < LSEQ) acc = fmaf(w[k], xi[(size_t)(b*LSEQ + ls)*8192], acc);
        }
    }
    const float sig = 1.f / (1.f + __expf(-acc));
    const float u = acc * sig;
    const size_t o = (size_t)row*4096 + c;
    g_U[o] = u;
    __nv_bfloat16 h, lo2; split1(u, h, lo2);
    g_Uh[o] = h; g_Ul[o] = lo2;
}

// ------------------------- split-K reduce + plane split ----------------------
__global__ __launch_bounds__(256) void reduce_xdbl_kernel()
{
    const int i = blockIdx.x * 256 + threadIdx.x;
    float s = 0.f;
#pragma unroll
    for (int k = 0; k < 8; k++) s += g_XDBLP[(size_t)k*MROWS*256 + i];
    g_XDBL[i] = s;
    __nv_bfloat16 h, l; split1(s, h, l);
    g_XDh[i] = h; g_XDl[i] = l;
}

// ------------- selective scan: 2 states/thread, 4 d/warp, 3-shfl reduce ------
__global__ __launch_bounds__(256) void scan_kernel(
    const float* __restrict__ Alog_f, const float* __restrict__ Alog_b,
    const float* __restrict__ Dp_f,  const float* __restrict__ Dp_b)
{
    const int dir = blockIdx.z;
    const int b   = blockIdx.y;
    const int d0  = blockIdx.x * 32;
    const int t    = threadIdx.x;
    const int lane = t & 31;
    const int w    = t >> 5;
    const int dlw  = (w << 2) + (lane >> 3);
    const int np   = lane & 7;
    const int d    = d0 + dlw;

    const float* Alog = dir ? Alog_b : Alog_f;
    const float Ac0 = -__expf(Alog[d*NST + np]);
    const float Ac1 = -__expf(Alog[d*NST + np + 8]);
    const float DpE = (dir ? Dp_b : Dp_f)[d0 + (t & 31)];

    __shared__ float2 sDdw[32][32];
    __shared__ float2 sUZ [32][32];
    __shared__ float4 sBC [32][8];
    __shared__ float  sY  [32][32];

    const int sll = t >> 5;
    const int sdq = t & 31;
    const int bll = t >> 3, bj = t & 7;

    float rgD[4], rgU[4], rgZ[4], rgB[4];
    auto prefetch = [&](int lb) {
#pragma unroll
        for (int e = 0; e < 4; e++) {
            const int row = b*LSEQ + lb + sll + e*8;
            rgD[e] = g_DELTA[(size_t)row*4096 + dir*2048 + d0 + sdq];
            rgU[e] = g_U[(size_t)row*4096 + dir*2048 + d0 + sdq];
            rgZ[e] = g_XZ[(size_t)row*8192 + dir*4096 + 2048 + d0 + sdq];
        }
        const int rowb = b*LSEQ + lb + bll;
        rgB[0] = g_XDBL[(size_t)rowb*256 + dir*128 + 64 + bj];
        rgB[1] = g_XDBL[(size_t)rowb*256 + dir*128 + 80 + bj];
        rgB[2] = g_XDBL[(size_t)rowb*256 + dir*128 + 64 + bj + 8];
        rgB[3] = g_XDBL[(size_t)rowb*256 + dir*128 + 80 + bj + 8];
    };

    prefetch((dir == 0) ? 0 : (LSEQ - 32));

    float h0 = 0.f, h1 = 0.f;
    const int NCH = LSEQ / 32;
    for (int c = 0; c < NCH; c++) {
        __syncthreads();
#pragma unroll
        for (int e = 0; e < 4; e++) {
            sDdw[sll + e*8][sdq] = make_float2(rgD[e], rgD[e]*rgU[e]);
            sUZ [sll + e*8][sdq] = make_float2(rgU[e], rgZ[e]);
        }
        sBC[bll][bj] = make_float4(rgB[0], rgB[1], rgB[2], rgB[3]);
        __syncthreads();
        if (c + 1 < NCH)
            prefetch((dir == 0) ? (c+1)*32 : (LSEQ - (c+2)*32));
        const int lb = (dir == 0) ? c*32 : (LSEQ - (c+1)*32);
#pragma unroll 4
        for (int s = 0; s < 32; s++) {
            const int ll = (dir == 0) ? s : (31 - s);
            const float2 ddw = sDdw[ll][dlw];
            const float4 bc  = sBC[ll][np];
            const float dA0 = __expf(ddw.x * Ac0);
            const float dA1 = __expf(ddw.x * Ac1);
            h0 = fmaf(h0, dA0, ddw.y * bc.x);
            h1 = fmaf(h1, dA1, ddw.y * bc.z);
            float py = fmaf(h1, bc.w, h0 * bc.y);
            py += __shfl_xor_sync(0xffffffffu, py, 4);
            py += __shfl_xor_sync(0xffffffffu, py, 2);
            py += __shfl_xor_sync(0xffffffffu, py, 1);
            if (np == 0) sY[ll][dlw] = py;
        }
        __syncthreads();
#pragma unroll
        for (int e = 0; e < 4; e++) {
            const int ll = sll + e*8;
            const float2 uz = sUZ[ll][sdq];
            const float y = fmaf(uz.x, DpE, sY[ll][sdq]);
            const float sig = 1.f / (1.f + __expf(-uz.y));
            const float yg = y * (uz.y * sig);
            const size_t o = (size_t)(b*LSEQ + lb + ll)*4096 + dir*2048 + d0 + sdq;
            __half hh, lo2; split1h(yg, hh, lo2);
            g_YGh[o] = hh; g_YGl[o] = lo2;
        }
    }
}

// ------------------------------------ launch ---------------------------------
extern "C" void kernel_launch(void* const* d_in, const int* in_sizes, int n_in,
                              void* d_out, int out_size)
{
    const float* x      = (const float*)d_in[0];
    const float* inW_f  = (const float*)d_in[1];
    const float* convW_f= (const float*)d_in[2];
    const float* convB_f= (const float*)d_in[3];
    const float* xpW_f  = (const float*)d_in[4];
    const float* dtW_f  = (const float*)d_in[5];
    const float* dtB_f  = (const float*)d_in[6];
    const float* Alog_f = (const float*)d_in[7];
    const float* Dp_f   = (const float*)d_in[8];
    const float* outW_f = (const float*)d_in[9];
    const float* inW_b  = (const float*)d_in[10];
    const float* convW_b= (const float*)d_in[11];
    const float* convB_b= (const float*)d_in[12];
    const float* xpW_b  = (const float*)d_in[13];
    const float* dtW_b  = (const float*)d_in[14];
    const float* dtB_b  = (const float*)d_in[15];
    const float* Alog_b = (const float*)d_in[16];
    const float* Dp_b   = (const float*)d_in[17];
    const float* outW_b = (const float*)d_in[18];
    float* out = (float*)d_out;

    float *XZ, *XDBLP, *DELTA, *OUTP;
    __nv_bfloat16 *Uh, *Ul, *Xph, *Xpl, *XDh, *XDl, *dtWh, *dtWl;
    __half *Xh, *Xl, *Win, *YGh, *YGl, *Wout;
    cudaGetSymbolAddress((void**)&XZ,    g_XZ);
    cudaGetSymbolAddress((void**)&XDBLP, g_XDBLP);
    cudaGetSymbolAddress((void**)&DELTA, g_DELTA);
    cudaGetSymbolAddress((void**)&OUTP,  g_OUTP);
    cudaGetSymbolAddress((void**)&Xh,    g_Xh);
    cudaGetSymbolAddress((void**)&Xl,    g_Xl);
    cudaGetSymbolAddress((void**)&Win,   g_Win);
    cudaGetSymbolAddress((void**)&Uh,    g_Uh);
    cudaGetSymbolAddress((void**)&Ul,    g_Ul);
    cudaGetSymbolAddress((void**)&Xph,   g_Xph);
    cudaGetSymbolAddress((void**)&Xpl,   g_Xpl);
    cudaGetSymbolAddress((void**)&XDh,   g_XDh);
    cudaGetSymbolAddress((void**)&XDl,   g_XDl);
    cudaGetSymbolAddress((void**)&dtWh,  g_dtWh);
    cudaGetSymbolAddress((void**)&dtWl,  g_dtWl);
    cudaGetSymbolAddress((void**)&YGh,   g_YGh);
    cudaGetSymbolAddress((void**)&YGl,   g_YGl);
    cudaGetSymbolAddress((void**)&Wout,  g_Wout);

    cudaFuncSetAttribute(hgemm<0>, cudaFuncAttributeMaxDynamicSharedMemorySize, HG_SMEM);
    cudaFuncSetAttribute(hgemm<1>, cudaFuncAttributeMaxDynamicSharedMemorySize, HG_SMEM);
    cudaFuncSetAttribute(hgemm2,   cudaFuncAttributeMaxDynamicSharedMemorySize, H2_SMEM);

    // 0-2) converts (in-proj GEMM stays at launch index 3 = ncu slot)
    cvt_x_kernel  <<<N4_X/256, 256>>>(x);
    cvt_inw_kernel<<<2*N4_INW/256, 256>>>(inW_f, inW_b);
    cvt_rest_kernel<<<(2*N4_DTW + N4_XP + N4_OUT)/256, 256>>>(
        dtW_f, dtW_b, xpW_f, xpW_b, outW_f, outW_b);

    // 3) input projection (fp16 2-term): [2048,8192] = X * Win^T
    hgemm2<<<dim3(64,16,1), 256, H2_SMEM>>>(
        Xh, Xl, DMODEL, Win, DMODEL, XZ, 8192, DMODEL, 0);

    // 4) depthwise conv + SiLU (emits U fp32 + bf16 planes)
    conv_silu_kernel<<<(MROWS*4096)/256, 256>>>(convW_f, convB_f, convW_b, convB_b);

    // 5) x_dbl (bf16 3-term): split-K=8
    hgemm<0><<<dim3(2,16,8), 256, HG_SMEM>>>(
        Uh, Ul, 4096, 2048, 128, Xph, Xpl, DIN,
        XDBLP, 256, DIN, nullptr, nullptr, 256);
    reduce_xdbl_kernel<<<(MROWS*256)/256, 256>>>();

    // 6) delta = softplus(dt @ dtWcat^T + dtB) (bf16 3-term)
    hgemm<1><<<dim3(32,16,1), 256, HG_SMEM>>>(
        XDh, XDl, 256, 128, 2048, dtWh, dtWl, DTR,
        DELTA, 4096, DTR, dtB_f, dtB_b, 0);

    // 7) selective scan + gating (emits YG fp16 planes)
    scan_kernel<<<dim3(64,2,2), 256>>>(Alog_f, Alog_b, Dp_f, Dp_b);

    // 8) out-proj (fp16 2-term) split-K=4, then 0.5*sum
    hgemm2<<<dim3(8,16,4), 256, H2_SMEM>>>(
        YGh, YGl, 4096, Wout, 4096, OUTP, DMODEL, 4096, 1024);
    reduce_out_kernel<<<(MROWS*DMODEL/4)/256, 256>>>(out);
}

// round 12
// speedup vs baseline: 2.1502x; 1.1562x over previous
#include <cuda_runtime.h>
#include <cuda_bf16.h>
#include <cuda_fp16.h>
#include <math.h>
#include <cstdint>

#define B_SZ   2
#define LSEQ   1024
#define DMODEL 1024
#define DIN    2048
#define NST    16
#define DTR    64
#define MROWS  (B_SZ*LSEQ)   /* 2048 */

// ---------------- scratch (device globals; no allocation allowed) ------------
__device__ float g_XZ[MROWS*8192];              // [m][dir*4096 + (xi | z)]
__device__ float g_U [MROWS*4096];              // fp32 for scan
__device__ __nv_bfloat16 g_Uh[MROWS*4096],  g_Ul[MROWS*4096];
__device__ __half g_Xh[MROWS*DMODEL];                            // single fp16 plane (in-proj A)
__device__ __half g_Win[8192*DMODEL];                            // single fp16 plane (in-proj B)
__device__ __nv_bfloat16 g_Xph[256*DIN],    g_Xpl[256*DIN];      // padded xpW
__device__ float g_XDBLP[8*MROWS*256];
__device__ float g_XDBL[MROWS*256];
__device__ __nv_bfloat16 g_XDh[MROWS*256],  g_XDl[MROWS*256];
__device__ __nv_bfloat16 g_dtWh[4096*DTR],  g_dtWl[4096*DTR];    // dir-concat rows
__device__ float g_DELTA[(size_t)MROWS*4096];
__device__ __half g_YGh[MROWS*4096], g_YGl[MROWS*4096];          // fp16 planes (out-proj A)
__device__ __half g_Wout[DMODEL*4096];                           // single fp16 plane (out-proj B)
__device__ float g_OUTP[4*MROWS*DMODEL];        // out-proj split-K=4 partials

// ======================= helpers =============================================
__device__ __forceinline__ uint32_t smem_u32(const void* p) {
    uint32_t a;
    asm("{ .reg .u64 t; cvta.to.shared.u64 t, %1; cvt.u32.u64 %0, t; }" : "=r"(a) : "l"(p));
    return a;
}
#define LDM4(r0,r1,r2,r3,addr)                                                      \
    asm volatile("ldmatrix.sync.aligned.m8n8.x4.shared.b16 {%0,%1,%2,%3}, [%4];"    \
        : "=r"(r0),"=r"(r1),"=r"(r2),"=r"(r3) : "r"(addr))
#define MMA_BF16(c,a,b)                                                             \
    asm volatile("mma.sync.aligned.m16n8k16.row.col.f32.bf16.bf16.f32 "             \
        "{%0,%1,%2,%3}, {%4,%5,%6,%7}, {%8,%9}, {%0,%1,%2,%3};"                     \
        : "+f"((c)[0]),"+f"((c)[1]),"+f"((c)[2]),"+f"((c)[3])                       \
        : "r"((a)[0]),"r"((a)[1]),"r"((a)[2]),"r"((a)[3]),"r"((b)[0]),"r"((b)[1]))
#define MMA_F16(c,a,b)                                                              \
    asm volatile("mma.sync.aligned.m16n8k16.row.col.f32.f16.f16.f32 "               \
        "{%0,%1,%2,%3}, {%4,%5,%6,%7}, {%8,%9}, {%0,%1,%2,%3};"                     \
        : "+f"((c)[0]),"+f"((c)[1]),"+f"((c)[2]),"+f"((c)[3])                       \
        : "r"((a)[0]),"r"((a)[1]),"r"((a)[2]),"r"((a)[3]),"r"((b)[0]),"r"((b)[1]))
#define CPA16(dst, src) asm volatile("cp.async.cg.shared.global [%0], [%1], 16;" :: "r"(dst), "l"(src) : "memory")
#define CPCOMMIT()      asm volatile("cp.async.commit_group;" ::: "memory")
#define CPWAIT0()       asm volatile("cp.async.wait_group 0;" ::: "memory")

__device__ __forceinline__ void split1(float v, __nv_bfloat16& h, __nv_bfloat16& l) {
    h = __float2bfloat16(v);
    l = __float2bfloat16(v - __bfloat162float(h));
}
__device__ __forceinline__ void split1h(float v, __half& h, __half& l) {
    h = __float2half(v);
    l = __float2half(v - __half2float(h));
}
__device__ __forceinline__ void store_planes(
    __nv_bfloat16* __restrict__ hi, __nv_bfloat16* __restrict__ lo,
    int i, float4 v)
{
    __nv_bfloat16 h0,h1,h2,h3,l0,l1,l2,l3;
    split1(v.x,h0,l0); split1(v.y,h1,l1); split1(v.z,h2,l2); split1(v.w,h3,l3);
    reinterpret_cast<__nv_bfloat162*>(hi)[2*i]   = __nv_bfloat162(h0,h1);
    reinterpret_cast<__nv_bfloat162*>(hi)[2*i+1] = __nv_bfloat162(h2,h3);
    reinterpret_cast<__nv_bfloat162*>(lo)[2*i]   = __nv_bfloat162(l0,l1);
    reinterpret_cast<__nv_bfloat162*>(lo)[2*i+1] = __nv_bfloat162(l2,l3);
}

// ======================= bf16 3-term GEMM (small stages) =====================
#define BKC 32
#define ASTRIDE 80
#define STG_A_HI 0
#define STG_A_LO 10240
#define STG_B_HI 20480
#define STG_B_LO 30720
#define STG_STRIDE 40960
#define HG_SMEM (2*STG_STRIDE)

template<int EPI>
__global__ __launch_bounds__(256, 2) void hgemm(
    const __nv_bfloat16* __restrict__ Ah, const __nv_bfloat16* __restrict__ Al,
    int lda, int a_off1, int nsplit,
    const __nv_bfloat16* __restrict__ Bh, const __nv_bfloat16* __restrict__ Bl,
    int ldb,
    float* __restrict__ C, int ldc, int K,
    const float* __restrict__ bias0, const float* __restrict__ bias1,
    int kz)
{
    extern __shared__ char sm[];
    const uint32_t smb = smem_u32(sm);
    const int tid = threadIdx.x;
    const int bm = blockIdx.y * 128, bn = blockIdx.x * 128;
    if (kz > 0) {
        Ah += (size_t)blockIdx.z * kz;  Al += (size_t)blockIdx.z * kz;
        Bh += (size_t)blockIdx.z * kz;  Bl += (size_t)blockIdx.z * kz;
        C  += (size_t)blockIdx.z * (size_t)(gridDim.y * 128) * (size_t)ldc;
        K = kz;
    }
    const int aoff = (nsplit && bn >= nsplit) ? a_off1 : 0;

    const int grow = tid >> 1;
    const int seg  = (tid & 1) << 1;
    const char* gAh = (const char*)(Ah + aoff + (size_t)(bm + grow) * lda);
    const char* gAl = (const char*)(Al + aoff + (size_t)(bm + grow) * lda);
    const char* gBh = (const char*)(Bh + (size_t)(bn + grow) * ldb);
    const char* gBl = (const char*)(Bl + (size_t)(bn + grow) * ldb);
    const uint32_t srow = smb + (uint32_t)(grow * ASTRIDE + seg * 16);

    const int wid = tid >> 5, lane = tid & 31;
    const int wm = (wid >> 2) * 64;
    const int wn = (wid & 3) * 32;
    const int tq = lane >> 2, tr = lane & 3;
    const uint32_t aoffm = (uint32_t)((wm + (lane & 15)) * ASTRIDE + ((lane >> 4) << 4));
    const int g = lane >> 3;
    const uint32_t boffm = (uint32_t)((wn + ((g >> 1) << 3) + (lane & 7)) * ASTRIDE + ((g & 1) << 4));

    float acc[4][4][4];
#pragma unroll
    for (int i = 0; i < 4; i++)
#pragma unroll
        for (int j = 0; j < 4; j++)
#pragma unroll
            for (int q = 0; q < 4; q++) acc[i][j][q] = 0.f;

    const int nch = K / BKC;

    auto issue = [&](int s) {
        const uint32_t st = srow + (uint32_t)(s & 1) * STG_STRIDE;
        const int go = s * (BKC * 2) + seg * 16;
        CPA16(st + STG_A_HI,      gAh + go);
        CPA16(st + STG_A_HI + 16, gAh + go + 16);
        CPA16(st + STG_A_LO,      gAl + go);
        CPA16(st + STG_A_LO + 16, gAl + go + 16);
        CPA16(st + STG_B_HI,      gBh + go);
        CPA16(st + STG_B_HI + 16, gBh + go + 16);
        CPA16(st + STG_B_LO,      gBl + go);
        CPA16(st + STG_B_LO + 16, gBl + go + 16);
        CPCOMMIT();
    };

    issue(0);
    for (int s = 0; s < nch; s++) {
        CPWAIT0();
        __syncthreads();
        if (s + 1 < nch) issue(s + 1);
        const uint32_t sa = smb + (uint32_t)(s & 1) * STG_STRIDE;
#pragma unroll
        for (int ph = 0; ph < 2; ph++) {
            const uint32_t ka = sa + ph * 32;
            uint32_t ah[4][4], al[4][4], bh[4][2], bl[4][2];
#pragma unroll
            for (int i = 0; i < 4; i++)
                LDM4(ah[i][0], ah[i][1], ah[i][2], ah[i][3], ka + STG_A_HI + aoffm + i*(16*ASTRIDE));
            LDM4(bh[0][0], bh[0][1], bh[1][0], bh[1][1], ka + STG_B_HI + boffm);
            LDM4(bh[2][0], bh[2][1], bh[3][0], bh[3][1], ka + STG_B_HI + boffm + 16*ASTRIDE);
#pragma unroll
            for (int i = 0; i < 4; i++)
#pragma unroll
                for (int j = 0; j < 4; j++)
                    MMA_BF16(acc[i][j], ah[i], bh[j]);
#pragma unroll
            for (int i = 0; i < 4; i++)
                LDM4(al[i][0], al[i][1], al[i][2], al[i][3], ka + STG_A_LO + aoffm + i*(16*ASTRIDE));
            LDM4(bl[0][0], bl[0][1], bl[1][0], bl[1][1], ka + STG_B_LO + boffm);
            LDM4(bl[2][0], bl[2][1], bl[3][0], bl[3][1], ka + STG_B_LO + boffm + 16*ASTRIDE);
#pragma unroll
            for (int i = 0; i < 4; i++)
#pragma unroll
                for (int j = 0; j < 4; j++)
                    MMA_BF16(acc[i][j], ah[i], bl[j]);
#pragma unroll
            for (int i = 0; i < 4; i++)
#pragma unroll
                for (int j = 0; j < 4; j++)
                    MMA_BF16(acc[i][j], al[i], bh[j]);
        }
    }

    const float* bias = nullptr;
    if (EPI == 1) bias = (nsplit && bn >= nsplit) ? (bias1 - nsplit) : bias0;
#pragma unroll
    for (int i = 0; i < 4; i++) {
        const int row0 = bm + wm + 16*i + tq;
#pragma unroll
        for (int j = 0; j < 4; j++) {
            const int col = bn + wn + 8*j + 2*tr;
            float v0 = acc[i][j][0], v1 = acc[i][j][1];
            float v2 = acc[i][j][2], v3 = acc[i][j][3];
            if (EPI == 1) {
                const float b0v = bias[col], b1v = bias[col+1];
                v0 += b0v; v1 += b1v; v2 += b0v; v3 += b1v;
                v0 = (v0 > 20.f) ? v0 : log1pf(__expf(v0));
                v1 = (v1 > 20.f) ? v1 : log1pf(__expf(v1));
                v2 = (v2 > 20.f) ? v2 : log1pf(__expf(v2));
                v3 = (v3 > 20.f) ? v3 : log1pf(__expf(v3));
            }
            *reinterpret_cast<float2*>(C + (size_t)row0 * ldc + col)       = make_float2(v0, v1);
            *reinterpret_cast<float2*>(C + (size_t)(row0 + 8) * ldc + col) = make_float2(v2, v3);
        }
    }
}

// ======== fp16 GEMM: A = TERMS planes (hi[,lo]), B single plane ==============
#define H2_A_HI 0
#define H2_A_LO 10240
#define H2_B    20480
#define H2_STRIDE 30720
#define H2_SMEM (2*H2_STRIDE)

template<int TERMS>
__global__ __launch_bounds__(256, 2) void hgemm2(
    const __half* __restrict__ Ah, const __half* __restrict__ Al, int lda,
    const __half* __restrict__ B, int ldb,
    float* __restrict__ C, int ldc, int K, int kz)
{
    extern __shared__ char sm[];
    const uint32_t smb = smem_u32(sm);
    const int tid = threadIdx.x;
    const int bm = blockIdx.y * 128, bn = blockIdx.x * 128;
    if (kz > 0) {
        Ah += (size_t)blockIdx.z * kz;  Al += (size_t)blockIdx.z * kz;
        B  += (size_t)blockIdx.z * kz;
        C  += (size_t)blockIdx.z * (size_t)(gridDim.y * 128) * (size_t)ldc;
        K = kz;
    }

    const int grow = tid >> 1;
    const int seg  = (tid & 1) << 1;
    const char* gAh = (const char*)(Ah + (size_t)(bm + grow) * lda);
    const char* gAl = (const char*)(Al + (size_t)(bm + grow) * lda);
    const char* gB  = (const char*)(B  + (size_t)(bn + grow) * ldb);
    const uint32_t srow = smb + (uint32_t)(grow * ASTRIDE + seg * 16);

    const int wid = tid >> 5, lane = tid & 31;
    const int wm = (wid >> 2) * 64;
    const int wn = (wid & 3) * 32;
    const int tq = lane >> 2, tr = lane & 3;
    const uint32_t aoffm = (uint32_t)((wm + (lane & 15)) * ASTRIDE + ((lane >> 4) << 4));
    const int g = lane >> 3;
    const uint32_t boffm = (uint32_t)((wn + ((g >> 1) << 3) + (lane & 7)) * ASTRIDE + ((g & 1) << 4));

    float acc[4][4][4];
#pragma unroll
    for (int i = 0; i < 4; i++)
#pragma unroll
        for (int j = 0; j < 4; j++)
#pragma unroll
            for (int q = 0; q < 4; q++) acc[i][j][q] = 0.f;

    const int nch = K / BKC;

    auto issue = [&](int s) {
        const uint32_t st = srow + (uint32_t)(s & 1) * H2_STRIDE;
        const int go = s * (BKC * 2) + seg * 16;
        CPA16(st + H2_A_HI,      gAh + go);
        CPA16(st + H2_A_HI + 16, gAh + go + 16);
        if (TERMS == 2) {
            CPA16(st + H2_A_LO,      gAl + go);
            CPA16(st + H2_A_LO + 16, gAl + go + 16);
        }
        CPA16(st + H2_B,         gB + go);
        CPA16(st + H2_B + 16,    gB + go + 16);
        CPCOMMIT();
    };

    issue(0);
    for (int s = 0; s < nch; s++) {
        CPWAIT0();
        __syncthreads();
        if (s + 1 < nch) issue(s + 1);
        const uint32_t sa = smb + (uint32_t)(s & 1) * H2_STRIDE;
#pragma unroll
        for (int ph = 0; ph < 2; ph++) {
            const uint32_t ka = sa + ph * 32;
            uint32_t ah[4][4], al[4][4], bb[4][2];
#pragma unroll
            for (int i = 0; i < 4; i++)
                LDM4(ah[i][0], ah[i][1], ah[i][2], ah[i][3], ka + H2_A_HI + aoffm + i*(16*ASTRIDE));
            LDM4(bb[0][0], bb[0][1], bb[1][0], bb[1][1], ka + H2_B + boffm);
            LDM4(bb[2][0], bb[2][1], bb[3][0], bb[3][1], ka + H2_B + boffm + 16*ASTRIDE);
#pragma unroll
            for (int i = 0; i < 4; i++)
#pragma unroll
                for (int j = 0; j < 4; j++)
                    MMA_F16(acc[i][j], ah[i], bb[j]);
            if (TERMS == 2) {
#pragma unroll
                for (int i = 0; i < 4; i++)
                    LDM4(al[i][0], al[i][1], al[i][2], al[i][3], ka + H2_A_LO + aoffm + i*(16*ASTRIDE));
#pragma unroll
                for (int i = 0; i < 4; i++)
#pragma unroll
                    for (int j = 0; j < 4; j++)
                        MMA_F16(acc[i][j], al[i], bb[j]);
            }
        }
    }

#pragma unroll
    for (int i = 0; i < 4; i++) {
        const int row0 = bm + wm + 16*i + tq;
#pragma unroll
        for (int j = 0; j < 4; j++) {
            const int col = bn + wn + 8*j + 2*tr;
            *reinterpret_cast<float2*>(C + (size_t)row0 * ldc + col)
                = make_float2(acc[i][j][0], acc[i][j][1]);
            *reinterpret_cast<float2*>(C + (size_t)(row0 + 8) * ldc + col)
                = make_float2(acc[i][j][2], acc[i][j][3]);
        }
    }
}

// ======================= merged convert kernels ===============================
#define N4_X    (MROWS*DMODEL/4)
#define N4_INW  (4096*DMODEL/4)
#define N4_DTW  (2048*DTR/4)
#define N4_XP   (256*DIN/4)
#define N4_OUT  (DMODEL*4096/4)

__global__ __launch_bounds__(256) void cvt_x_kernel(const float* __restrict__ x)
{
    const int i = blockIdx.x * 256 + threadIdx.x;
    const float4 v = reinterpret_cast<const float4*>(x)[i];
    reinterpret_cast<__half2*>(g_Xh)[2*i]   = __floats2half2_rn(v.x, v.y);
    reinterpret_cast<__half2*>(g_Xh)[2*i+1] = __floats2half2_rn(v.z, v.w);
}

__global__ __launch_bounds__(256) void cvt_inw_kernel(
    const float* __restrict__ f, const float* __restrict__ b)
{
    const int i = blockIdx.x * 256 + threadIdx.x;
    const float4 v = (i < N4_INW)
        ? reinterpret_cast<const float4*>(f)[i]
        : reinterpret_cast<const float4*>(b)[i - N4_INW];
    reinterpret_cast<__half2*>(g_Win)[2*i]   = __floats2half2_rn(v.x, v.y);
    reinterpret_cast<__half2*>(g_Win)[2*i+1] = __floats2half2_rn(v.z, v.w);
}

__global__ __launch_bounds__(256) void cvt_rest_kernel(
    const float* __restrict__ dtW_f, const float* __restrict__ dtW_b,
    const float* __restrict__ xpW_f, const float* __restrict__ xpW_b,
    const float* __restrict__ outW_f, const float* __restrict__ outW_b)
{
    int i = blockIdx.x * 256 + threadIdx.x;
    if (i < 2*N4_DTW) {
        const float4 v = (i < N4_DTW)
            ? reinterpret_cast<const float4*>(dtW_f)[i]
            : reinterpret_cast<const float4*>(dtW_b)[i - N4_DTW];
        store_planes(g_dtWh, g_dtWl, i, v);
        return;
    }
    i -= 2*N4_DTW;
    if (i < N4_XP) {
        const int idx = i * 4;
        const int r = idx >> 11, c = idx & 2047;
        float4 v = make_float4(0.f,0.f,0.f,0.f);
        if (r < 96)                   v = *reinterpret_cast<const float4*>(xpW_f + r*2048 + c);
        else if (r >= 128 && r < 224) v = *reinterpret_cast<const float4*>(xpW_b + (r-128)*2048 + c);
        store_planes(g_Xph, g_Xpl, i, v);
        return;
    }
    i -= N4_XP;
    {   // outW K-concat -> single fp16 plane
        const int idx = i * 4;
        const int r = idx >> 12, c = idx & 4095;
        const float4 v = (c < 2048)
            ? *reinterpret_cast<const float4*>(outW_f + (size_t)r*2048 + c)
            : *reinterpret_cast<const float4*>(outW_b + (size_t)r*2048 + (c - 2048));
        reinterpret_cast<__half2*>(g_Wout)[2*i]   = __floats2half2_rn(v.x, v.y);
        reinterpret_cast<__half2*>(g_Wout)[2*i+1] = __floats2half2_rn(v.z, v.w);
    }
}

__global__ __launch_bounds__(256) void reduce_out_kernel(float* __restrict__ out)
{
    const int i = blockIdx.x * 256 + threadIdx.x;
    float4 s = reinterpret_cast<const float4*>(g_OUTP)[i];
#pragma unroll
    for (int k = 1; k < 4; k++) {
        const float4 p = reinterpret_cast<const float4*>(g_OUTP + (size_t)k*MROWS*DMODEL)[i];
        s.x += p.x; s.y += p.y; s.z += p.z; s.w += p.w;
    }
    reinterpret_cast<float4*>(out)[i] = make_float4(0.5f*s.x, 0.5f*s.y, 0.5f*s.z, 0.5f*s.w);
}

// ------------- depthwise conv + SiLU; writes fp32 U and bf16 planes ----------
__global__ __launch_bounds__(256) void conv_silu_kernel(
    const float* __restrict__ convW_f, const float* __restrict__ convB_f,
    const float* __restrict__ convW_b, const float* __restrict__ convB_b)
{
    const int i = blockIdx.x * 256 + threadIdx.x;
    const int c = i & 4095;
    const int row = i >> 12;
    const int l = row & (LSEQ - 1);
    const int b = row >> 10;
    const int dir = c >> 11;
    const int d = c & (DIN - 1);
    const float* w = (dir ? convW_b : convW_f) + d*4;
    float acc = (dir ? convB_b : convB_f)[d];
    const float* xi = g_XZ + dir*4096 + d;
    if (dir == 0) {
#pragma unroll
        for (int k = 0; k < 4; k++) {
            int ls = l - 3 + k;
            if (ls >= 0) acc = fmaf(w[k], xi[(size_t)(b*LSEQ + ls)*8192], acc);
        }
    } else {
#pragma unroll
        for (int k = 0; k < 4; k++) {
            int ls = l + 3 - k;
            if (ls < LSEQ) acc = fmaf(w[k], xi[(size_t)(b*LSEQ + ls)*8192], acc);
        }
    }
    const float sig = 1.f / (1.f + __expf(-acc));
    const float u = acc * sig;
    const size_t o = (size_t)row*4096 + c;
    g_U[o] = u;
    __nv_bfloat16 h, lo2; split1(u, h, lo2);
    g_Uh[o] = h; g_Ul[o] = lo2;
}

// ------------------------- split-K reduce + plane split ----------------------
__global__ __launch_bounds__(256) void reduce_xdbl_kernel()
{
    const int i = blockIdx.x * 256 + threadIdx.x;
    float s = 0.f;
#pragma unroll
    for (int k = 0; k < 8; k++) s += g_XDBLP[(size_t)k*MROWS*256 + i];
    g_XDBL[i] = s;
    __nv_bfloat16 h, l; split1(s, h, l);
    g_XDh[i] = h; g_XDl[i] = l;
}

// ------------- selective scan: 2 states/thread, 4 d/warp, 3-shfl reduce ------
__global__ __launch_bounds__(256) void scan_kernel(
    const float* __restrict__ Alog_f, const float* __restrict__ Alog_b,
    const float* __restrict__ Dp_f,  const float* __restrict__ Dp_b)
{
    const int dir = blockIdx.z;
    const int b   = blockIdx.y;
    const int d0  = blockIdx.x * 32;
    const int t    = threadIdx.x;
    const int lane = t & 31;
    const int w    = t >> 5;
    const int dlw  = (w << 2) + (lane >> 3);
    const int np   = lane & 7;
    const int d    = d0 + dlw;

    const float* Alog = dir ? Alog_b : Alog_f;
    const float Ac0 = -__expf(Alog[d*NST + np]);
    const float Ac1 = -__expf(Alog[d*NST + np + 8]);
    const float DpE = (dir ? Dp_b : Dp_f)[d0 + (t & 31)];

    __shared__ float2 sDdw[32][32];
    __shared__ float2 sUZ [32][32];
    __shared__ float4 sBC [32][8];
    __shared__ float  sY  [32][32];

    const int sll = t >> 5;
    const int sdq = t & 31;
    const int bll = t >> 3, bj = t & 7;

    float rgD[4], rgU[4], rgZ[4], rgB[4];
    auto prefetch = [&](int lb) {
#pragma unroll
        for (int e = 0; e < 4; e++) {
            const int row = b*LSEQ + lb + sll + e*8;
            rgD[e] = g_DELTA[(size_t)row*4096 + dir*2048 + d0 + sdq];
            rgU[e] = g_U[(size_t)row*4096 + dir*2048 + d0 + sdq];
            rgZ[e] = g_XZ[(size_t)row*8192 + dir*4096 + 2048 + d0 + sdq];
        }
        const int rowb = b*LSEQ + lb + bll;
        rgB[0] = g_XDBL[(size_t)rowb*256 + dir*128 + 64 + bj];
        rgB[1] = g_XDBL[(size_t)rowb*256 + dir*128 + 80 + bj];
        rgB[2] = g_XDBL[(size_t)rowb*256 + dir*128 + 64 + bj + 8];
        rgB[3] = g_XDBL[(size_t)rowb*256 + dir*128 + 80 + bj + 8];
    };

    prefetch((dir == 0) ? 0 : (LSEQ - 32));

    float h0 = 0.f, h1 = 0.f;
    const int NCH = LSEQ / 32;
    for (int c = 0; c < NCH; c++) {
        __syncthreads();
#pragma unroll
        for (int e = 0; e < 4; e++) {
            sDdw[sll + e*8][sdq] = make_float2(rgD[e], rgD[e]*rgU[e]);
            sUZ [sll + e*8][sdq] = make_float2(rgU[e], rgZ[e]);
        }
        sBC[bll][bj] = make_float4(rgB[0], rgB[1], rgB[2], rgB[3]);
        __syncthreads();
        if (c + 1 < NCH)
            prefetch((dir == 0) ? (c+1)*32 : (LSEQ - (c+2)*32));
        const int lb = (dir == 0) ? c*32 : (LSEQ - (c+1)*32);
#pragma unroll 4
        for (int s = 0; s < 32; s++) {
            const int ll = (dir == 0) ? s : (31 - s);
            const float2 ddw = sDdw[ll][dlw];
            const float4 bc  = sBC[ll][np];
            const float dA0 = __expf(ddw.x * Ac0);
            const float dA1 = __expf(ddw.x * Ac1);
            h0 = fmaf(h0, dA0, ddw.y * bc.x);
            h1 = fmaf(h1, dA1, ddw.y * bc.z);
            float py = fmaf(h1, bc.w, h0 * bc.y);
            py += __shfl_xor_sync(0xffffffffu, py, 4);
            py += __shfl_xor_sync(0xffffffffu, py, 2);
            py += __shfl_xor_sync(0xffffffffu, py, 1);
            if (np == 0) sY[ll][dlw] = py;
        }
        __syncthreads();
#pragma unroll
        for (int e = 0; e < 4; e++) {
            const int ll = sll + e*8;
            const float2 uz = sUZ[ll][sdq];
            const float y = fmaf(uz.x, DpE, sY[ll][sdq]);
            const float sig = 1.f / (1.f + __expf(-uz.y));
            const float yg = y * (uz.y * sig);
            const size_t o = (size_t)(b*LSEQ + lb + ll)*4096 + dir*2048 + d0 + sdq;
            __half hh, lo2; split1h(yg, hh, lo2);
            g_YGh[o] = hh; g_YGl[o] = lo2;
        }
    }
}

// ------------------------------------ launch ---------------------------------
extern "C" void kernel_launch(void* const* d_in, const int* in_sizes, int n_in,
                              void* d_out, int out_size)
{
    const float* x      = (const float*)d_in[0];
    const float* inW_f  = (const float*)d_in[1];
    const float* convW_f= (const float*)d_in[2];
    const float* convB_f= (const float*)d_in[3];
    const float* xpW_f  = (const float*)d_in[4];
    const float* dtW_f  = (const float*)d_in[5];
    const float* dtB_f  = (const float*)d_in[6];
    const float* Alog_f = (const float*)d_in[7];
    const float* Dp_f   = (const float*)d_in[8];
    const float* outW_f = (const float*)d_in[9];
    const float* inW_b  = (const float*)d_in[10];
    const float* convW_b= (const float*)d_in[11];
    const float* convB_b= (const float*)d_in[12];
    const float* xpW_b  = (const float*)d_in[13];
    const float* dtW_b  = (const float*)d_in[14];
    const float* dtB_b  = (const float*)d_in[15];
    const float* Alog_b = (const float*)d_in[16];
    const float* Dp_b   = (const float*)d_in[17];
    const float* outW_b = (const float*)d_in[18];
    float* out = (float*)d_out;

    float *XZ, *XDBLP, *DELTA, *OUTP;
    __nv_bfloat16 *Uh, *Ul, *Xph, *Xpl, *XDh, *XDl, *dtWh, *dtWl;
    __half *Xh, *Win, *YGh, *YGl, *Wout;
    cudaGetSymbolAddress((void**)&XZ,    g_XZ);
    cudaGetSymbolAddress((void**)&XDBLP, g_XDBLP);
    cudaGetSymbolAddress((void**)&DELTA, g_DELTA);
    cudaGetSymbolAddress((void**)&OUTP,  g_OUTP);
    cudaGetSymbolAddress((void**)&Xh,    g_Xh);
    cudaGetSymbolAddress((void**)&Win,   g_Win);
    cudaGetSymbolAddress((void**)&Uh,    g_Uh);
    cudaGetSymbolAddress((void**)&Ul,    g_Ul);
    cudaGetSymbolAddress((void**)&Xph,   g_Xph);
    cudaGetSymbolAddress((void**)&Xpl,   g_Xpl);
    cudaGetSymbolAddress((void**)&XDh,   g_XDh);
    cudaGetSymbolAddress((void**)&XDl,   g_XDl);
    cudaGetSymbolAddress((void**)&dtWh,  g_dtWh);
    cudaGetSymbolAddress((void**)&dtWl,  g_dtWl);
    cudaGetSymbolAddress((void**)&YGh,   g_YGh);
    cudaGetSymbolAddress((void**)&YGl,   g_YGl);
    cudaGetSymbolAddress((void**)&Wout,  g_Wout);

    cudaFuncSetAttribute(hgemm<0>,  cudaFuncAttributeMaxDynamicSharedMemorySize, HG_SMEM);
    cudaFuncSetAttribute(hgemm<1>,  cudaFuncAttributeMaxDynamicSharedMemorySize, HG_SMEM);
    cudaFuncSetAttribute(hgemm2<1>, cudaFuncAttributeMaxDynamicSharedMemorySize, H2_SMEM);
    cudaFuncSetAttribute(hgemm2<2>, cudaFuncAttributeMaxDynamicSharedMemorySize, H2_SMEM);

    // 0-2) converts (in-proj GEMM stays at launch index 3 = ncu slot)
    cvt_x_kernel  <<<N4_X/256, 256>>>(x);
    cvt_inw_kernel<<<2*N4_INW/256, 256>>>(inW_f, inW_b);
    cvt_rest_kernel<<<(2*N4_DTW + N4_XP + N4_OUT)/256, 256>>>(
        dtW_f, dtW_b, xpW_f, xpW_b, outW_f, outW_b);

    // 3) input projection (fp16 single-term): [2048,8192] = X * Win^T
    hgemm2<1><<<dim3(64,16,1), 256, H2_SMEM>>>(
        Xh, Xh, DMODEL, Win, DMODEL, XZ, 8192, DMODEL, 0);

    // 4) depthwise conv + SiLU (emits U fp32 + bf16 planes)
    conv_silu_kernel<<<(MROWS*4096)/256, 256>>>(convW_f, convB_f, convW_b, convB_b);

    // 5) x_dbl (bf16 3-term): split-K=8
    hgemm<0><<<dim3(2,16,8), 256, HG_SMEM>>>(
        Uh, Ul, 4096, 2048, 128, Xph, Xpl, DIN,
        XDBLP, 256, DIN, nullptr, nullptr, 256);
    reduce_xdbl_kernel<<<(MROWS*256)/256, 256>>>();

    // 6) delta = softplus(dt @ dtWcat^T + dtB) (bf16 3-term)
    hgemm<1><<<dim3(32,16,1), 256, HG_SMEM>>>(
        XDh, XDl, 256, 128, 2048, dtWh, dtWl, DTR,
        DELTA, 4096, DTR, dtB_f, dtB_b, 0);

    // 7) selective scan + gating (emits YG fp16 planes)
    scan_kernel<<<dim3(64,2,2), 256>>>(Alog_f, Alog_b, Dp_f, Dp_b);

    // 8) out-proj (fp16 2-term) split-K=4, then 0.5*sum
    hgemm2<2><<<dim3(8,16,4), 256, H2_SMEM>>>(
        YGh, YGl, 4096, Wout, 4096, OUTP, DMODEL, 4096, 1024);
    reduce_out_kernel<<<(MROWS*DMODEL/4)/256, 256>>>(out);
}

// round 13
// speedup vs baseline: 2.3186x; 1.0783x over previous
#include <cuda_runtime.h>
#include <cuda_bf16.h>
#include <cuda_fp16.h>
#include <math.h>
#include <cstdint>

#define B_SZ   2
#define LSEQ   1024
#define DMODEL 1024
#define DIN    2048
#define NST    16
#define DTR    64
#define MROWS  (B_SZ*LSEQ)   /* 2048 */

// ---------------- scratch (device globals; no allocation allowed) ------------
__device__ float g_XZ[MROWS*8192];              // [m][dir*4096 + (xi | z)]
__device__ float g_U [MROWS*4096];              // fp32 for scan
__device__ __nv_bfloat16 g_Uh[MROWS*4096],  g_Ul[MROWS*4096];
__device__ __half g_Xh[MROWS*DMODEL];                            // single fp16 plane (in-proj A)
__device__ __half g_Win[8192*DMODEL];                            // single fp16 plane (in-proj B)
__device__ __nv_bfloat16 g_Xph[256*DIN],    g_Xpl[256*DIN];      // padded xpW
__device__ float g_XDBLP[8*MROWS*256];
__device__ float g_XDBL[MROWS*256];
__device__ __nv_bfloat16 g_XDh[MROWS*256],  g_XDl[MROWS*256];
__device__ __nv_bfloat16 g_dtWh[4096*DTR],  g_dtWl[4096*DTR];    // dir-concat rows
__device__ float g_DELTA[(size_t)MROWS*4096];
__device__ __half g_YGh[MROWS*4096];                             // single fp16 plane (out-proj A)
__device__ __half g_Wout[DMODEL*4096];                           // single fp16 plane (out-proj B)
__device__ float g_OUTP[4*MROWS*DMODEL];        // out-proj split-K=4 partials

// ======================= helpers =============================================
__device__ __forceinline__ uint32_t smem_u32(const void* p) {
    uint32_t a;
    asm("{ .reg .u64 t; cvta.to.shared.u64 t, %1; cvt.u32.u64 %0, t; }" : "=r"(a) : "l"(p));
    return a;
}
#define LDM4(r0,r1,r2,r3,addr)                                                      \
    asm volatile("ldmatrix.sync.aligned.m8n8.x4.shared.b16 {%0,%1,%2,%3}, [%4];"    \
        : "=r"(r0),"=r"(r1),"=r"(r2),"=r"(r3) : "r"(addr))
#define MMA_BF16(c,a,b)                                                             \
    asm volatile("mma.sync.aligned.m16n8k16.row.col.f32.bf16.bf16.f32 "             \
        "{%0,%1,%2,%3}, {%4,%5,%6,%7}, {%8,%9}, {%0,%1,%2,%3};"                     \
        : "+f"((c)[0]),"+f"((c)[1]),"+f"((c)[2]),"+f"((c)[3])                       \
        : "r"((a)[0]),"r"((a)[1]),"r"((a)[2]),"r"((a)[3]),"r"((b)[0]),"r"((b)[1]))
#define MMA_F16(c,a,b)                                                              \
    asm volatile("mma.sync.aligned.m16n8k16.row.col.f32.f16.f16.f32 "               \
        "{%0,%1,%2,%3}, {%4,%5,%6,%7}, {%8,%9}, {%0,%1,%2,%3};"                     \
        : "+f"((c)[0]),"+f"((c)[1]),"+f"((c)[2]),"+f"((c)[3])                       \
        : "r"((a)[0]),"r"((a)[1]),"r"((a)[2]),"r"((a)[3]),"r"((b)[0]),"r"((b)[1]))
#define CPA16(dst, src) asm volatile("cp.async.cg.shared.global [%0], [%1], 16;" :: "r"(dst), "l"(src) : "memory")
#define CPCOMMIT()      asm volatile("cp.async.commit_group;" ::: "memory")
#define CPWAIT0()       asm volatile("cp.async.wait_group 0;" ::: "memory")

__device__ __forceinline__ void split1(float v, __nv_bfloat16& h, __nv_bfloat16& l) {
    h = __float2bfloat16(v);
    l = __float2bfloat16(v - __bfloat162float(h));
}
__device__ __forceinline__ void store_planes(
    __nv_bfloat16* __restrict__ hi, __nv_bfloat16* __restrict__ lo,
    int i, float4 v)
{
    __nv_bfloat16 h0,h1,h2,h3,l0,l1,l2,l3;
    split1(v.x,h0,l0); split1(v.y,h1,l1); split1(v.z,h2,l2); split1(v.w,h3,l3);
    reinterpret_cast<__nv_bfloat162*>(hi)[2*i]   = __nv_bfloat162(h0,h1);
    reinterpret_cast<__nv_bfloat162*>(hi)[2*i+1] = __nv_bfloat162(h2,h3);
    reinterpret_cast<__nv_bfloat162*>(lo)[2*i]   = __nv_bfloat162(l0,l1);
    reinterpret_cast<__nv_bfloat162*>(lo)[2*i+1] = __nv_bfloat162(l2,l3);
}

// ======================= bf16 3-term GEMM (small stages) =====================
#define BKC 32
#define ASTRIDE 80
#define STG_A_HI 0
#define STG_A_LO 10240
#define STG_B_HI 20480
#define STG_B_LO 30720
#define STG_STRIDE 40960
#define HG_SMEM (2*STG_STRIDE)

template<int EPI>
__global__ __launch_bounds__(256, 2) void hgemm(
    const __nv_bfloat16* __restrict__ Ah, const __nv_bfloat16* __restrict__ Al,
    int lda, int a_off1, int nsplit,
    const __nv_bfloat16* __restrict__ Bh, const __nv_bfloat16* __restrict__ Bl,
    int ldb,
    float* __restrict__ C, int ldc, int K,
    const float* __restrict__ bias0, const float* __restrict__ bias1,
    int kz)
{
    extern __shared__ char sm[];
    const uint32_t smb = smem_u32(sm);
    const int tid = threadIdx.x;
    const int bm = blockIdx.y * 128, bn = blockIdx.x * 128;
    if (kz > 0) {
        Ah += (size_t)blockIdx.z * kz;  Al += (size_t)blockIdx.z * kz;
        Bh += (size_t)blockIdx.z * kz;  Bl += (size_t)blockIdx.z * kz;
        C  += (size_t)blockIdx.z * (size_t)(gridDim.y * 128) * (size_t)ldc;
        K = kz;
    }
    const int aoff = (nsplit && bn >= nsplit) ? a_off1 : 0;

    const int grow = tid >> 1;
    const int seg  = (tid & 1) << 1;
    const char* gAh = (const char*)(Ah + aoff + (size_t)(bm + grow) * lda);
    const char* gAl = (const char*)(Al + aoff + (size_t)(bm + grow) * lda);
    const char* gBh = (const char*)(Bh + (size_t)(bn + grow) * ldb);
    const char* gBl = (const char*)(Bl + (size_t)(bn + grow) * ldb);
    const uint32_t srow = smb + (uint32_t)(grow * ASTRIDE + seg * 16);

    const int wid = tid >> 5, lane = tid & 31;
    const int wm = (wid >> 2) * 64;
    const int wn = (wid & 3) * 32;
    const int tq = lane >> 2, tr = lane & 3;
    const uint32_t aoffm = (uint32_t)((wm + (lane & 15)) * ASTRIDE + ((lane >> 4) << 4));
    const int g = lane >> 3;
    const uint32_t boffm = (uint32_t)((wn + ((g >> 1) << 3) + (lane & 7)) * ASTRIDE + ((g & 1) << 4));

    float acc[4][4][4];
#pragma unroll
    for (int i = 0; i < 4; i++)
#pragma unroll
        for (int j = 0; j < 4; j++)
#pragma unroll
            for (int q = 0; q < 4; q++) acc[i][j][q] = 0.f;

    const int nch = K / BKC;

    auto issue = [&](int s) {
        const uint32_t st = srow + (uint32_t)(s & 1) * STG_STRIDE;
        const int go = s * (BKC * 2) + seg * 16;
        CPA16(st + STG_A_HI,      gAh + go);
        CPA16(st + STG_A_HI + 16, gAh + go + 16);
        CPA16(st + STG_A_LO,      gAl + go);
        CPA16(st + STG_A_LO + 16, gAl + go + 16);
        CPA16(st + STG_B_HI,      gBh + go);
        CPA16(st + STG_B_HI + 16, gBh + go + 16);
        CPA16(st + STG_B_LO,      gBl + go);
        CPA16(st + STG_B_LO + 16, gBl + go + 16);
        CPCOMMIT();
    };

    issue(0);
    for (int s = 0; s < nch; s++) {
        CPWAIT0();
        __syncthreads();
        if (s + 1 < nch) issue(s + 1);
        const uint32_t sa = smb + (uint32_t)(s & 1) * STG_STRIDE;
#pragma unroll
        for (int ph = 0; ph < 2; ph++) {
            const uint32_t ka = sa + ph * 32;
            uint32_t ah[4][4], al[4][4], bh[4][2], bl[4][2];
#pragma unroll
            for (int i = 0; i < 4; i++)
                LDM4(ah[i][0], ah[i][1], ah[i][2], ah[i][3], ka + STG_A_HI + aoffm + i*(16*ASTRIDE));
            LDM4(bh[0][0], bh[0][1], bh[1][0], bh[1][1], ka + STG_B_HI + boffm);
            LDM4(bh[2][0], bh[2][1], bh[3][0], bh[3][1], ka + STG_B_HI + boffm + 16*ASTRIDE);
#pragma unroll
            for (int i = 0; i < 4; i++)
#pragma unroll
                for (int j = 0; j < 4; j++)
                    MMA_BF16(acc[i][j], ah[i], bh[j]);
#pragma unroll
            for (int i = 0; i < 4; i++)
                LDM4(al[i][0], al[i][1], al[i][2], al[i][3], ka + STG_A_LO + aoffm + i*(16*ASTRIDE));
            LDM4(bl[0][0], bl[0][1], bl[1][0], bl[1][1], ka + STG_B_LO + boffm);
            LDM4(bl[2][0], bl[2][1], bl[3][0], bl[3][1], ka + STG_B_LO + boffm + 16*ASTRIDE);
#pragma unroll
            for (int i = 0; i < 4; i++)
#pragma unroll
                for (int j = 0; j < 4; j++)
                    MMA_BF16(acc[i][j], ah[i], bl[j]);
#pragma unroll
            for (int i = 0; i < 4; i++)
#pragma unroll
                for (int j = 0; j < 4; j++)
                    MMA_BF16(acc[i][j], al[i], bh[j]);
        }
    }

    const float* bias = nullptr;
    if (EPI == 1) bias = (nsplit && bn >= nsplit) ? (bias1 - nsplit) : bias0;
#pragma unroll
    for (int i = 0; i < 4; i++) {
        const int row0 = bm + wm + 16*i + tq;
#pragma unroll
        for (int j = 0; j < 4; j++) {
            const int col = bn + wn + 8*j + 2*tr;
            float v0 = acc[i][j][0], v1 = acc[i][j][1];
            float v2 = acc[i][j][2], v3 = acc[i][j][3];
            if (EPI == 1) {
                const float b0v = bias[col], b1v = bias[col+1];
                v0 += b0v; v1 += b1v; v2 += b0v; v3 += b1v;
                v0 = (v0 > 20.f) ? v0 : log1pf(__expf(v0));
                v1 = (v1 > 20.f) ? v1 : log1pf(__expf(v1));
                v2 = (v2 > 20.f) ? v2 : log1pf(__expf(v2));
                v3 = (v3 > 20.f) ? v3 : log1pf(__expf(v3));
            }
            *reinterpret_cast<float2*>(C + (size_t)row0 * ldc + col)       = make_float2(v0, v1);
            *reinterpret_cast<float2*>(C + (size_t)(row0 + 8) * ldc + col) = make_float2(v2, v3);
        }
    }
}

// ======== fp16 GEMM: A = TERMS planes (hi[,lo]), B single plane ==============
#define H2_A_HI 0
#define H2_A_LO 10240
#define H2_B    20480
#define H2_STRIDE 30720
#define H2_SMEM (2*H2_STRIDE)

template<int TERMS>
__global__ __launch_bounds__(256, 2) void hgemm2(
    const __half* __restrict__ Ah, const __half* __restrict__ Al, int lda,
    const __half* __restrict__ B, int ldb,
    float* __restrict__ C, int ldc, int K, int kz)
{
    extern __shared__ char sm[];
    const uint32_t smb = smem_u32(sm);
    const int tid = threadIdx.x;
    const int bm = blockIdx.y * 128, bn = blockIdx.x * 128;
    if (kz > 0) {
        Ah += (size_t)blockIdx.z * kz;  Al += (size_t)blockIdx.z * kz;
        B  += (size_t)blockIdx.z * kz;
        C  += (size_t)blockIdx.z * (size_t)(gridDim.y * 128) * (size_t)ldc;
        K = kz;
    }

    const int grow = tid >> 1;
    const int seg  = (tid & 1) << 1;
    const char* gAh = (const char*)(Ah + (size_t)(bm + grow) * lda);
    const char* gAl = (const char*)(Al + (size_t)(bm + grow) * lda);
    const char* gB  = (const char*)(B  + (size_t)(bn + grow) * ldb);
    const uint32_t srow = smb + (uint32_t)(grow * ASTRIDE + seg * 16);

    const int wid = tid >> 5, lane = tid & 31;
    const int wm = (wid >> 2) * 64;
    const int wn = (wid & 3) * 32;
    const int tq = lane >> 2, tr = lane & 3;
    const uint32_t aoffm = (uint32_t)((wm + (lane & 15)) * ASTRIDE + ((lane >> 4) << 4));
    const int g = lane >> 3;
    const uint32_t boffm = (uint32_t)((wn + ((g >> 1) << 3) + (lane & 7)) * ASTRIDE + ((g & 1) << 4));

    float acc[4][4][4];
#pragma unroll
    for (int i = 0; i < 4; i++)
#pragma unroll
        for (int j = 0; j < 4; j++)
#pragma unroll
            for (int q = 0; q < 4; q++) acc[i][j][q] = 0.f;

    const int nch = K / BKC;

    auto issue = [&](int s) {
        const uint32_t st = srow + (uint32_t)(s & 1) * H2_STRIDE;
        const int go = s * (BKC * 2) + seg * 16;
        CPA16(st + H2_A_HI,      gAh + go);
        CPA16(st + H2_A_HI + 16, gAh + go + 16);
        if (TERMS == 2) {
            CPA16(st + H2_A_LO,      gAl + go);
            CPA16(st + H2_A_LO + 16, gAl + go + 16);
        }
        CPA16(st + H2_B,         gB + go);
        CPA16(st + H2_B + 16,    gB + go + 16);
        CPCOMMIT();
    };

    issue(0);
    for (int s = 0; s < nch; s++) {
        CPWAIT0();
        __syncthreads();
        if (s + 1 < nch) issue(s + 1);
        const uint32_t sa = smb + (uint32_t)(s & 1) * H2_STRIDE;
#pragma unroll
        for (int ph = 0; ph < 2; ph++) {
            const uint32_t ka = sa + ph * 32;
            uint32_t ah[4][4], al[4][4], bb[4][2];
#pragma unroll
            for (int i = 0; i < 4; i++)
                LDM4(ah[i][0], ah[i][1], ah[i][2], ah[i][3], ka + H2_A_HI + aoffm + i*(16*ASTRIDE));
            LDM4(bb[0][0], bb[0][1], bb[1][0], bb[1][1], ka + H2_B + boffm);
            LDM4(bb[2][0], bb[2][1], bb[3][0], bb[3][1], ka + H2_B + boffm + 16*ASTRIDE);
#pragma unroll
            for (int i = 0; i < 4; i++)
#pragma unroll
                for (int j = 0; j < 4; j++)
                    MMA_F16(acc[i][j], ah[i], bb[j]);
            if (TERMS == 2) {
#pragma unroll
                for (int i = 0; i < 4; i++)
                    LDM4(al[i][0], al[i][1], al[i][2], al[i][3], ka + H2_A_LO + aoffm + i*(16*ASTRIDE));
#pragma unroll
                for (int i = 0; i < 4; i++)
#pragma unroll
                    for (int j = 0; j < 4; j++)
                        MMA_F16(acc[i][j], al[i], bb[j]);
            }
        }
    }

#pragma unroll
    for (int i = 0; i < 4; i++) {
        const int row0 = bm + wm + 16*i + tq;
#pragma unroll
        for (int j = 0; j < 4; j++) {
            const int col = bn + wn + 8*j + 2*tr;
            *reinterpret_cast<float2*>(C + (size_t)row0 * ldc + col)
                = make_float2(acc[i][j][0], acc[i][j][1]);
            *reinterpret_cast<float2*>(C + (size_t)(row0 + 8) * ldc + col)
                = make_float2(acc[i][j][2], acc[i][j][3]);
        }
    }
}

// ======================= merged convert kernels ===============================
#define N4_X    (MROWS*DMODEL/4)
#define N4_INW  (4096*DMODEL/4)
#define N4_DTW  (2048*DTR/4)
#define N4_XP   (256*DIN/4)
#define N4_OUT  (DMODEL*4096/4)

__global__ __launch_bounds__(256) void cvt_x_kernel(const float* __restrict__ x)
{
    const int i = blockIdx.x * 256 + threadIdx.x;
    const float4 v = reinterpret_cast<const float4*>(x)[i];
    reinterpret_cast<__half2*>(g_Xh)[2*i]   = __floats2half2_rn(v.x, v.y);
    reinterpret_cast<__half2*>(g_Xh)[2*i+1] = __floats2half2_rn(v.z, v.w);
}

__global__ __launch_bounds__(256) void cvt_inw_kernel(
    const float* __restrict__ f, const float* __restrict__ b)
{
    const int i = blockIdx.x * 256 + threadIdx.x;
    const float4 v = (i < N4_INW)
        ? reinterpret_cast<const float4*>(f)[i]
        : reinterpret_cast<const float4*>(b)[i - N4_INW];
    reinterpret_cast<__half2*>(g_Win)[2*i]   = __floats2half2_rn(v.x, v.y);
    reinterpret_cast<__half2*>(g_Win)[2*i+1] = __floats2half2_rn(v.z, v.w);
}

__global__ __launch_bounds__(256) void cvt_rest_kernel(
    const float* __restrict__ dtW_f, const float* __restrict__ dtW_b,
    const float* __restrict__ xpW_f, const float* __restrict__ xpW_b,
    const float* __restrict__ outW_f, const float* __restrict__ outW_b)
{
    int i = blockIdx.x * 256 + threadIdx.x;
    if (i < 2*N4_DTW) {
        const float4 v = (i < N4_DTW)
            ? reinterpret_cast<const float4*>(dtW_f)[i]
            : reinterpret_cast<const float4*>(dtW_b)[i - N4_DTW];
        store_planes(g_dtWh, g_dtWl, i, v);
        return;
    }
    i -= 2*N4_DTW;
    if (i < N4_XP) {
        const int idx = i * 4;
        const int r = idx >> 11, c = idx & 2047;
        float4 v = make_float4(0.f,0.f,0.f,0.f);
        if (r < 96)                   v = *reinterpret_cast<const float4*>(xpW_f + r*2048 + c);
        else if (r >= 128 && r < 224) v = *reinterpret_cast<const float4*>(xpW_b + (r-128)*2048 + c);
        store_planes(g_Xph, g_Xpl, i, v);
        return;
    }
    i -= N4_XP;
    {   // outW K-concat -> single fp16 plane
        const int idx = i * 4;
        const int r = idx >> 12, c = idx & 4095;
        const float4 v = (c < 2048)
            ? *reinterpret_cast<const float4*>(outW_f + (size_t)r*2048 + c)
            : *reinterpret_cast<const float4*>(outW_b + (size_t)r*2048 + (c - 2048));
        reinterpret_cast<__half2*>(g_Wout)[2*i]   = __floats2half2_rn(v.x, v.y);
        reinterpret_cast<__half2*>(g_Wout)[2*i+1] = __floats2half2_rn(v.z, v.w);
    }
}

__global__ __launch_bounds__(256) void reduce_out_kernel(float* __restrict__ out)
{
    const int i = blockIdx.x * 256 + threadIdx.x;
    float4 s = reinterpret_cast<const float4*>(g_OUTP)[i];
#pragma unroll
    for (int k = 1; k < 4; k++) {
        const float4 p = reinterpret_cast<const float4*>(g_OUTP + (size_t)k*MROWS*DMODEL)[i];
        s.x += p.x; s.y += p.y; s.z += p.z; s.w += p.w;
    }
    reinterpret_cast<float4*>(out)[i] = make_float4(0.5f*s.x, 0.5f*s.y, 0.5f*s.z, 0.5f*s.w);
}

// ------------- depthwise conv + SiLU; writes fp32 U and bf16 planes ----------
__global__ __launch_bounds__(256) void conv_silu_kernel(
    const float* __restrict__ convW_f, const float* __restrict__ convB_f,
    const float* __restrict__ convW_b, const float* __restrict__ convB_b)
{
    const int i = blockIdx.x * 256 + threadIdx.x;
    const int c = i & 4095;
    const int row = i >> 12;
    const int l = row & (LSEQ - 1);
    const int b = row >> 10;
    const int dir = c >> 11;
    const int d = c & (DIN - 1);
    const float* w = (dir ? convW_b : convW_f) + d*4;
    float acc = (dir ? convB_b : convB_f)[d];
    const float* xi = g_XZ + dir*4096 + d;
    if (dir == 0) {
#pragma unroll
        for (int k = 0; k < 4; k++) {
            int ls = l - 3 + k;
            if (ls >= 0) acc = fmaf(w[k], xi[(size_t)(b*LSEQ + ls)*8192], acc);
        }
    } else {
#pragma unroll
        for (int k = 0; k < 4; k++) {
            int ls = l + 3 - k;
            if (ls < LSEQ) acc = fmaf(w[k], xi[(size_t)(b*LSEQ + ls)*8192], acc);
        }
    }
    const float sig = 1.f / (1.f + __expf(-acc));
    const float u = acc * sig;
    const size_t o = (size_t)row*4096 + c;
    g_U[o] = u;
    __nv_bfloat16 h, lo2; split1(u, h, lo2);
    g_Uh[o] = h; g_Ul[o] = lo2;
}

// ------------------------- split-K reduce + plane split ----------------------
__global__ __launch_bounds__(256) void reduce_xdbl_kernel()
{
    const int i = blockIdx.x * 256 + threadIdx.x;
    float s = 0.f;
#pragma unroll
    for (int k = 0; k < 8; k++) s += g_XDBLP[(size_t)k*MROWS*256 + i];
    g_XDBL[i] = s;
    __nv_bfloat16 h, l; split1(s, h, l);
    g_XDh[i] = h; g_XDl[i] = l;
}

// ------------- selective scan: 2 states/thread, 4 d/warp, 3-shfl reduce ------
__global__ __launch_bounds__(256) void scan_kernel(
    const float* __restrict__ Alog_f, const float* __restrict__ Alog_b,
    const float* __restrict__ Dp_f,  const float* __restrict__ Dp_b)
{
    const int dir = blockIdx.z;
    const int b   = blockIdx.y;
    const int d0  = blockIdx.x * 32;
    const int t    = threadIdx.x;
    const int lane = t & 31;
    const int w    = t >> 5;
    const int dlw  = (w << 2) + (lane >> 3);
    const int np   = lane & 7;
    const int d    = d0 + dlw;

    const float* Alog = dir ? Alog_b : Alog_f;
    const float Ac0 = -__expf(Alog[d*NST + np]);
    const float Ac1 = -__expf(Alog[d*NST + np + 8]);
    const float DpE = (dir ? Dp_b : Dp_f)[d0 + (t & 31)];

    __shared__ float2 sDdw[32][32];
    __shared__ float2 sUZ [32][32];
    __shared__ float4 sBC [32][8];
    __shared__ float  sY  [32][32];

    const int sll = t >> 5;
    const int sdq = t & 31;
    const int bll = t >> 3, bj = t & 7;

    float rgD[4], rgU[4], rgZ[4], rgB[4];
    auto prefetch = [&](int lb) {
#pragma unroll
        for (int e = 0; e < 4; e++) {
            const int row = b*LSEQ + lb + sll + e*8;
            rgD[e] = g_DELTA[(size_t)row*4096 + dir*2048 + d0 + sdq];
            rgU[e] = g_U[(size_t)row*4096 + dir*2048 + d0 + sdq];
            rgZ[e] = g_XZ[(size_t)row*8192 + dir*4096 + 2048 + d0 + sdq];
        }
        const int rowb = b*LSEQ + lb + bll;
        rgB[0] = g_XDBL[(size_t)rowb*256 + dir*128 + 64 + bj];
        rgB[1] = g_XDBL[(size_t)rowb*256 + dir*128 + 80 + bj];
        rgB[2] = g_XDBL[(size_t)rowb*256 + dir*128 + 64 + bj + 8];
        rgB[3] = g_XDBL[(size_t)rowb*256 + dir*128 + 80 + bj + 8];
    };

    prefetch((dir == 0) ? 0 : (LSEQ - 32));

    float h0 = 0.f, h1 = 0.f;
    const int NCH = LSEQ / 32;
    for (int c = 0; c < NCH; c++) {
        __syncthreads();
#pragma unroll
        for (int e = 0; e < 4; e++) {
            sDdw[sll + e*8][sdq] = make_float2(rgD[e], rgD[e]*rgU[e]);
            sUZ [sll + e*8][sdq] = make_float2(rgU[e], rgZ[e]);
        }
        sBC[bll][bj] = make_float4(rgB[0], rgB[1], rgB[2], rgB[3]);
        __syncthreads();
        if (c + 1 < NCH)
            prefetch((dir == 0) ? (c+1)*32 : (LSEQ - (c+2)*32));
        const int lb = (dir == 0) ? c*32 : (LSEQ - (c+1)*32);
#pragma unroll 4
        for (int s = 0; s < 32; s++) {
            const int ll = (dir == 0) ? s : (31 - s);
            const float2 ddw = sDdw[ll][dlw];
            const float4 bc  = sBC[ll][np];
            const float dA0 = __expf(ddw.x * Ac0);
            const float dA1 = __expf(ddw.x * Ac1);
            h0 = fmaf(h0, dA0, ddw.y * bc.x);
            h1 = fmaf(h1, dA1, ddw.y * bc.z);
            float py = fmaf(h1, bc.w, h0 * bc.y);
            py += __shfl_xor_sync(0xffffffffu, py, 4);
            py += __shfl_xor_sync(0xffffffffu, py, 2);
            py += __shfl_xor_sync(0xffffffffu, py, 1);
            if (np == 0) sY[ll][dlw] = py;
        }
        __syncthreads();
#pragma unroll
        for (int e = 0; e < 4; e++) {
            const int ll = sll + e*8;
            const float2 uz = sUZ[ll][sdq];
            const float y = fmaf(uz.x, DpE, sY[ll][sdq]);
            const float sig = 1.f / (1.f + __expf(-uz.y));
            const float yg = y * (uz.y * sig);
            const size_t o = (size_t)(b*LSEQ + lb + ll)*4096 + dir*2048 + d0 + sdq;
            g_YGh[o] = __float2half(yg);
        }
    }
}

// ------------------------------------ launch ---------------------------------
extern "C" void kernel_launch(void* const* d_in, const int* in_sizes, int n_in,
                              void* d_out, int out_size)
{
    const float* x      = (const float*)d_in[0];
    const float* inW_f  = (const float*)d_in[1];
    const float* convW_f= (const float*)d_in[2];
    const float* convB_f= (const float*)d_in[3];
    const float* xpW_f  = (const float*)d_in[4];
    const float* dtW_f  = (const float*)d_in[5];
    const float* dtB_f  = (const float*)d_in[6];
    const float* Alog_f = (const float*)d_in[7];
    const float* Dp_f   = (const float*)d_in[8];
    const float* outW_f = (const float*)d_in[9];
    const float* inW_b  = (const float*)d_in[10];
    const float* convW_b= (const float*)d_in[11];
    const float* convB_b= (const float*)d_in[12];
    const float* xpW_b  = (const float*)d_in[13];
    const float* dtW_b  = (const float*)d_in[14];
    const float* dtB_b  = (const float*)d_in[15];
    const float* Alog_b = (const float*)d_in[16];
    const float* Dp_b   = (const float*)d_in[17];
    const float* outW_b = (const float*)d_in[18];
    float* out = (float*)d_out;

    float *XZ, *XDBLP, *DELTA, *OUTP;
    __nv_bfloat16 *Uh, *Ul, *Xph, *Xpl, *XDh, *XDl, *dtWh, *dtWl;
    __half *Xh, *Win, *YGh, *Wout;
    cudaGetSymbolAddress((void**)&XZ,    g_XZ);
    cudaGetSymbolAddress((void**)&XDBLP, g_XDBLP);
    cudaGetSymbolAddress((void**)&DELTA, g_DELTA);
    cudaGetSymbolAddress((void**)&OUTP,  g_OUTP);
    cudaGetSymbolAddress((void**)&Xh,    g_Xh);
    cudaGetSymbolAddress((void**)&Win,   g_Win);
    cudaGetSymbolAddress((void**)&Uh,    g_Uh);
    cudaGetSymbolAddress((void**)&Ul,    g_Ul);
    cudaGetSymbolAddress((void**)&Xph,   g_Xph);
    cudaGetSymbolAddress((void**)&Xpl,   g_Xpl);
    cudaGetSymbolAddress((void**)&XDh,   g_XDh);
    cudaGetSymbolAddress((void**)&XDl,   g_XDl);
    cudaGetSymbolAddress((void**)&dtWh,  g_dtWh);
    cudaGetSymbolAddress((void**)&dtWl,  g_dtWl);
    cudaGetSymbolAddress((void**)&YGh,   g_YGh);
    cudaGetSymbolAddress((void**)&Wout,  g_Wout);

    cudaFuncSetAttribute(hgemm<0>,  cudaFuncAttributeMaxDynamicSharedMemorySize, HG_SMEM);
    cudaFuncSetAttribute(hgemm<1>,  cudaFuncAttributeMaxDynamicSharedMemorySize, HG_SMEM);
    cudaFuncSetAttribute(hgemm2<1>, cudaFuncAttributeMaxDynamicSharedMemorySize, H2_SMEM);

    // 0-2) converts (in-proj GEMM stays at launch index 3 = ncu slot)
    cvt_x_kernel  <<<N4_X/256, 256>>>(x);
    cvt_inw_kernel<<<2*N4_INW/256, 256>>>(inW_f, inW_b);
    cvt_rest_kernel<<<(2*N4_DTW + N4_XP + N4_OUT)/256, 256>>>(
        dtW_f, dtW_b, xpW_f, xpW_b, outW_f, outW_b);

    // 3) input projection (fp16 single-term): [2048,8192] = X * Win^T
    hgemm2<1><<<dim3(64,16,1), 256, H2_SMEM>>>(
        Xh, Xh, DMODEL, Win, DMODEL, XZ, 8192, DMODEL, 0);

    // 4) depthwise conv + SiLU (emits U fp32 + bf16 planes)
    conv_silu_kernel<<<(MROWS*4096)/256, 256>>>(convW_f, convB_f, convW_b, convB_b);

    // 5) x_dbl (bf16 3-term): split-K=8
    hgemm<0><<<dim3(2,16,8), 256, HG_SMEM>>>(
        Uh, Ul, 4096, 2048, 128, Xph, Xpl, DIN,
        XDBLP, 256, DIN, nullptr, nullptr, 256);
    reduce_xdbl_kernel<<<(MROWS*256)/256, 256>>>();

    // 6) delta = softplus(dt @ dtWcat^T + dtB) (bf16 3-term)
    hgemm<1><<<dim3(32,16,1), 256, HG_SMEM>>>(
        XDh, XDl, 256, 128, 2048, dtWh, dtWl, DTR,
        DELTA, 4096, DTR, dtB_f, dtB_b, 0);

    // 7) selective scan + gating (emits YG single fp16 plane)
    scan_kernel<<<dim3(64,2,2), 256>>>(Alog_f, Alog_b, Dp_f, Dp_b);

    // 8) out-proj (fp16 single-term) split-K=4, then 0.5*sum
    hgemm2<1><<<dim3(8,16,4), 256, H2_SMEM>>>(
        YGh, YGh, 4096, Wout, 4096, OUTP, DMODEL, 4096, 1024);
    reduce_out_kernel<<<(MROWS*DMODEL/4)/256, 256>>>(out);
}

// round 14
// speedup vs baseline: 2.3194x; 1.0003x over previous
#include <cuda_runtime.h>
#include <cuda_bf16.h>
#include <cuda_fp16.h>
#include <math.h>
#include <cstdint>

#define B_SZ   2
#define LSEQ   1024
#define DMODEL 1024
#define DIN    2048
#define NST    16
#define DTR    64
#define MROWS  (B_SZ*LSEQ)   /* 2048 */

// ---------------- scratch (device globals; no allocation allowed) ------------
__device__ float g_XZ[MROWS*8192];              // [m][dir*4096 + (xi | z)]
__device__ float g_U [MROWS*4096];              // fp32 for scan
__device__ __nv_bfloat16 g_Uh[MROWS*4096],  g_Ul[MROWS*4096];
__device__ __half g_Xh[MROWS*DMODEL];                            // single fp16 plane (in-proj A)
__device__ __half g_Win[8192*DMODEL];                            // single fp16 plane (in-proj B)
__device__ __nv_bfloat16 g_Xph[256*DIN],    g_Xpl[256*DIN];      // padded xpW
__device__ float g_XDBLP[8*MROWS*256];
__device__ float g_XDBL[MROWS*256];
__device__ __nv_bfloat16 g_XDh[MROWS*256],  g_XDl[MROWS*256];
__device__ __nv_bfloat16 g_dtWh[4096*DTR],  g_dtWl[4096*DTR];    // dir-concat rows
__device__ float g_DELTA[(size_t)MROWS*4096];
__device__ __half g_YGh[MROWS*4096];                             // single fp16 plane (out-proj A)
__device__ __half g_Wout[DMODEL*4096];                           // single fp16 plane (out-proj B)
__device__ float g_OUTP[4*MROWS*DMODEL];        // out-proj split-K=4 partials

// ======================= helpers =============================================
__device__ __forceinline__ uint32_t smem_u32(const void* p) {
    uint32_t a;
    asm("{ .reg .u64 t; cvta.to.shared.u64 t, %1; cvt.u32.u64 %0, t; }" : "=r"(a) : "l"(p));
    return a;
}
#define LDM4(r0,r1,r2,r3,addr)                                                      \
    asm volatile("ldmatrix.sync.aligned.m8n8.x4.shared.b16 {%0,%1,%2,%3}, [%4];"    \
        : "=r"(r0),"=r"(r1),"=r"(r2),"=r"(r3) : "r"(addr))
#define MMA_BF16(c,a,b)                                                             \
    asm volatile("mma.sync.aligned.m16n8k16.row.col.f32.bf16.bf16.f32 "             \
        "{%0,%1,%2,%3}, {%4,%5,%6,%7}, {%8,%9}, {%0,%1,%2,%3};"                     \
        : "+f"((c)[0]),"+f"((c)[1]),"+f"((c)[2]),"+f"((c)[3])                       \
        : "r"((a)[0]),"r"((a)[1]),"r"((a)[2]),"r"((a)[3]),"r"((b)[0]),"r"((b)[1]))
#define MMA_F16(c,a,b)                                                              \
    asm volatile("mma.sync.aligned.m16n8k16.row.col.f32.f16.f16.f32 "               \
        "{%0,%1,%2,%3}, {%4,%5,%6,%7}, {%8,%9}, {%0,%1,%2,%3};"                     \
        : "+f"((c)[0]),"+f"((c)[1]),"+f"((c)[2]),"+f"((c)[3])                       \
        : "r"((a)[0]),"r"((a)[1]),"r"((a)[2]),"r"((a)[3]),"r"((b)[0]),"r"((b)[1]))
#define CPA16(dst, src) asm volatile("cp.async.cg.shared.global [%0], [%1], 16;" :: "r"(dst), "l"(src) : "memory")
#define CPCOMMIT()      asm volatile("cp.async.commit_group;" ::: "memory")
#define CPWAIT0()       asm volatile("cp.async.wait_group 0;" ::: "memory")
#define CPWAIT1()       asm volatile("cp.async.wait_group 1;" ::: "memory")

__device__ __forceinline__ void split1(float v, __nv_bfloat16& h, __nv_bfloat16& l) {
    h = __float2bfloat16(v);
    l = __float2bfloat16(v - __bfloat162float(h));
}
__device__ __forceinline__ void store_planes(
    __nv_bfloat16* __restrict__ hi, __nv_bfloat16* __restrict__ lo,
    int i, float4 v)
{
    __nv_bfloat16 h0,h1,h2,h3,l0,l1,l2,l3;
    split1(v.x,h0,l0); split1(v.y,h1,l1); split1(v.z,h2,l2); split1(v.w,h3,l3);
    reinterpret_cast<__nv_bfloat162*>(hi)[2*i]   = __nv_bfloat162(h0,h1);
    reinterpret_cast<__nv_bfloat162*>(hi)[2*i+1] = __nv_bfloat162(h2,h3);
    reinterpret_cast<__nv_bfloat162*>(lo)[2*i]   = __nv_bfloat162(l0,l1);
    reinterpret_cast<__nv_bfloat162*>(lo)[2*i+1] = __nv_bfloat162(l2,l3);
}

// ======================= bf16 3-term GEMM (small stages) =====================
#define BKC 32
#define ASTRIDE 80
#define STG_A_HI 0
#define STG_A_LO 10240
#define STG_B_HI 20480
#define STG_B_LO 30720
#define STG_STRIDE 40960
#define HG_SMEM (2*STG_STRIDE)

template<int EPI>
__global__ __launch_bounds__(256, 2) void hgemm(
    const __nv_bfloat16* __restrict__ Ah, const __nv_bfloat16* __restrict__ Al,
    int lda, int a_off1, int nsplit,
    const __nv_bfloat16* __restrict__ Bh, const __nv_bfloat16* __restrict__ Bl,
    int ldb,
    float* __restrict__ C, int ldc, int K,
    const float* __restrict__ bias0, const float* __restrict__ bias1,
    int kz)
{
    extern __shared__ char sm[];
    const uint32_t smb = smem_u32(sm);
    const int tid = threadIdx.x;
    const int bm = blockIdx.y * 128, bn = blockIdx.x * 128;
    if (kz > 0) {
        Ah += (size_t)blockIdx.z * kz;  Al += (size_t)blockIdx.z * kz;
        Bh += (size_t)blockIdx.z * kz;  Bl += (size_t)blockIdx.z * kz;
        C  += (size_t)blockIdx.z * (size_t)(gridDim.y * 128) * (size_t)ldc;
        K = kz;
    }
    const int aoff = (nsplit && bn >= nsplit) ? a_off1 : 0;

    const int grow = tid >> 1;
    const int seg  = (tid & 1) << 1;
    const char* gAh = (const char*)(Ah + aoff + (size_t)(bm + grow) * lda);
    const char* gAl = (const char*)(Al + aoff + (size_t)(bm + grow) * lda);
    const char* gBh = (const char*)(Bh + (size_t)(bn + grow) * ldb);
    const char* gBl = (const char*)(Bl + (size_t)(bn + grow) * ldb);
    const uint32_t srow = smb + (uint32_t)(grow * ASTRIDE + seg * 16);

    const int wid = tid >> 5, lane = tid & 31;
    const int wm = (wid >> 2) * 64;
    const int wn = (wid & 3) * 32;
    const int tq = lane >> 2, tr = lane & 3;
    const uint32_t aoffm = (uint32_t)((wm + (lane & 15)) * ASTRIDE + ((lane >> 4) << 4));
    const int g = lane >> 3;
    const uint32_t boffm = (uint32_t)((wn + ((g >> 1) << 3) + (lane & 7)) * ASTRIDE + ((g & 1) << 4));

    float acc[4][4][4];
#pragma unroll
    for (int i = 0; i < 4; i++)
#pragma unroll
        for (int j = 0; j < 4; j++)
#pragma unroll
            for (int q = 0; q < 4; q++) acc[i][j][q] = 0.f;

    const int nch = K / BKC;

    auto issue = [&](int s) {
        const uint32_t st = srow + (uint32_t)(s & 1) * STG_STRIDE;
        const int go = s * (BKC * 2) + seg * 16;
        CPA16(st + STG_A_HI,      gAh + go);
        CPA16(st + STG_A_HI + 16, gAh + go + 16);
        CPA16(st + STG_A_LO,      gAl + go);
        CPA16(st + STG_A_LO + 16, gAl + go + 16);
        CPA16(st + STG_B_HI,      gBh + go);
        CPA16(st + STG_B_HI + 16, gBh + go + 16);
        CPA16(st + STG_B_LO,      gBl + go);
        CPA16(st + STG_B_LO + 16, gBl + go + 16);
        CPCOMMIT();
    };

    issue(0);
    for (int s = 0; s < nch; s++) {
        CPWAIT0();
        __syncthreads();
        if (s + 1 < nch) issue(s + 1);
        const uint32_t sa = smb + (uint32_t)(s & 1) * STG_STRIDE;
#pragma unroll
        for (int ph = 0; ph < 2; ph++) {
            const uint32_t ka = sa + ph * 32;
            uint32_t ah[4][4], al[4][4], bh[4][2], bl[4][2];
#pragma unroll
            for (int i = 0; i < 4; i++)
                LDM4(ah[i][0], ah[i][1], ah[i][2], ah[i][3], ka + STG_A_HI + aoffm + i*(16*ASTRIDE));
            LDM4(bh[0][0], bh[0][1], bh[1][0], bh[1][1], ka + STG_B_HI + boffm);
            LDM4(bh[2][0], bh[2][1], bh[3][0], bh[3][1], ka + STG_B_HI + boffm + 16*ASTRIDE);
#pragma unroll
            for (int i = 0; i < 4; i++)
#pragma unroll
                for (int j = 0; j < 4; j++)
                    MMA_BF16(acc[i][j], ah[i], bh[j]);
#pragma unroll
            for (int i = 0; i < 4; i++)
                LDM4(al[i][0], al[i][1], al[i][2], al[i][3], ka + STG_A_LO + aoffm + i*(16*ASTRIDE));
            LDM4(bl[0][0], bl[0][1], bl[1][0], bl[1][1], ka + STG_B_LO + boffm);
            LDM4(bl[2][0], bl[2][1], bl[3][0], bl[3][1], ka + STG_B_LO + boffm + 16*ASTRIDE);
#pragma unroll
            for (int i = 0; i < 4; i++)
#pragma unroll
                for (int j = 0; j < 4; j++)
                    MMA_BF16(acc[i][j], ah[i], bl[j]);
#pragma unroll
            for (int i = 0; i < 4; i++)
#pragma unroll
                for (int j = 0; j < 4; j++)
                    MMA_BF16(acc[i][j], al[i], bh[j]);
        }
    }

    const float* bias = nullptr;
    if (EPI == 1) bias = (nsplit && bn >= nsplit) ? (bias1 - nsplit) : bias0;
#pragma unroll
    for (int i = 0; i < 4; i++) {
        const int row0 = bm + wm + 16*i + tq;
#pragma unroll
        for (int j = 0; j < 4; j++) {
            const int col = bn + wn + 8*j + 2*tr;
            float v0 = acc[i][j][0], v1 = acc[i][j][1];
            float v2 = acc[i][j][2], v3 = acc[i][j][3];
            if (EPI == 1) {
                const float b0v = bias[col], b1v = bias[col+1];
                v0 += b0v; v1 += b1v; v2 += b0v; v3 += b1v;
                v0 = (v0 > 20.f) ? v0 : log1pf(__expf(v0));
                v1 = (v1 > 20.f) ? v1 : log1pf(__expf(v1));
                v2 = (v2 > 20.f) ? v2 : log1pf(__expf(v2));
                v3 = (v3 > 20.f) ? v3 : log1pf(__expf(v3));
            }
            *reinterpret_cast<float2*>(C + (size_t)row0 * ldc + col)       = make_float2(v0, v1);
            *reinterpret_cast<float2*>(C + (size_t)(row0 + 8) * ldc + col) = make_float2(v2, v3);
        }
    }
}

// ======== fp16 GEMM: A single plane, B single plane, 3-stage pipeline ========
#define H2_A    0
#define H2_B    10240
#define H2_STRIDE 20480
#define H2_SMEM (3*H2_STRIDE)

__global__ __launch_bounds__(256, 2) void hgemm2(
    const __half* __restrict__ Ah, int lda,
    const __half* __restrict__ B, int ldb,
    float* __restrict__ C, int ldc, int K, int kz)
{
    extern __shared__ char sm[];
    const uint32_t smb = smem_u32(sm);
    const int tid = threadIdx.x;
    const int bm = blockIdx.y * 128, bn = blockIdx.x * 128;
    if (kz > 0) {
        Ah += (size_t)blockIdx.z * kz;
        B  += (size_t)blockIdx.z * kz;
        C  += (size_t)blockIdx.z * (size_t)(gridDim.y * 128) * (size_t)ldc;
        K = kz;
    }

    const int grow = tid >> 1;
    const int seg  = (tid & 1) << 1;
    const char* gAh = (const char*)(Ah + (size_t)(bm + grow) * lda);
    const char* gB  = (const char*)(B  + (size_t)(bn + grow) * ldb);
    const uint32_t srow = smb + (uint32_t)(grow * ASTRIDE + seg * 16);

    const int wid = tid >> 5, lane = tid & 31;
    const int wm = (wid >> 2) * 64;
    const int wn = (wid & 3) * 32;
    const int tq = lane >> 2, tr = lane & 3;
    const uint32_t aoffm = (uint32_t)((wm + (lane & 15)) * ASTRIDE + ((lane >> 4) << 4));
    const int g = lane >> 3;
    const uint32_t boffm = (uint32_t)((wn + ((g >> 1) << 3) + (lane & 7)) * ASTRIDE + ((g & 1) << 4));

    float acc[4][4][4];
#pragma unroll
    for (int i = 0; i < 4; i++)
#pragma unroll
        for (int j = 0; j < 4; j++)
#pragma unroll
            for (int q = 0; q < 4; q++) acc[i][j][q] = 0.f;

    const int nch = K / BKC;

    auto issue = [&](int s) {
        const uint32_t st = srow + (uint32_t)(s % 3) * H2_STRIDE;
        const int go = s * (BKC * 2) + seg * 16;
        CPA16(st + H2_A,      gAh + go);
        CPA16(st + H2_A + 16, gAh + go + 16);
        CPA16(st + H2_B,      gB + go);
        CPA16(st + H2_B + 16, gB + go + 16);
        CPCOMMIT();
    };

    issue(0);
    if (nch > 1) issue(1);
    for (int s = 0; s < nch; s++) {
        if (s + 1 < nch) CPWAIT1();      // chunk s resident; s+1 may be in flight
        else             CPWAIT0();
        __syncthreads();                  // + all warps done with stage (s+2)%3 (chunk s-1)
        if (s + 2 < nch) issue(s + 2);
        const uint32_t sa = smb + (uint32_t)(s % 3) * H2_STRIDE;
#pragma unroll
        for (int ph = 0; ph < 2; ph++) {
            const uint32_t ka = sa + ph * 32;
            uint32_t ah[4][4], bb[4][2];
#pragma unroll
            for (int i = 0; i < 4; i++)
                LDM4(ah[i][0], ah[i][1], ah[i][2], ah[i][3], ka + H2_A + aoffm + i*(16*ASTRIDE));
            LDM4(bb[0][0], bb[0][1], bb[1][0], bb[1][1], ka + H2_B + boffm);
            LDM4(bb[2][0], bb[2][1], bb[3][0], bb[3][1], ka + H2_B + boffm + 16*ASTRIDE);
#pragma unroll
            for (int i = 0; i < 4; i++)
#pragma unroll
                for (int j = 0; j < 4; j++)
                    MMA_F16(acc[i][j], ah[i], bb[j]);
        }
    }

#pragma unroll
    for (int i = 0; i < 4; i++) {
        const int row0 = bm + wm + 16*i + tq;
#pragma unroll
        for (int j = 0; j < 4; j++) {
            const int col = bn + wn + 8*j + 2*tr;
            *reinterpret_cast<float2*>(C + (size_t)row0 * ldc + col)
                = make_float2(acc[i][j][0], acc[i][j][1]);
            *reinterpret_cast<float2*>(C + (size_t)(row0 + 8) * ldc + col)
                = make_float2(acc[i][j][2], acc[i][j][3]);
        }
    }
}

// ======================= merged convert kernels ===============================
#define N4_X    (MROWS*DMODEL/4)
#define N4_INW  (4096*DMODEL/4)
#define N4_DTW  (2048*DTR/4)
#define N4_XP   (256*DIN/4)
#define N4_OUT  (DMODEL*4096/4)

__global__ __launch_bounds__(256) void cvt_x_kernel(const float* __restrict__ x)
{
    const int i = blockIdx.x * 256 + threadIdx.x;
    const float4 v = reinterpret_cast<const float4*>(x)[i];
    reinterpret_cast<__half2*>(g_Xh)[2*i]   = __floats2half2_rn(v.x, v.y);
    reinterpret_cast<__half2*>(g_Xh)[2*i+1] = __floats2half2_rn(v.z, v.w);
}

__global__ __launch_bounds__(256) void cvt_inw_kernel(
    const float* __restrict__ f, const float* __restrict__ b)
{
    const int i = blockIdx.x * 256 + threadIdx.x;
    const float4 v = (i < N4_INW)
        ? reinterpret_cast<const float4*>(f)[i]
        : reinterpret_cast<const float4*>(b)[i - N4_INW];
    reinterpret_cast<__half2*>(g_Win)[2*i]   = __floats2half2_rn(v.x, v.y);
    reinterpret_cast<__half2*>(g_Win)[2*i+1] = __floats2half2_rn(v.z, v.w);
}

__global__ __launch_bounds__(256) void cvt_rest_kernel(
    const float* __restrict__ dtW_f, const float* __restrict__ dtW_b,
    const float* __restrict__ xpW_f, const float* __restrict__ xpW_b,
    const float* __restrict__ outW_f, const float* __restrict__ outW_b)
{
    int i = blockIdx.x * 256 + threadIdx.x;
    if (i < 2*N4_DTW) {
        const float4 v = (i < N4_DTW)
            ? reinterpret_cast<const float4*>(dtW_f)[i]
            : reinterpret_cast<const float4*>(dtW_b)[i - N4_DTW];
        store_planes(g_dtWh, g_dtWl, i, v);
        return;
    }
    i -= 2*N4_DTW;
    if (i < N4_XP) {
        const int idx = i * 4;
        const int r = idx >> 11, c = idx & 2047;
        float4 v = make_float4(0.f,0.f,0.f,0.f);
        if (r < 96)                   v = *reinterpret_cast<const float4*>(xpW_f + r*2048 + c);
        else if (r >= 128 && r < 224) v = *reinterpret_cast<const float4*>(xpW_b + (r-128)*2048 + c);
        store_planes(g_Xph, g_Xpl, i, v);
        return;
    }
    i -= N4_XP;
    {   // outW K-concat -> single fp16 plane
        const int idx = i * 4;
        const int r = idx >> 12, c = idx & 4095;
        const float4 v = (c < 2048)
            ? *reinterpret_cast<const float4*>(outW_f + (size_t)r*2048 + c)
            : *reinterpret_cast<const float4*>(outW_b + (size_t)r*2048 + (c - 2048));
        reinterpret_cast<__half2*>(g_Wout)[2*i]   = __floats2half2_rn(v.x, v.y);
        reinterpret_cast<__half2*>(g_Wout)[2*i+1] = __floats2half2_rn(v.z, v.w);
    }
}

__global__ __launch_bounds__(256) void reduce_out_kernel(float* __restrict__ out)
{
    const int i = blockIdx.x * 256 + threadIdx.x;
    float4 s = reinterpret_cast<const float4*>(g_OUTP)[i];
#pragma unroll
    for (int k = 1; k < 4; k++) {
        const float4 p = reinterpret_cast<const float4*>(g_OUTP + (size_t)k*MROWS*DMODEL)[i];
        s.x += p.x; s.y += p.y; s.z += p.z; s.w += p.w;
    }
    reinterpret_cast<float4*>(out)[i] = make_float4(0.5f*s.x, 0.5f*s.y, 0.5f*s.z, 0.5f*s.w);
}

// ------------- depthwise conv + SiLU; writes fp32 U and bf16 planes ----------
__global__ __launch_bounds__(256) void conv_silu_kernel(
    const float* __restrict__ convW_f, const float* __restrict__ convB_f,
    const float* __restrict__ convW_b, const float* __restrict__ convB_b)
{
    const int i = blockIdx.x * 256 + threadIdx.x;
    const int c = i & 4095;
    const int row = i >> 12;
    const int l = row & (LSEQ - 1);
    const int b = row >> 10;
    const int dir = c >> 11;
    const int d = c & (DIN - 1);
    const float* w = (dir ? convW_b : convW_f) + d*4;
    float acc = (dir ? convB_b : convB_f)[d];
    const float* xi = g_XZ + dir*4096 + d;
    if (dir == 0) {
#pragma unroll
        for (int k = 0; k < 4; k++) {
            int ls = l - 3 + k;
            if (ls >= 0) acc = fmaf(w[k], xi[(size_t)(b*LSEQ + ls)*8192], acc);
        }
    } else {
#pragma unroll
        for (int k = 0; k < 4; k++) {
            int ls = l + 3 - k;
            if (ls < LSEQ) acc = fmaf(w[k], xi[(size_t)(b*LSEQ + ls)*8192], acc);
        }
    }
    const float sig = 1.f / (1.f + __expf(-acc));
    const float u = acc * sig;
    const size_t o = (size_t)row*4096 + c;
    g_U[o] = u;
    __nv_bfloat16 h, lo2; split1(u, h, lo2);
    g_Uh[o] = h; g_Ul[o] = lo2;
}

// ------------------------- split-K reduce + plane split ----------------------
__global__ __launch_bounds__(256) void reduce_xdbl_kernel()
{
    const int i = blockIdx.x * 256 + threadIdx.x;
    float s = 0.f;
#pragma unroll
    for (int k = 0; k < 8; k++) s += g_XDBLP[(size_t)k*MROWS*256 + i];
    g_XDBL[i] = s;
    __nv_bfloat16 h, l; split1(s, h, l);
    g_XDh[i] = h; g_XDl[i] = l;
}

// ------------- selective scan: 2 states/thread, 4 d/warp, 3-shfl reduce ------
__global__ __launch_bounds__(256) void scan_kernel(
    const float* __restrict__ Alog_f, const float* __restrict__ Alog_b,
    const float* __restrict__ Dp_f,  const float* __restrict__ Dp_b)
{
    const int dir = blockIdx.z;
    const int b   = blockIdx.y;
    const int d0  = blockIdx.x * 32;
    const int t    = threadIdx.x;
    const int lane = t & 31;
    const int w    = t >> 5;
    const int dlw  = (w << 2) + (lane >> 3);
    const int np   = lane & 7;
    const int d    = d0 + dlw;

    const float* Alog = dir ? Alog_b : Alog_f;
    const float Ac0 = -__expf(Alog[d*NST + np]);
    const float Ac1 = -__expf(Alog[d*NST + np + 8]);
    const float DpE = (dir ? Dp_b : Dp_f)[d0 + (t & 31)];

    __shared__ float2 sDdw[32][32];
    __shared__ float2 sUZ [32][32];
    __shared__ float4 sBC [32][8];
    __shared__ float  sY  [32][32];

    const int sll = t >> 5;
    const int sdq = t & 31;
    const int bll = t >> 3, bj = t & 7;

    float rgD[4], rgU[4], rgZ[4], rgB[4];
    auto prefetch = [&](int lb) {
#pragma unroll
        for (int e = 0; e < 4; e++) {
            const int row = b*LSEQ + lb + sll + e*8;
            rgD[e] = g_DELTA[(size_t)row*4096 + dir*2048 + d0 + sdq];
            rgU[e] = g_U[(size_t)row*4096 + dir*2048 + d0 + sdq];
            rgZ[e] = g_XZ[(size_t)row*8192 + dir*4096 + 2048 + d0 + sdq];
        }
        const int rowb = b*LSEQ + lb + bll;
        rgB[0] = g_XDBL[(size_t)rowb*256 + dir*128 + 64 + bj];
        rgB[1] = g_XDBL[(size_t)rowb*256 + dir*128 + 80 + bj];
        rgB[2] = g_XDBL[(size_t)rowb*256 + dir*128 + 64 + bj + 8];
        rgB[3] = g_XDBL[(size_t)rowb*256 + dir*128 + 80 + bj + 8];
    };

    prefetch((dir == 0) ? 0 : (LSEQ - 32));

    float h0 = 0.f, h1 = 0.f;
    const int NCH = LSEQ / 32;
    for (int c = 0; c < NCH; c++) {
        __syncthreads();
#pragma unroll
        for (int e = 0; e < 4; e++) {
            sDdw[sll + e*8][sdq] = make_float2(rgD[e], rgD[e]*rgU[e]);
            sUZ [sll + e*8][sdq] = make_float2(rgU[e], rgZ[e]);
        }
        sBC[bll][bj] = make_float4(rgB[0], rgB[1], rgB[2], rgB[3]);
        __syncthreads();
        if (c + 1 < NCH)
            prefetch((dir == 0) ? (c+1)*32 : (LSEQ - (c+2)*32));
        const int lb = (dir == 0) ? c*32 : (LSEQ - (c+1)*32);
#pragma unroll 4
        for (int s = 0; s < 32; s++) {
            const int ll = (dir == 0) ? s : (31 - s);
            const float2 ddw = sDdw[ll][dlw];
            const float4 bc  = sBC[ll][np];
            const float dA0 = __expf(ddw.x * Ac0);
            const float dA1 = __expf(ddw.x * Ac1);
            h0 = fmaf(h0, dA0, ddw.y * bc.x);
            h1 = fmaf(h1, dA1, ddw.y * bc.z);
            float py = fmaf(h1, bc.w, h0 * bc.y);
            py += __shfl_xor_sync(0xffffffffu, py, 4);
            py += __shfl_xor_sync(0xffffffffu, py, 2);
            py += __shfl_xor_sync(0xffffffffu, py, 1);
            if (np == 0) sY[ll][dlw] = py;
        }
        __syncthreads();
#pragma unroll
        for (int e = 0; e < 4; e++) {
            const int ll = sll + e*8;
            const float2 uz = sUZ[ll][sdq];
            const float y = fmaf(uz.x, DpE, sY[ll][sdq]);
            const float sig = 1.f / (1.f + __expf(-uz.y));
            const float yg = y * (uz.y * sig);
            const size_t o = (size_t)(b*LSEQ + lb + ll)*4096 + dir*2048 + d0 + sdq;
            g_YGh[o] = __float2half(yg);
        }
    }
}

// ------------------------------------ launch ---------------------------------
extern "C" void kernel_launch(void* const* d_in, const int* in_sizes, int n_in,
                              void* d_out, int out_size)
{
    const float* x      = (const float*)d_in[0];
    const float* inW_f  = (const float*)d_in[1];
    const float* convW_f= (const float*)d_in[2];
    const float* convB_f= (const float*)d_in[3];
    const float* xpW_f  = (const float*)d_in[4];
    const float* dtW_f  = (const float*)d_in[5];
    const float* dtB_f  = (const float*)d_in[6];
    const float* Alog_f = (const float*)d_in[7];
    const float* Dp_f   = (const float*)d_in[8];
    const float* outW_f = (const float*)d_in[9];
    const float* inW_b  = (const float*)d_in[10];
    const float* convW_b= (const float*)d_in[11];
    const float* convB_b= (const float*)d_in[12];
    const float* xpW_b  = (const float*)d_in[13];
    const float* dtW_b  = (const float*)d_in[14];
    const float* dtB_b  = (const float*)d_in[15];
    const float* Alog_b = (const float*)d_in[16];
    const float* Dp_b   = (const float*)d_in[17];
    const float* outW_b = (const float*)d_in[18];
    float* out = (float*)d_out;

    float *XZ, *XDBLP, *DELTA, *OUTP;
    __nv_bfloat16 *Uh, *Ul, *Xph, *Xpl, *XDh, *XDl, *dtWh, *dtWl;
    __half *Xh, *Win, *YGh, *Wout;
    cudaGetSymbolAddress((void**)&XZ,    g_XZ);
    cudaGetSymbolAddress((void**)&XDBLP, g_XDBLP);
    cudaGetSymbolAddress((void**)&DELTA, g_DELTA);
    cudaGetSymbolAddress((void**)&OUTP,  g_OUTP);
    cudaGetSymbolAddress((void**)&Xh,    g_Xh);
    cudaGetSymbolAddress((void**)&Win,   g_Win);
    cudaGetSymbolAddress((void**)&Uh,    g_Uh);
    cudaGetSymbolAddress((void**)&Ul,    g_Ul);
    cudaGetSymbolAddress((void**)&Xph,   g_Xph);
    cudaGetSymbolAddress((void**)&Xpl,   g_Xpl);
    cudaGetSymbolAddress((void**)&XDh,   g_XDh);
    cudaGetSymbolAddress((void**)&XDl,   g_XDl);
    cudaGetSymbolAddress((void**)&dtWh,  g_dtWh);
    cudaGetSymbolAddress((void**)&dtWl,  g_dtWl);
    cudaGetSymbolAddress((void**)&YGh,   g_YGh);
    cudaGetSymbolAddress((void**)&Wout,  g_Wout);

    cudaFuncSetAttribute(hgemm<0>, cudaFuncAttributeMaxDynamicSharedMemorySize, HG_SMEM);
    cudaFuncSetAttribute(hgemm<1>, cudaFuncAttributeMaxDynamicSharedMemorySize, HG_SMEM);
    cudaFuncSetAttribute(hgemm2,   cudaFuncAttributeMaxDynamicSharedMemorySize, H2_SMEM);

    // 0-2) converts (in-proj GEMM stays at launch index 3 = ncu slot)
    cvt_x_kernel  <<<N4_X/256, 256>>>(x);
    cvt_inw_kernel<<<2*N4_INW/256, 256>>>(inW_f, inW_b);
    cvt_rest_kernel<<<(2*N4_DTW + N4_XP + N4_OUT)/256, 256>>>(
        dtW_f, dtW_b, xpW_f, xpW_b, outW_f, outW_b);

    // 3) input projection (fp16 single-term, 3-stage): [2048,8192] = X * Win^T
    hgemm2<<<dim3(64,16,1), 256, H2_SMEM>>>(
        Xh, DMODEL, Win, DMODEL, XZ, 8192, DMODEL, 0);

    // 4) depthwise conv + SiLU (emits U fp32 + bf16 planes)
    conv_silu_kernel<<<(MROWS*4096)/256, 256>>>(convW_f, convB_f, convW_b, convB_b);

    // 5) x_dbl (bf16 3-term): split-K=8
    hgemm<0><<<dim3(2,16,8), 256, HG_SMEM>>>(
        Uh, Ul, 4096, 2048, 128, Xph, Xpl, DIN,
        XDBLP, 256, DIN, nullptr, nullptr, 256);
    reduce_xdbl_kernel<<<(MROWS*256)/256, 256>>>();

    // 6) delta = softplus(dt @ dtWcat^T + dtB) (bf16 3-term)
    hgemm<1><<<dim3(32,16,1), 256, HG_SMEM>>>(
        XDh, XDl, 256, 128, 2048, dtWh, dtWl, DTR,
        DELTA, 4096, DTR, dtB_f, dtB_b, 0);

    // 7) selective scan + gating (emits YG single fp16 plane)
    scan_kernel<<<dim3(64,2,2), 256>>>(Alog_f, Alog_b, Dp_f, Dp_b);

    // 8) out-proj (fp16 single-term, 3-stage) split-K=4, then 0.5*sum
    hgemm2<<<dim3(8,16,4), 256, H2_SMEM>>>(
        YGh, 4096, Wout, 4096, OUTP, DMODEL, 4096, 1024);
    reduce_out_kernel<<<(MROWS*DMODEL/4)/256, 256>>>(out);
}

// round 15
// speedup vs baseline: 2.4265x; 1.0462x over previous
#include <cuda_runtime.h>
#include <cuda_bf16.h>
#include <cuda_fp16.h>
#include <math.h>
#include <cstdint>

#define B_SZ   2
#define LSEQ   1024
#define DMODEL 1024
#define DIN    2048
#define NST    16
#define DTR    64
#define MROWS  (B_SZ*LSEQ)   /* 2048 */

// ---------------- scratch (device globals; no allocation allowed) ------------
__device__ float g_XZ[MROWS*8192];              // [m][dir*4096 + (xi | z)]
__device__ float g_U [MROWS*4096];              // fp32 for scan
__device__ __nv_bfloat16 g_Uh[MROWS*4096],  g_Ul[MROWS*4096];
__device__ __half g_Xh[MROWS*DMODEL];                            // fp16 (in-proj A)
__device__ __half g_Win[8192*DMODEL];                            // fp16 (in-proj B)
__device__ __nv_bfloat16 g_Xph[256*DIN],    g_Xpl[256*DIN];      // padded xpW
__device__ float g_XDBLP[8*MROWS*256];
__device__ float g_XDBL[MROWS*256];
__device__ __nv_bfloat16 g_XDh[MROWS*256],  g_XDl[MROWS*256];
__device__ __nv_bfloat16 g_dtWh[4096*DTR],  g_dtWl[4096*DTR];    // dir-concat rows
__device__ float g_DELTA[(size_t)MROWS*4096];
__device__ __half g_YGh[MROWS*4096];                             // fp16 (out-proj A)
__device__ __half g_Wout[DMODEL*4096];                           // fp16 (out-proj B)
__device__ float g_OUTP[4*MROWS*DMODEL];        // out-proj split-K=4 partials

// ======================= helpers =============================================
__device__ __forceinline__ uint32_t smem_u32(const void* p) {
    uint32_t a;
    asm("{ .reg .u64 t; cvta.to.shared.u64 t, %1; cvt.u32.u64 %0, t; }" : "=r"(a) : "l"(p));
    return a;
}
#define LDM4(r0,r1,r2,r3,addr)                                                      \
    asm volatile("ldmatrix.sync.aligned.m8n8.x4.shared.b16 {%0,%1,%2,%3}, [%4];"    \
        : "=r"(r0),"=r"(r1),"=r"(r2),"=r"(r3) : "r"(addr))
#define MMA_BF16(c,a,b)                                                             \
    asm volatile("mma.sync.aligned.m16n8k16.row.col.f32.bf16.bf16.f32 "             \
        "{%0,%1,%2,%3}, {%4,%5,%6,%7}, {%8,%9}, {%0,%1,%2,%3};"                     \
        : "+f"((c)[0]),"+f"((c)[1]),"+f"((c)[2]),"+f"((c)[3])                       \
        : "r"((a)[0]),"r"((a)[1]),"r"((a)[2]),"r"((a)[3]),"r"((b)[0]),"r"((b)[1]))
#define MMA_F16(c,a,b)                                                              \
    asm volatile("mma.sync.aligned.m16n8k16.row.col.f32.f16.f16.f32 "               \
        "{%0,%1,%2,%3}, {%4,%5,%6,%7}, {%8,%9}, {%0,%1,%2,%3};"                     \
        : "+f"((c)[0]),"+f"((c)[1]),"+f"((c)[2]),"+f"((c)[3])                       \
        : "r"((a)[0]),"r"((a)[1]),"r"((a)[2]),"r"((a)[3]),"r"((b)[0]),"r"((b)[1]))
#define CPA16(dst, src) asm volatile("cp.async.cg.shared.global [%0], [%1], 16;" :: "r"(dst), "l"(src) : "memory")
#define CPCOMMIT()      asm volatile("cp.async.commit_group;" ::: "memory")
#define CPWAIT0()       asm volatile("cp.async.wait_group 0;" ::: "memory")
#define CPWAIT1()       asm volatile("cp.async.wait_group 1;" ::: "memory")
#define EX2F(r, x)      asm("ex2.approx.f32 %0, %1;" : "=f"(r) : "f"(x))

__device__ __forceinline__ void split1(float v, __nv_bfloat16& h, __nv_bfloat16& l) {
    h = __float2bfloat16(v);
    l = __float2bfloat16(v - __bfloat162float(h));
}
__device__ __forceinline__ void store_planes(
    __nv_bfloat16* __restrict__ hi, __nv_bfloat16* __restrict__ lo,
    int i, float4 v)
{
    __nv_bfloat16 h0,h1,h2,h3,l0,l1,l2,l3;
    split1(v.x,h0,l0); split1(v.y,h1,l1); split1(v.z,h2,l2); split1(v.w,h3,l3);
    reinterpret_cast<__nv_bfloat162*>(hi)[2*i]   = __nv_bfloat162(h0,h1);
    reinterpret_cast<__nv_bfloat162*>(hi)[2*i+1] = __nv_bfloat162(h2,h3);
    reinterpret_cast<__nv_bfloat162*>(lo)[2*i]   = __nv_bfloat162(l0,l1);
    reinterpret_cast<__nv_bfloat162*>(lo)[2*i+1] = __nv_bfloat162(l2,l3);
}
__device__ __forceinline__ void store_h(__half* __restrict__ p, int i, float4 v) {
    reinterpret_cast<__half2*>(p)[2*i]   = __floats2half2_rn(v.x, v.y);
    reinterpret_cast<__half2*>(p)[2*i+1] = __floats2half2_rn(v.z, v.w);
}

// ======================= bf16 3-term GEMM (small stages) =====================
#define BKC 32
#define ASTRIDE 80
#define STG_A_HI 0
#define STG_A_LO 10240
#define STG_B_HI 20480
#define STG_B_LO 30720
#define STG_STRIDE 40960
#define HG_SMEM (2*STG_STRIDE)

template<int EPI>
__global__ __launch_bounds__(256, 2) void hgemm(
    const __nv_bfloat16* __restrict__ Ah, const __nv_bfloat16* __restrict__ Al,
    int lda, int a_off1, int nsplit,
    const __nv_bfloat16* __restrict__ Bh, const __nv_bfloat16* __restrict__ Bl,
    int ldb,
    float* __restrict__ C, int ldc, int K,
    const float* __restrict__ bias0, const float* __restrict__ bias1,
    int kz)
{
    extern __shared__ char sm[];
    const uint32_t smb = smem_u32(sm);
    const int tid = threadIdx.x;
    const int bm = blockIdx.y * 128, bn = blockIdx.x * 128;
    if (kz > 0) {
        Ah += (size_t)blockIdx.z * kz;  Al += (size_t)blockIdx.z * kz;
        Bh += (size_t)blockIdx.z * kz;  Bl += (size_t)blockIdx.z * kz;
        C  += (size_t)blockIdx.z * (size_t)(gridDim.y * 128) * (size_t)ldc;
        K = kz;
    }
    const int aoff = (nsplit && bn >= nsplit) ? a_off1 : 0;

    const int grow = tid >> 1;
    const int seg  = (tid & 1) << 1;
    const char* gAh = (const char*)(Ah + aoff + (size_t)(bm + grow) * lda);
    const char* gAl = (const char*)(Al + aoff + (size_t)(bm + grow) * lda);
    const char* gBh = (const char*)(Bh + (size_t)(bn + grow) * ldb);
    const char* gBl = (const char*)(Bl + (size_t)(bn + grow) * ldb);
    const uint32_t srow = smb + (uint32_t)(grow * ASTRIDE + seg * 16);

    const int wid = tid >> 5, lane = tid & 31;
    const int wm = (wid >> 2) * 64;
    const int wn = (wid & 3) * 32;
    const int tq = lane >> 2, tr = lane & 3;
    const uint32_t aoffm = (uint32_t)((wm + (lane & 15)) * ASTRIDE + ((lane >> 4) << 4));
    const int g = lane >> 3;
    const uint32_t boffm = (uint32_t)((wn + ((g >> 1) << 3) + (lane & 7)) * ASTRIDE + ((g & 1) << 4));

    float acc[4][4][4];
#pragma unroll
    for (int i = 0; i < 4; i++)
#pragma unroll
        for (int j = 0; j < 4; j++)
#pragma unroll
            for (int q = 0; q < 4; q++) acc[i][j][q] = 0.f;

    const int nch = K / BKC;

    auto issue = [&](int s) {
        const uint32_t st = srow + (uint32_t)(s & 1) * STG_STRIDE;
        const int go = s * (BKC * 2) + seg * 16;
        CPA16(st + STG_A_HI,      gAh + go);
        CPA16(st + STG_A_HI + 16, gAh + go + 16);
        CPA16(st + STG_A_LO,      gAl + go);
        CPA16(st + STG_A_LO + 16, gAl + go + 16);
        CPA16(st + STG_B_HI,      gBh + go);
        CPA16(st + STG_B_HI + 16, gBh + go + 16);
        CPA16(st + STG_B_LO,      gBl + go);
        CPA16(st + STG_B_LO + 16, gBl + go + 16);
        CPCOMMIT();
    };

    issue(0);
    for (int s = 0; s < nch; s++) {
        CPWAIT0();
        __syncthreads();
        if (s + 1 < nch) issue(s + 1);
        const uint32_t sa = smb + (uint32_t)(s & 1) * STG_STRIDE;
#pragma unroll
        for (int ph = 0; ph < 2; ph++) {
            const uint32_t ka = sa + ph * 32;
            uint32_t ah[4][4], al[4][4], bh[4][2], bl[4][2];
#pragma unroll
            for (int i = 0; i < 4; i++)
                LDM4(ah[i][0], ah[i][1], ah[i][2], ah[i][3], ka + STG_A_HI + aoffm + i*(16*ASTRIDE));
            LDM4(bh[0][0], bh[0][1], bh[1][0], bh[1][1], ka + STG_B_HI + boffm);
            LDM4(bh[2][0], bh[2][1], bh[3][0], bh[3][1], ka + STG_B_HI + boffm + 16*ASTRIDE);
#pragma unroll
            for (int i = 0; i < 4; i++)
#pragma unroll
                for (int j = 0; j < 4; j++)
                    MMA_BF16(acc[i][j], ah[i], bh[j]);
#pragma unroll
            for (int i = 0; i < 4; i++)
                LDM4(al[i][0], al[i][1], al[i][2], al[i][3], ka + STG_A_LO + aoffm + i*(16*ASTRIDE));
            LDM4(bl[0][0], bl[0][1], bl[1][0], bl[1][1], ka + STG_B_LO + boffm);
            LDM4(bl[2][0], bl[2][1], bl[3][0], bl[3][1], ka + STG_B_LO + boffm + 16*ASTRIDE);
#pragma unroll
            for (int i = 0; i < 4; i++)
#pragma unroll
                for (int j = 0; j < 4; j++)
                    MMA_BF16(acc[i][j], ah[i], bl[j]);
#pragma unroll
            for (int i = 0; i < 4; i++)
#pragma unroll
                for (int j = 0; j < 4; j++)
                    MMA_BF16(acc[i][j], al[i], bh[j]);
        }
    }

    const float* bias = nullptr;
    if (EPI == 1) bias = (nsplit && bn >= nsplit) ? (bias1 - nsplit) : bias0;
#pragma unroll
    for (int i = 0; i < 4; i++) {
        const int row0 = bm + wm + 16*i + tq;
#pragma unroll
        for (int j = 0; j < 4; j++) {
            const int col = bn + wn + 8*j + 2*tr;
            float v0 = acc[i][j][0], v1 = acc[i][j][1];
            float v2 = acc[i][j][2], v3 = acc[i][j][3];
            if (EPI == 1) {
                const float b0v = bias[col], b1v = bias[col+1];
                v0 += b0v; v1 += b1v; v2 += b0v; v3 += b1v;
                v0 = (v0 > 20.f) ? v0 : log1pf(__expf(v0));
                v1 = (v1 > 20.f) ? v1 : log1pf(__expf(v1));
                v2 = (v2 > 20.f) ? v2 : log1pf(__expf(v2));
                v3 = (v3 > 20.f) ? v3 : log1pf(__expf(v3));
            }
            *reinterpret_cast<float2*>(C + (size_t)row0 * ldc + col)       = make_float2(v0, v1);
            *reinterpret_cast<float2*>(C + (size_t)(row0 + 8) * ldc + col) = make_float2(v2, v3);
        }
    }
}

// ======== fp16 GEMM: A single plane, B single plane, 3-stage pipeline ========
#define H2_A    0
#define H2_B    10240
#define H2_STRIDE 20480
#define H2_SMEM (3*H2_STRIDE)

__global__ __launch_bounds__(256, 2) void hgemm2(
    const __half* __restrict__ Ah, int lda,
    const __half* __restrict__ B, int ldb,
    float* __restrict__ C, int ldc, int K, int kz)
{
    extern __shared__ char sm[];
    const uint32_t smb = smem_u32(sm);
    const int tid = threadIdx.x;
    const int bm = blockIdx.y * 128, bn = blockIdx.x * 128;
    if (kz > 0) {
        Ah += (size_t)blockIdx.z * kz;
        B  += (size_t)blockIdx.z * kz;
        C  += (size_t)blockIdx.z * (size_t)(gridDim.y * 128) * (size_t)ldc;
        K = kz;
    }

    const int grow = tid >> 1;
    const int seg  = (tid & 1) << 1;
    const char* gAh = (const char*)(Ah + (size_t)(bm + grow) * lda);
    const char* gB  = (const char*)(B  + (size_t)(bn + grow) * ldb);
    const uint32_t srow = smb + (uint32_t)(grow * ASTRIDE + seg * 16);

    const int wid = tid >> 5, lane = tid & 31;
    const int wm = (wid >> 2) * 64;
    const int wn = (wid & 3) * 32;
    const int tq = lane >> 2, tr = lane & 3;
    const uint32_t aoffm = (uint32_t)((wm + (lane & 15)) * ASTRIDE + ((lane >> 4) << 4));
    const int g = lane >> 3;
    const uint32_t boffm = (uint32_t)((wn + ((g >> 1) << 3) + (lane & 7)) * ASTRIDE + ((g & 1) << 4));

    float acc[4][4][4];
#pragma unroll
    for (int i = 0; i < 4; i++)
#pragma unroll
        for (int j = 0; j < 4; j++)
#pragma unroll
            for (int q = 0; q < 4; q++) acc[i][j][q] = 0.f;

    const int nch = K / BKC;

    auto issue = [&](int s) {
        const uint32_t st = srow + (uint32_t)(s % 3) * H2_STRIDE;
        const int go = s * (BKC * 2) + seg * 16;
        CPA16(st + H2_A,      gAh + go);
        CPA16(st + H2_A + 16, gAh + go + 16);
        CPA16(st + H2_B,      gB + go);
        CPA16(st + H2_B + 16, gB + go + 16);
        CPCOMMIT();
    };

    issue(0);
    if (nch > 1) issue(1);
    for (int s = 0; s < nch; s++) {
        if (s + 1 < nch) CPWAIT1();
        else             CPWAIT0();
        __syncthreads();
        if (s + 2 < nch) issue(s + 2);
        const uint32_t sa = smb + (uint32_t)(s % 3) * H2_STRIDE;
#pragma unroll
        for (int ph = 0; ph < 2; ph++) {
            const uint32_t ka = sa + ph * 32;
            uint32_t ah[4][4], bb[4][2];
#pragma unroll
            for (int i = 0; i < 4; i++)
                LDM4(ah[i][0], ah[i][1], ah[i][2], ah[i][3], ka + H2_A + aoffm + i*(16*ASTRIDE));
            LDM4(bb[0][0], bb[0][1], bb[1][0], bb[1][1], ka + H2_B + boffm);
            LDM4(bb[2][0], bb[2][1], bb[3][0], bb[3][1], ka + H2_B + boffm + 16*ASTRIDE);
#pragma unroll
            for (int i = 0; i < 4; i++)
#pragma unroll
                for (int j = 0; j < 4; j++)
                    MMA_F16(acc[i][j], ah[i], bb[j]);
        }
    }

#pragma unroll
    for (int i = 0; i < 4; i++) {
        const int row0 = bm + wm + 16*i + tq;
#pragma unroll
        for (int j = 0; j < 4; j++) {
            const int col = bn + wn + 8*j + 2*tr;
            *reinterpret_cast<float2*>(C + (size_t)row0 * ldc + col)
                = make_float2(acc[i][j][0], acc[i][j][1]);
            *reinterpret_cast<float2*>(C + (size_t)(row0 + 8) * ldc + col)
                = make_float2(acc[i][j][2], acc[i][j][3]);
        }
    }
}

// ======================= single merged convert kernel =========================
#define N4_X    (MROWS*DMODEL/4)        /* 524288  */
#define N4_INW  (4096*DMODEL/4)         /* 1048576 per dir */
#define N4_DTW  (2048*DTR/4)            /* 32768 per dir */
#define N4_XP   (256*DIN/4)             /* 131072 */
#define N4_OUT  (DMODEL*4096/4)         /* 1048576 */
#define N4_ALL  (N4_X + 2*N4_INW + 2*N4_DTW + N4_XP + N4_OUT)   /* 3866624 */

__global__ __launch_bounds__(256) void cvt_all_kernel(
    const float* __restrict__ x,
    const float* __restrict__ inW_f, const float* __restrict__ inW_b,
    const float* __restrict__ dtW_f, const float* __restrict__ dtW_b,
    const float* __restrict__ xpW_f, const float* __restrict__ xpW_b,
    const float* __restrict__ outW_f, const float* __restrict__ outW_b)
{
    int i = blockIdx.x * 256 + threadIdx.x;
    if (i < N4_X) {                       // x -> fp16 plane
        store_h(g_Xh, i, reinterpret_cast<const float4*>(x)[i]);
        return;
    }
    i -= N4_X;
    if (i < 2*N4_INW) {                   // inW f|b -> fp16 plane
        const float4 v = (i < N4_INW)
            ? reinterpret_cast<const float4*>(inW_f)[i]
            : reinterpret_cast<const float4*>(inW_b)[i - N4_INW];
        store_h(g_Win, i, v);
        return;
    }
    i -= 2*N4_INW;
    if (i < 2*N4_DTW) {                   // dtW f|b -> bf16 planes
        const float4 v = (i < N4_DTW)
            ? reinterpret_cast<const float4*>(dtW_f)[i]
            : reinterpret_cast<const float4*>(dtW_b)[i - N4_DTW];
        store_planes(g_dtWh, g_dtWl, i, v);
        return;
    }
    i -= 2*N4_DTW;
    if (i < N4_XP) {                      // padded xpW -> bf16 planes
        const int idx = i * 4;
        const int r = idx >> 11, c = idx & 2047;
        float4 v = make_float4(0.f,0.f,0.f,0.f);
        if (r < 96)                   v = *reinterpret_cast<const float4*>(xpW_f + r*2048 + c);
        else if (r >= 128 && r < 224) v = *reinterpret_cast<const float4*>(xpW_b + (r-128)*2048 + c);
        store_planes(g_Xph, g_Xpl, i, v);
        return;
    }
    i -= N4_XP;
    {                                     // outW K-concat -> fp16 plane
        const int idx = i * 4;
        const int r = idx >> 12, c = idx & 4095;
        const float4 v = (c < 2048)
            ? *reinterpret_cast<const float4*>(outW_f + (size_t)r*2048 + c)
            : *reinterpret_cast<const float4*>(outW_b + (size_t)r*2048 + (c - 2048));
        store_h(g_Wout, i, v);
    }
}

__global__ __launch_bounds__(256) void reduce_out_kernel(float* __restrict__ out)
{
    const int i = blockIdx.x * 256 + threadIdx.x;
    float4 s = reinterpret_cast<const float4*>(g_OUTP)[i];
#pragma unroll
    for (int k = 1; k < 4; k++) {
        const float4 p = reinterpret_cast<const float4*>(g_OUTP + (size_t)k*MROWS*DMODEL)[i];
        s.x += p.x; s.y += p.y; s.z += p.z; s.w += p.w;
    }
    reinterpret_cast<float4*>(out)[i] = make_float4(0.5f*s.x, 0.5f*s.y, 0.5f*s.z, 0.5f*s.w);
}

// ------- depthwise conv + SiLU: 4 rows/thread sliding window -----------------
__global__ __launch_bounds__(256) void conv_silu_kernel(
    const float* __restrict__ convW_f, const float* __restrict__ convB_f,
    const float* __restrict__ convW_b, const float* __restrict__ convB_b)
{
    const int t = blockIdx.x * 256 + threadIdx.x;   // over (MROWS/4)*4096
    const int c = t & 4095;
    const int rq = t >> 12;                         // 0..511
    const int b = rq >> 8;
    const int l0 = (rq & 255) << 2;
    const int dir = c >> 11;
    const int d = c & (DIN - 1);
    const float* w = (dir ? convW_b : convW_f) + d*4;
    const float bias = (dir ? convB_b : convB_f)[d];
    const float* xi = g_XZ + dir*4096 + d;

    float xv[7];
    if (dir == 0) {                                 // need rows l0-3 .. l0+3
#pragma unroll
        for (int k = 0; k < 7; k++) {
            const int ls = l0 - 3 + k;
            xv[k] = (ls >= 0) ? xi[(size_t)(b*LSEQ + ls)*8192] : 0.f;
        }
#pragma unroll
        for (int j = 0; j < 4; j++) {
            float acc = bias;
#pragma unroll
            for (int k = 0; k < 4; k++) acc = fmaf(w[k], xv[j + k], acc);
            const float sig = 1.f / (1.f + __expf(-acc));
            const float u = acc * sig;
            const size_t o = (size_t)(b*LSEQ + l0 + j)*4096 + c;
            g_U[o] = u;
            __nv_bfloat16 h, lo2; split1(u, h, lo2);
            g_Uh[o] = h; g_Ul[o] = lo2;
        }
    } else {                                        // need rows l0 .. l0+6
#pragma unroll
        for (int k = 0; k < 7; k++) {
            const int ls = l0 + k;
            xv[k] = (ls < LSEQ) ? xi[(size_t)(b*LSEQ + ls)*8192] : 0.f;
        }
#pragma unroll
        for (int j = 0; j < 4; j++) {
            float acc = bias;
#pragma unroll
            for (int k = 0; k < 4; k++) acc = fmaf(w[k], xv[j + 3 - k], acc);
            const float sig = 1.f / (1.f + __expf(-acc));
            const float u = acc * sig;
            const size_t o = (size_t)(b*LSEQ + l0 + j)*4096 + c;
            g_U[o] = u;
            __nv_bfloat16 h, lo2; split1(u, h, lo2);
            g_Uh[o] = h; g_Ul[o] = lo2;
        }
    }
}

// ------------------------- split-K reduce + plane split ----------------------
__global__ __launch_bounds__(256) void reduce_xdbl_kernel()
{
    const int i = blockIdx.x * 256 + threadIdx.x;
    float s = 0.f;
#pragma unroll
    for (int k = 0; k < 8; k++) s += g_XDBLP[(size_t)k*MROWS*256 + i];
    g_XDBL[i] = s;
    __nv_bfloat16 h, l; split1(s, h, l);
    g_XDh[i] = h; g_XDl[i] = l;
}

// ------------- selective scan: 2 states/thread, ex2 fast path ---------------
__global__ __launch_bounds__(256) void scan_kernel(
    const float* __restrict__ Alog_f, const float* __restrict__ Alog_b,
    const float* __restrict__ Dp_f,  const float* __restrict__ Dp_b)
{
    const int dir = blockIdx.z;
    const int b   = blockIdx.y;
    const int d0  = blockIdx.x * 32;
    const int t    = threadIdx.x;
    const int lane = t & 31;
    const int w    = t >> 5;
    const int dlw  = (w << 2) + (lane >> 3);
    const int np   = lane & 7;
    const int d    = d0 + dlw;

    const float LOG2E = 1.4426950408889634f;
    const float* Alog = dir ? Alog_b : Alog_f;
    const float Ac0 = -__expf(Alog[d*NST + np])     * LOG2E;
    const float Ac1 = -__expf(Alog[d*NST + np + 8]) * LOG2E;
    const float DpE = (dir ? Dp_b : Dp_f)[d0 + (t & 31)];

    __shared__ float2 sDdw[32][32];
    __shared__ float2 sUZ [32][32];
    __shared__ float4 sBC [32][8];
    __shared__ float  sY  [32][32];

    const int sll = t >> 5;
    const int sdq = t & 31;
    const int bll = t >> 3, bj = t & 7;

    float rgD[4], rgU[4], rgZ[4], rgB[4];
    auto prefetch = [&](int lb) {
#pragma unroll
        for (int e = 0; e < 4; e++) {
            const int row = b*LSEQ + lb + sll + e*8;
            rgD[e] = g_DELTA[(size_t)row*4096 + dir*2048 + d0 + sdq];
            rgU[e] = g_U[(size_t)row*4096 + dir*2048 + d0 + sdq];
            rgZ[e] = g_XZ[(size_t)row*8192 + dir*4096 + 2048 + d0 + sdq];
        }
        const int rowb = b*LSEQ + lb + bll;
        rgB[0] = g_XDBL[(size_t)rowb*256 + dir*128 + 64 + bj];
        rgB[1] = g_XDBL[(size_t)rowb*256 + dir*128 + 80 + bj];
        rgB[2] = g_XDBL[(size_t)rowb*256 + dir*128 + 64 + bj + 8];
        rgB[3] = g_XDBL[(size_t)rowb*256 + dir*128 + 80 + bj + 8];
    };

    prefetch((dir == 0) ? 0 : (LSEQ - 32));

    float h0 = 0.f, h1 = 0.f;
    const int NCH = LSEQ / 32;
    for (int c = 0; c < NCH; c++) {
        __syncthreads();
#pragma unroll
        for (int e = 0; e < 4; e++) {
            sDdw[sll + e*8][sdq] = make_float2(rgD[e], rgD[e]*rgU[e]);
            sUZ [sll + e*8][sdq] = make_float2(rgU[e], rgZ[e]);
        }
        sBC[bll][bj] = make_float4(rgB[0], rgB[1], rgB[2], rgB[3]);
        __syncthreads();
        if (c + 1 < NCH)
            prefetch((dir == 0) ? (c+1)*32 : (LSEQ - (c+2)*32));
        const int lb = (dir == 0) ? c*32 : (LSEQ - (c+1)*32);
#pragma unroll 4
        for (int s = 0; s < 32; s++) {
            const int ll = (dir == 0) ? s : (31 - s);
            const float2 ddw = sDdw[ll][dlw];
            const float4 bc  = sBC[ll][np];
            float dA0, dA1;
            EX2F(dA0, ddw.x * Ac0);
            EX2F(dA1, ddw.x * Ac1);
            h0 = fmaf(h0, dA0, ddw.y * bc.x);
            h1 = fmaf(h1, dA1, ddw.y * bc.z);
            float py = fmaf(h1, bc.w, h0 * bc.y);
            py += __shfl_xor_sync(0xffffffffu, py, 4);
            py += __shfl_xor_sync(0xffffffffu, py, 2);
            py += __shfl_xor_sync(0xffffffffu, py, 1);
            if (np == 0) sY[ll][dlw] = py;
        }
        __syncthreads();
#pragma unroll
        for (int e = 0; e < 4; e++) {
            const int ll = sll + e*8;
            const float2 uz = sUZ[ll][sdq];
            const float y = fmaf(uz.x, DpE, sY[ll][sdq]);
            const float sig = 1.f / (1.f + __expf(-uz.y));
            const float yg = y * (uz.y * sig);
            const size_t o = (size_t)(b*LSEQ + lb + ll)*4096 + dir*2048 + d0 + sdq;
            g_YGh[o] = __float2half(yg);
        }
    }
}

// ------------------------------------ launch ---------------------------------
extern "C" void kernel_launch(void* const* d_in, const int* in_sizes, int n_in,
                              void* d_out, int out_size)
{
    const float* x      = (const float*)d_in[0];
    const float* inW_f  = (const float*)d_in[1];
    const float* convW_f= (const float*)d_in[2];
    const float* convB_f= (const float*)d_in[3];
    const float* xpW_f  = (const float*)d_in[4];
    const float* dtW_f  = (const float*)d_in[5];
    const float* dtB_f  = (const float*)d_in[6];
    const float* Alog_f = (const float*)d_in[7];
    const float* Dp_f   = (const float*)d_in[8];
    const float* outW_f = (const float*)d_in[9];
    const float* inW_b  = (const float*)d_in[10];
    const float* convW_b= (const float*)d_in[11];
    const float* convB_b= (const float*)d_in[12];
    const float* xpW_b  = (const float*)d_in[13];
    const float* dtW_b  = (const float*)d_in[14];
    const float* dtB_b  = (const float*)d_in[15];
    const float* Alog_b = (const float*)d_in[16];
    const float* Dp_b   = (const float*)d_in[17];
    const float* outW_b = (const float*)d_in[18];
    float* out = (float*)d_out;

    float *XZ, *XDBLP, *DELTA, *OUTP;
    __nv_bfloat16 *Uh, *Ul, *Xph, *Xpl, *XDh, *XDl, *dtWh, *dtWl;
    __half *Xh, *Win, *YGh, *Wout;
    cudaGetSymbolAddress((void**)&XZ,    g_XZ);
    cudaGetSymbolAddress((void**)&XDBLP, g_XDBLP);
    cudaGetSymbolAddress((void**)&DELTA, g_DELTA);
    cudaGetSymbolAddress((void**)&OUTP,  g_OUTP);
    cudaGetSymbolAddress((void**)&Xh,    g_Xh);
    cudaGetSymbolAddress((void**)&Win,   g_Win);
    cudaGetSymbolAddress((void**)&Uh,    g_Uh);
    cudaGetSymbolAddress((void**)&Ul,    g_Ul);
    cudaGetSymbolAddress((void**)&Xph,   g_Xph);
    cudaGetSymbolAddress((void**)&Xpl,   g_Xpl);
    cudaGetSymbolAddress((void**)&XDh,   g_XDh);
    cudaGetSymbolAddress((void**)&XDl,   g_XDl);
    cudaGetSymbolAddress((void**)&dtWh,  g_dtWh);
    cudaGetSymbolAddress((void**)&dtWl,  g_dtWl);
    cudaGetSymbolAddress((void**)&YGh,   g_YGh);
    cudaGetSymbolAddress((void**)&Wout,  g_Wout);

    cudaFuncSetAttribute(hgemm<0>, cudaFuncAttributeMaxDynamicSharedMemorySize, HG_SMEM);
    cudaFuncSetAttribute(hgemm<1>, cudaFuncAttributeMaxDynamicSharedMemorySize, HG_SMEM);
    cudaFuncSetAttribute(hgemm2,   cudaFuncAttributeMaxDynamicSharedMemorySize, H2_SMEM);

    // 0) all operand conversions in one launch
    cvt_all_kernel<<<N4_ALL/256, 256>>>(x, inW_f, inW_b, dtW_f, dtW_b,
                                        xpW_f, xpW_b, outW_f, outW_b);

    // 1) input projection (fp16 single-term): [2048,8192] = X * Win^T
    hgemm2<<<dim3(64,16,1), 256, H2_SMEM>>>(
        Xh, DMODEL, Win, DMODEL, XZ, 8192, DMODEL, 0);

    // 2) depthwise conv + SiLU (4 rows/thread sliding window)
    conv_silu_kernel<<<(MROWS/4*4096)/256, 256>>>(convW_f, convB_f, convW_b, convB_b);

    // 3) x_dbl (bf16 3-term): split-K=8
    hgemm<0><<<dim3(2,16,8), 256, HG_SMEM>>>(
        Uh, Ul, 4096, 2048, 128, Xph, Xpl, DIN,
        XDBLP, 256, DIN, nullptr, nullptr, 256);
    reduce_xdbl_kernel<<<(MROWS*256)/256, 256>>>();

    // 4) delta = softplus(dt @ dtWcat^T + dtB) (bf16 3-term)
    hgemm<1><<<dim3(32,16,1), 256, HG_SMEM>>>(
        XDh, XDl, 256, 128, 2048, dtWh, dtWl, DTR,
        DELTA, 4096, DTR, dtB_f, dtB_b, 0);

    // 5) selective scan + gating (emits YG fp16 plane)
    scan_kernel<<<dim3(64,2,2), 256>>>(Alog_f, Alog_b, Dp_f, Dp_b);

    // 6) out-proj (fp16 single-term, 3-stage) split-K=4, then 0.5*sum
    hgemm2<<<dim3(8,16,4), 256, H2_SMEM>>>(
        YGh, 4096, Wout, 4096, OUTP, DMODEL, 4096, 1024);
    reduce_out_kernel<<<(MROWS*DMODEL/4)/256, 256>>>(out);
}

// round 16
// speedup vs baseline: 2.5330x; 1.0439x over previous
#include <cuda_runtime.h>
#include <cuda_fp16.h>
#include <math.h>
#include <cstdint>

#define B_SZ   2
#define LSEQ   1024
#define DMODEL 1024
#define DIN    2048
#define NST    16
#define DTR    64
#define MROWS  (B_SZ*LSEQ)   /* 2048 */

// ---------------- scratch (device globals; no allocation allowed) ------------
__device__ float g_XZ[MROWS*8192];              // [m][dir*4096 + (xi | z)]
__device__ float g_U [MROWS*4096];              // fp32 for scan
__device__ __half g_Uq[MROWS*4096];             // fp16 (x_dbl A)
__device__ __half g_Xh[MROWS*DMODEL];           // fp16 (in-proj A)
__device__ __half g_Win[8192*DMODEL];           // fp16 (in-proj B)
__device__ __half g_Xp[256*DIN];                // fp16 padded xpW (x_dbl B)
__device__ float g_XDBLP[8*MROWS*256];
__device__ float g_XDBL[MROWS*256];             // fp32 for scan (B, C cols)
__device__ __half g_XDq[MROWS*256];             // fp16 (delta A)
__device__ __half g_dtW[4096*DTR];              // fp16 dir-concat rows (delta B)
__device__ float g_DELTA[(size_t)MROWS*4096];
__device__ __half g_YGh[MROWS*4096];            // fp16 (out-proj A)
__device__ __half g_Wout[DMODEL*4096];          // fp16 (out-proj B)
__device__ float g_OUTP[4*MROWS*DMODEL];        // out-proj split-K=4 partials

// ======================= helpers =============================================
__device__ __forceinline__ uint32_t smem_u32(const void* p) {
    uint32_t a;
    asm("{ .reg .u64 t; cvta.to.shared.u64 t, %1; cvt.u32.u64 %0, t; }" : "=r"(a) : "l"(p));
    return a;
}
#define LDM4(r0,r1,r2,r3,addr)                                                      \
    asm volatile("ldmatrix.sync.aligned.m8n8.x4.shared.b16 {%0,%1,%2,%3}, [%4];"    \
        : "=r"(r0),"=r"(r1),"=r"(r2),"=r"(r3) : "r"(addr))
#define MMA_F16(c,a,b)                                                              \
    asm volatile("mma.sync.aligned.m16n8k16.row.col.f32.f16.f16.f32 "               \
        "{%0,%1,%2,%3}, {%4,%5,%6,%7}, {%8,%9}, {%0,%1,%2,%3};"                     \
        : "+f"((c)[0]),"+f"((c)[1]),"+f"((c)[2]),"+f"((c)[3])                       \
        : "r"((a)[0]),"r"((a)[1]),"r"((a)[2]),"r"((a)[3]),"r"((b)[0]),"r"((b)[1]))
#define CPA16(dst, src) asm volatile("cp.async.cg.shared.global [%0], [%1], 16;" :: "r"(dst), "l"(src) : "memory")
#define CPCOMMIT()      asm volatile("cp.async.commit_group;" ::: "memory")
#define CPWAIT0()       asm volatile("cp.async.wait_group 0;" ::: "memory")
#define CPWAIT1()       asm volatile("cp.async.wait_group 1;" ::: "memory")
#define EX2F(r, x)      asm("ex2.approx.f32 %0, %1;" : "=f"(r) : "f"(x))

__device__ __forceinline__ void store_h(__half* __restrict__ p, int i, float4 v) {
    reinterpret_cast<__half2*>(p)[2*i]   = __floats2half2_rn(v.x, v.y);
    reinterpret_cast<__half2*>(p)[2*i+1] = __floats2half2_rn(v.z, v.w);
}

// ======== fp16 single-term GEMM, 3-stage cp.async pipeline ===================
// C[M,N] = A[M,K] * B[N,K]^T.  A += a_off1 when CTA n-tile >= nsplit.
// kz>0: split-K over blockIdx.z (C offset z*M*ldc).
// EPI: 0 = store, 1 = softplus(acc + bias[n]) with bias0/bias1 split at nsplit.
#define BKC 32
#define ASTRIDE 80
#define H2_A    0
#define H2_B    10240
#define H2_STRIDE 20480
#define H2_SMEM (3*H2_STRIDE)

template<int EPI>
__global__ __launch_bounds__(256, 2) void hgemm2(
    const __half* __restrict__ Ah, int lda, int a_off1, int nsplit,
    const __half* __restrict__ B, int ldb,
    float* __restrict__ C, int ldc, int K,
    const float* __restrict__ bias0, const float* __restrict__ bias1, int kz)
{
    extern __shared__ char sm[];
    const uint32_t smb = smem_u32(sm);
    const int tid = threadIdx.x;
    const int bm = blockIdx.y * 128, bn = blockIdx.x * 128;
    if (kz > 0) {
        Ah += (size_t)blockIdx.z * kz;
        B  += (size_t)blockIdx.z * kz;
        C  += (size_t)blockIdx.z * (size_t)(gridDim.y * 128) * (size_t)ldc;
        K = kz;
    }
    const int aoff = (nsplit && bn >= nsplit) ? a_off1 : 0;

    const int grow = tid >> 1;
    const int seg  = (tid & 1) << 1;
    const char* gAh = (const char*)(Ah + aoff + (size_t)(bm + grow) * lda);
    const char* gB  = (const char*)(B  + (size_t)(bn + grow) * ldb);
    const uint32_t srow = smb + (uint32_t)(grow * ASTRIDE + seg * 16);

    const int wid = tid >> 5, lane = tid & 31;
    const int wm = (wid >> 2) * 64;
    const int wn = (wid & 3) * 32;
    const int tq = lane >> 2, tr = lane & 3;
    const uint32_t aoffm = (uint32_t)((wm + (lane & 15)) * ASTRIDE + ((lane >> 4) << 4));
    const int g = lane >> 3;
    const uint32_t boffm = (uint32_t)((wn + ((g >> 1) << 3) + (lane & 7)) * ASTRIDE + ((g & 1) << 4));

    float acc[4][4][4];
#pragma unroll
    for (int i = 0; i < 4; i++)
#pragma unroll
        for (int j = 0; j < 4; j++)
#pragma unroll
            for (int q = 0; q < 4; q++) acc[i][j][q] = 0.f;

    const int nch = K / BKC;

    auto issue = [&](int s) {
        const uint32_t st = srow + (uint32_t)(s % 3) * H2_STRIDE;
        const int go = s * (BKC * 2) + seg * 16;
        CPA16(st + H2_A,      gAh + go);
        CPA16(st + H2_A + 16, gAh + go + 16);
        CPA16(st + H2_B,      gB + go);
        CPA16(st + H2_B + 16, gB + go + 16);
        CPCOMMIT();
    };

    issue(0);
    if (nch > 1) issue(1);
    for (int s = 0; s < nch; s++) {
        if (s + 1 < nch) CPWAIT1();
        else             CPWAIT0();
        __syncthreads();
        if (s + 2 < nch) issue(s + 2);
        const uint32_t sa = smb + (uint32_t)(s % 3) * H2_STRIDE;
#pragma unroll
        for (int ph = 0; ph < 2; ph++) {
            const uint32_t ka = sa + ph * 32;
            uint32_t ah[4][4], bb[4][2];
#pragma unroll
            for (int i = 0; i < 4; i++)
                LDM4(ah[i][0], ah[i][1], ah[i][2], ah[i][3], ka + H2_A + aoffm + i*(16*ASTRIDE));
            LDM4(bb[0][0], bb[0][1], bb[1][0], bb[1][1], ka + H2_B + boffm);
            LDM4(bb[2][0], bb[2][1], bb[3][0], bb[3][1], ka + H2_B + boffm + 16*ASTRIDE);
#pragma unroll
            for (int i = 0; i < 4; i++)
#pragma unroll
                for (int j = 0; j < 4; j++)
                    MMA_F16(acc[i][j], ah[i], bb[j]);
        }
    }

    const float* bias = nullptr;
    if (EPI == 1) bias = (nsplit && bn >= nsplit) ? (bias1 - nsplit) : bias0;
#pragma unroll
    for (int i = 0; i < 4; i++) {
        const int row0 = bm + wm + 16*i + tq;
#pragma unroll
        for (int j = 0; j < 4; j++) {
            const int col = bn + wn + 8*j + 2*tr;
            float v0 = acc[i][j][0], v1 = acc[i][j][1];
            float v2 = acc[i][j][2], v3 = acc[i][j][3];
            if (EPI == 1) {
                const float b0v = bias[col], b1v = bias[col+1];
                v0 += b0v; v1 += b1v; v2 += b0v; v3 += b1v;
                v0 = (v0 > 20.f) ? v0 : log1pf(__expf(v0));
                v1 = (v1 > 20.f) ? v1 : log1pf(__expf(v1));
                v2 = (v2 > 20.f) ? v2 : log1pf(__expf(v2));
                v3 = (v3 > 20.f) ? v3 : log1pf(__expf(v3));
            }
            *reinterpret_cast<float2*>(C + (size_t)row0 * ldc + col)       = make_float2(v0, v1);
            *reinterpret_cast<float2*>(C + (size_t)(row0 + 8) * ldc + col) = make_float2(v2, v3);
        }
    }
}

// ======================= single merged convert kernel =========================
#define N4_X    (MROWS*DMODEL/4)        /* 524288  */
#define N4_INW  (4096*DMODEL/4)         /* 1048576 per dir */
#define N4_DTW  (2048*DTR/4)            /* 32768 per dir */
#define N4_XP   (256*DIN/4)             /* 131072 */
#define N4_OUT  (DMODEL*4096/4)         /* 1048576 */
#define N4_ALL  (N4_X + 2*N4_INW + 2*N4_DTW + N4_XP + N4_OUT)

__global__ __launch_bounds__(256) void cvt_all_kernel(
    const float* __restrict__ x,
    const float* __restrict__ inW_f, const float* __restrict__ inW_b,
    const float* __restrict__ dtW_f, const float* __restrict__ dtW_b,
    const float* __restrict__ xpW_f, const float* __restrict__ xpW_b,
    const float* __restrict__ outW_f, const float* __restrict__ outW_b)
{
    int i = blockIdx.x * 256 + threadIdx.x;
    if (i < N4_X) {
        store_h(g_Xh, i, reinterpret_cast<const float4*>(x)[i]);
        return;
    }
    i -= N4_X;
    if (i < 2*N4_INW) {
        const float4 v = (i < N4_INW)
            ? reinterpret_cast<const float4*>(inW_f)[i]
            : reinterpret_cast<const float4*>(inW_b)[i - N4_INW];
        store_h(g_Win, i, v);
        return;
    }
    i -= 2*N4_INW;
    if (i < 2*N4_DTW) {                   // dtW f|b concat -> fp16 plane
        const float4 v = (i < N4_DTW)
            ? reinterpret_cast<const float4*>(dtW_f)[i]
            : reinterpret_cast<const float4*>(dtW_b)[i - N4_DTW];
        store_h(g_dtW, i, v);
        return;
    }
    i -= 2*N4_DTW;
    if (i < N4_XP) {                      // padded xpW -> fp16 plane
        const int idx = i * 4;
        const int r = idx >> 11, c = idx & 2047;
        float4 v = make_float4(0.f,0.f,0.f,0.f);
        if (r < 96)                   v = *reinterpret_cast<const float4*>(xpW_f + r*2048 + c);
        else if (r >= 128 && r < 224) v = *reinterpret_cast<const float4*>(xpW_b + (r-128)*2048 + c);
        store_h(g_Xp, i, v);
        return;
    }
    i -= N4_XP;
    {                                     // outW K-concat -> fp16 plane
        const int idx = i * 4;
        const int r = idx >> 12, c = idx & 4095;
        const float4 v = (c < 2048)
            ? *reinterpret_cast<const float4*>(outW_f + (size_t)r*2048 + c)
            : *reinterpret_cast<const float4*>(outW_b + (size_t)r*2048 + (c - 2048));
        store_h(g_Wout, i, v);
    }
}

__global__ __launch_bounds__(256) void reduce_out_kernel(float* __restrict__ out)
{
    const int i = blockIdx.x * 256 + threadIdx.x;
    float4 s = reinterpret_cast<const float4*>(g_OUTP)[i];
#pragma unroll
    for (int k = 1; k < 4; k++) {
        const float4 p = reinterpret_cast<const float4*>(g_OUTP + (size_t)k*MROWS*DMODEL)[i];
        s.x += p.x; s.y += p.y; s.z += p.z; s.w += p.w;
    }
    reinterpret_cast<float4*>(out)[i] = make_float4(0.5f*s.x, 0.5f*s.y, 0.5f*s.z, 0.5f*s.w);
}

// ------- depthwise conv + SiLU: 4 rows/thread; emits fp32 U + fp16 plane -----
__global__ __launch_bounds__(256) void conv_silu_kernel(
    const float* __restrict__ convW_f, const float* __restrict__ convB_f,
    const float* __restrict__ convW_b, const float* __restrict__ convB_b)
{
    const int t = blockIdx.x * 256 + threadIdx.x;   // over (MROWS/4)*4096
    const int c = t & 4095;
    const int rq = t >> 12;
    const int b = rq >> 8;
    const int l0 = (rq & 255) << 2;
    const int dir = c >> 11;
    const int d = c & (DIN - 1);
    const float* w = (dir ? convW_b : convW_f) + d*4;
    const float bias = (dir ? convB_b : convB_f)[d];
    const float* xi = g_XZ + dir*4096 + d;

    float xv[7];
    if (dir == 0) {
#pragma unroll
        for (int k = 0; k < 7; k++) {
            const int ls = l0 - 3 + k;
            xv[k] = (ls >= 0) ? xi[(size_t)(b*LSEQ + ls)*8192] : 0.f;
        }
#pragma unroll
        for (int j = 0; j < 4; j++) {
            float acc = bias;
#pragma unroll
            for (int k = 0; k < 4; k++) acc = fmaf(w[k], xv[j + k], acc);
            const float sig = 1.f / (1.f + __expf(-acc));
            const float u = acc * sig;
            const size_t o = (size_t)(b*LSEQ + l0 + j)*4096 + c;
            g_U[o] = u;
            g_Uq[o] = __float2half(u);
        }
    } else {
#pragma unroll
        for (int k = 0; k < 7; k++) {
            const int ls = l0 + k;
            xv[k] = (ls < LSEQ) ? xi[(size_t)(b*LSEQ + ls)*8192] : 0.f;
        }
#pragma unroll
        for (int j = 0; j < 4; j++) {
            float acc = bias;
#pragma unroll
            for (int k = 0; k < 4; k++) acc = fmaf(w[k], xv[j + 3 - k], acc);
            const float sig = 1.f / (1.f + __expf(-acc));
            const float u = acc * sig;
            const size_t o = (size_t)(b*LSEQ + l0 + j)*4096 + c;
            g_U[o] = u;
            g_Uq[o] = __float2half(u);
        }
    }
}

// ------------------ split-K reduce; emits fp32 + fp16 plane ------------------
__global__ __launch_bounds__(256) void reduce_xdbl_kernel()
{
    const int i = blockIdx.x * 256 + threadIdx.x;
    float s = 0.f;
#pragma unroll
    for (int k = 0; k < 8; k++) s += g_XDBLP[(size_t)k*MROWS*256 + i];
    g_XDBL[i] = s;
    g_XDq[i] = __float2half(s);
}

// ------------- selective scan: 2 states/thread, ex2 fast path ---------------
__global__ __launch_bounds__(256) void scan_kernel(
    const float* __restrict__ Alog_f, const float* __restrict__ Alog_b,
    const float* __restrict__ Dp_f,  const float* __restrict__ Dp_b)
{
    const int dir = blockIdx.z;
    const int b   = blockIdx.y;
    const int d0  = blockIdx.x * 32;
    const int t    = threadIdx.x;
    const int lane = t & 31;
    const int w    = t >> 5;
    const int dlw  = (w << 2) + (lane >> 3);
    const int np   = lane & 7;
    const int d    = d0 + dlw;

    const float LOG2E = 1.4426950408889634f;
    const float* Alog = dir ? Alog_b : Alog_f;
    const float Ac0 = -__expf(Alog[d*NST + np])     * LOG2E;
    const float Ac1 = -__expf(Alog[d*NST + np + 8]) * LOG2E;
    const float DpE = (dir ? Dp_b : Dp_f)[d0 + (t & 31)];

    __shared__ float2 sDdw[32][32];
    __shared__ float2 sUZ [32][32];
    __shared__ float4 sBC [32][8];
    __shared__ float  sY  [32][32];

    const int sll = t >> 5;
    const int sdq = t & 31;
    const int bll = t >> 3, bj = t & 7;

    float rgD[4], rgU[4], rgZ[4], rgB[4];
    auto prefetch = [&](int lb) {
#pragma unroll
        for (int e = 0; e < 4; e++) {
            const int row = b*LSEQ + lb + sll + e*8;
            rgD[e] = g_DELTA[(size_t)row*4096 + dir*2048 + d0 + sdq];
            rgU[e] = g_U[(size_t)row*4096 + dir*2048 + d0 + sdq];
            rgZ[e] = g_XZ[(size_t)row*8192 + dir*4096 + 2048 + d0 + sdq];
        }
        const int rowb = b*LSEQ + lb + bll;
        rgB[0] = g_XDBL[(size_t)rowb*256 + dir*128 + 64 + bj];
        rgB[1] = g_XDBL[(size_t)rowb*256 + dir*128 + 80 + bj];
        rgB[2] = g_XDBL[(size_t)rowb*256 + dir*128 + 64 + bj + 8];
        rgB[3] = g_XDBL[(size_t)rowb*256 + dir*128 + 80 + bj + 8];
    };

    prefetch((dir == 0) ? 0 : (LSEQ - 32));

    float h0 = 0.f, h1 = 0.f;
    const int NCH = LSEQ / 32;
    for (int c = 0; c < NCH; c++) {
        __syncthreads();
#pragma unroll
        for (int e = 0; e < 4; e++) {
            sDdw[sll + e*8][sdq] = make_float2(rgD[e], rgD[e]*rgU[e]);
            sUZ [sll + e*8][sdq] = make_float2(rgU[e], rgZ[e]);
        }
        sBC[bll][bj] = make_float4(rgB[0], rgB[1], rgB[2], rgB[3]);
        __syncthreads();
        if (c + 1 < NCH)
            prefetch((dir == 0) ? (c+1)*32 : (LSEQ - (c+2)*32));
        const int lb = (dir == 0) ? c*32 : (LSEQ - (c+1)*32);
#pragma unroll 4
        for (int s = 0; s < 32; s++) {
            const int ll = (dir == 0) ? s : (31 - s);
            const float2 ddw = sDdw[ll][dlw];
            const float4 bc  = sBC[ll][np];
            float dA0, dA1;
            EX2F(dA0, ddw.x * Ac0);
            EX2F(dA1, ddw.x * Ac1);
            h0 = fmaf(h0, dA0, ddw.y * bc.x);
            h1 = fmaf(h1, dA1, ddw.y * bc.z);
            float py = fmaf(h1, bc.w, h0 * bc.y);
            py += __shfl_xor_sync(0xffffffffu, py, 4);
            py += __shfl_xor_sync(0xffffffffu, py, 2);
            py += __shfl_xor_sync(0xffffffffu, py, 1);
            if (np == 0) sY[ll][dlw] = py;
        }
        __syncthreads();
#pragma unroll
        for (int e = 0; e < 4; e++) {
            const int ll = sll + e*8;
            const float2 uz = sUZ[ll][sdq];
            const float y = fmaf(uz.x, DpE, sY[ll][sdq]);
            const float sig = 1.f / (1.f + __expf(-uz.y));
            const float yg = y * (uz.y * sig);
            const size_t o = (size_t)(b*LSEQ + lb + ll)*4096 + dir*2048 + d0 + sdq;
            g_YGh[o] = __float2half(yg);
        }
    }
}

// ------------------------------------ launch ---------------------------------
extern "C" void kernel_launch(void* const* d_in, const int* in_sizes, int n_in,
                              void* d_out, int out_size)
{
    const float* x      = (const float*)d_in[0];
    const float* inW_f  = (const float*)d_in[1];
    const float* convW_f= (const float*)d_in[2];
    const float* convB_f= (const float*)d_in[3];
    const float* xpW_f  = (const float*)d_in[4];
    const float* dtW_f  = (const float*)d_in[5];
    const float* dtB_f  = (const float*)d_in[6];
    const float* Alog_f = (const float*)d_in[7];
    const float* Dp_f   = (const float*)d_in[8];
    const float* outW_f = (const float*)d_in[9];
    const float* inW_b  = (const float*)d_in[10];
    const float* convW_b= (const float*)d_in[11];
    const float* convB_b= (const float*)d_in[12];
    const float* xpW_b  = (const float*)d_in[13];
    const float* dtW_b  = (const float*)d_in[14];
    const float* dtB_b  = (const float*)d_in[15];
    const float* Alog_b = (const float*)d_in[16];
    const float* Dp_b   = (const float*)d_in[17];
    const float* outW_b = (const float*)d_in[18];
    float* out = (float*)d_out;

    float *XZ, *XDBLP, *DELTA, *OUTP;
    __half *Xh, *Win, *Uq, *Xp, *XDq, *dtW, *YGh, *Wout;
    cudaGetSymbolAddress((void**)&XZ,    g_XZ);
    cudaGetSymbolAddress((void**)&XDBLP, g_XDBLP);
    cudaGetSymbolAddress((void**)&DELTA, g_DELTA);
    cudaGetSymbolAddress((void**)&OUTP,  g_OUTP);
    cudaGetSymbolAddress((void**)&Xh,    g_Xh);
    cudaGetSymbolAddress((void**)&Win,   g_Win);
    cudaGetSymbolAddress((void**)&Uq,    g_Uq);
    cudaGetSymbolAddress((void**)&Xp,    g_Xp);
    cudaGetSymbolAddress((void**)&XDq,   g_XDq);
    cudaGetSymbolAddress((void**)&dtW,   g_dtW);
    cudaGetSymbolAddress((void**)&YGh,   g_YGh);
    cudaGetSymbolAddress((void**)&Wout,  g_Wout);

    cudaFuncSetAttribute(hgemm2<0>, cudaFuncAttributeMaxDynamicSharedMemorySize, H2_SMEM);
    cudaFuncSetAttribute(hgemm2<1>, cudaFuncAttributeMaxDynamicSharedMemorySize, H2_SMEM);

    // 0) all operand conversions in one launch
    cvt_all_kernel<<<N4_ALL/256, 256>>>(x, inW_f, inW_b, dtW_f, dtW_b,
                                        xpW_f, xpW_b, outW_f, outW_b);

    // 1) input projection: [2048,8192] = X * Win^T
    hgemm2<0><<<dim3(64,16,1), 256, H2_SMEM>>>(
        Xh, DMODEL, 0, 0, Win, DMODEL, XZ, 8192, DMODEL, nullptr, nullptr, 0);

    // 2) depthwise conv + SiLU
    conv_silu_kernel<<<(MROWS/4*4096)/256, 256>>>(convW_f, convB_f, convW_b, convB_b);

    // 3) x_dbl: [2048,256] = U[dir-slice] * Xp^T, split-K=8
    hgemm2<0><<<dim3(2,16,8), 256, H2_SMEM>>>(
        Uq, 4096, 2048, 128, Xp, DIN, XDBLP, 256, DIN, nullptr, nullptr, 256);
    reduce_xdbl_kernel<<<(MROWS*256)/256, 256>>>();

    // 4) delta = softplus(dt @ dtWcat^T + dtB), N=4096, K=64
    hgemm2<1><<<dim3(32,16,1), 256, H2_SMEM>>>(
        XDq, 256, 128, 2048, dtW, DTR, DELTA, 4096, DTR, dtB_f, dtB_b, 0);

    // 5) selective scan + gating
    scan_kernel<<<dim3(64,2,2), 256>>>(Alog_f, Alog_b, Dp_f, Dp_b);

    // 6) out-proj split-K=4, then 0.5*sum
    hgemm2<0><<<dim3(8,16,4), 256, H2_SMEM>>>(
        YGh, 4096, 0, 0, Wout, 4096, OUTP, DMODEL, 4096, nullptr, nullptr, 1024);
    reduce_out_kernel<<<(MROWS*DMODEL/4)/256, 256>>>(out);
}